// round 11
// baseline (speedup 1.0000x reference)
#include <cuda_runtime.h>
#include <cuda_bf16.h>
#include <math.h>
#include <mma.h>
using namespace nvcuda;

#define BB 128
#define SS 50
#define DD 128
#define NNODE 40000
#define SAMP 12
#define NNEI 8
#define LEAKC 0.2f
#define NSCORE 39999

// ---------------- scratch (device globals; no allocation) ----------------
__device__ float g_h[BB*SS*DD];
__device__ float g_hf1[BB*SS*DD];
__device__ float g_hf2[BB*SS*DD];
__device__ float g_x[BB*SS*DD];
__device__ float g_mirror[BB*SS*DD];
__device__ float g_xnew[BB*SS*DD];
__device__ float g_xdot[BB*SS*DD];
__device__ float g_sess[BB*DD];
__device__ float g_out0[BB*SS*DD];
__device__ float g_out1[BB*600*DD];
__device__ float g_hglob[BB*SS*DD];
__device__ float g_hs[BB*DD];
__device__ float g_hlocal[BB*DD];
__device__ float g_c2[BB*DD];
__device__ float g_beta[BB*SS];
__device__ float g_zg[BB*DD];
__device__ float g_zhT[DD*BB];
__device__ float g_partial[BB*SS];
__device__ float g_cat[BB*SS*2*DD];     // cat rows (mode 2 only)
__device__ float g_logits[BB*7200];
__device__ __nv_bfloat16 g_w1b[2*DD*DD]; // W1 rows 0..127, hop 0 and hop 1, bf16
__device__ float g_E3top[NNODE*DD];      // emb @ W3hop0[0:128]
__device__ float g_E3bot[NNODE*DD];      // emb @ W3hop0[128:256]

__device__ __forceinline__ float sigm(float x){ return 1.0f/(1.0f+expf(-x)); }

// ---------------- k_w1bf: convert W1 rows 0..127 (both hops) to bf16 ----------------
__global__ void k_w1bf(const float* __restrict__ w1){
  int i = blockIdx.x*256 + threadIdx.x;   // 0 .. 2*DD*DD-1
  int hop = i/(DD*DD), within = i - hop*(DD*DD);
  g_w1b[i] = __float2bfloat16(w1[(size_t)hop*129*DD + within]);
}

// ---------------- k_e3: E3top/E3bot = emb @ W3hop0 (fp32 exact) ----------------
__global__ void __launch_bounds__(128) k_e3(const float* __restrict__ emb,
                                            const float* __restrict__ w3){
  int row0 = blockIdx.x*32; int c = threadIdx.x;
  __shared__ __align__(16) float As[16][32];
  float accT[32], accB[32];
  #pragma unroll
  for(int r=0;r<32;r++){ accT[r]=0.f; accB[r]=0.f; }
  int rld = c & 31, kq = c >> 5;
  for(int k0=0;k0<DD;k0+=16){
    float4 av = *(const float4*)&emb[(size_t)(row0+rld)*DD + k0 + kq*4];
    As[kq*4+0][rld]=av.x; As[kq*4+1][rld]=av.y; As[kq*4+2][rld]=av.z; As[kq*4+3][rld]=av.w;
    __syncthreads();
    const float* wT = w3 + (size_t)k0*DD + c;
    const float* wB = w3 + (size_t)(k0+DD)*DD + c;
    #pragma unroll 4
    for(int k=0;k<16;k++){
      float bT = wT[k*DD], bB = wB[k*DD];
      #pragma unroll
      for(int r4=0;r4<8;r4++){
        float4 a = *(const float4*)&As[k][r4*4];
        accT[r4*4+0]=fmaf(a.x,bT,accT[r4*4+0]); accB[r4*4+0]=fmaf(a.x,bB,accB[r4*4+0]);
        accT[r4*4+1]=fmaf(a.y,bT,accT[r4*4+1]); accB[r4*4+1]=fmaf(a.y,bB,accB[r4*4+1]);
        accT[r4*4+2]=fmaf(a.z,bT,accT[r4*4+2]); accB[r4*4+2]=fmaf(a.z,bB,accB[r4*4+2]);
        accT[r4*4+3]=fmaf(a.w,bT,accT[r4*4+3]); accB[r4*4+3]=fmaf(a.w,bB,accB[r4*4+3]);
      }
    }
    __syncthreads();
  }
  #pragma unroll
  for(int r=0;r<32;r++){
    g_E3top[(size_t)(row0+r)*DD + c] = accT[r];
    g_E3bot[(size_t)(row0+r)*DD + c] = accB[r];
  }
}

// ---------------- k_pool ----------------
__global__ void k_pool(const int* __restrict__ inputs,
                       const int* __restrict__ as0, const int* __restrict__ as1,
                       const int* __restrict__ ssl0, const int* __restrict__ ssl1,
                       const float* __restrict__ emb){
  int blk = blockIdx.x; int tid = threadIdx.x;
  int node = inputs[blk];
  g_h[blk*DD+tid] = emb[node*DD+tid];
  float p1=0.f, p2=0.f;
  const int* L1[2] = {as0, as1};
  const int* L2[2] = {ssl0, ssl1};
  #pragma unroll
  for(int l=0;l<2;l++){
    float s=0.f,c=0.f;
    #pragma unroll
    for(int n=0;n<NNEI;n++){ int id=L1[l][blk*NNEI+n]; if(id!=0){ s+=emb[id*DD+tid]; c+=1.f; } }
    p1 += s/(c+1e-8f);
    s=0.f;c=0.f;
    #pragma unroll
    for(int n=0;n<NNEI;n++){ int id=L2[l][blk*NNEI+n]; if(id!=0){ s+=emb[id*DD+tid]; c+=1.f; } }
    p2 += s/(c+1e-8f);
  }
  g_hf1[blk*DD+tid] = p1*0.5f;
  g_hf2[blk*DD+tid] = p2*0.5f;
}

// ---------------- k_attrT: tiled (32 rows) attr gate; x=h, mirror=hf ----------------
__global__ void __launch_bounds__(128) k_attrT(const float* __restrict__ attr_w){
  int row0 = blockIdx.x*32; int c = threadIdx.x;
  __shared__ __align__(16) float As[16][32];
  float acc[32];
  #pragma unroll
  for(int r=0;r<32;r++) acc[r]=0.f;
  int rld=c&31, kq=c>>5;
  for(int k0=0;k0<2*DD;k0+=16){
    const float* srcA = (k0<DD)? g_h : g_hf1;
    int kk = k0 & (DD-1);
    float4 av = *(const float4*)&srcA[(size_t)(row0+rld)*DD + kk + kq*4];
    As[kq*4+0][rld]=av.x; As[kq*4+1][rld]=av.y; As[kq*4+2][rld]=av.z; As[kq*4+3][rld]=av.w;
    __syncthreads();
    const float* wc = attr_w + (size_t)k0*DD + c;
    #pragma unroll 4
    for(int k=0;k<16;k++){
      float bk = wc[k*DD];
      #pragma unroll
      for(int r4=0;r4<8;r4++){
        float4 a = *(const float4*)&As[k][r4*4];
        acc[r4*4+0]=fmaf(a.x,bk,acc[r4*4+0]);
        acc[r4*4+1]=fmaf(a.y,bk,acc[r4*4+1]);
        acc[r4*4+2]=fmaf(a.z,bk,acc[r4*4+2]);
        acc[r4*4+3]=fmaf(a.w,bk,acc[r4*4+3]);
      }
    }
    __syncthreads();
  }
  #pragma unroll
  for(int r=0;r<32;r++){
    size_t idx=(size_t)(row0+r)*DD + c;
    float g=sigm(acc[r]);
    float h=g_h[idx], f=g_hf1[idx];
    g_x[idx]=h;
    g_mirror[idx]=g*h+(1.f-g)*f;
  }
}

// ---------------- k_sess ----------------
__global__ void k_sess(const int* __restrict__ inputs, const int* __restrict__ item,
                       const float* __restrict__ emb){
  int b=blockIdx.x, tid=threadIdx.x;
  float acc=0.f, cnt=0.f;
  for(int s=0;s<SS;s++){
    int inp=inputs[b*SS+s];
    if(inp!=0){ acc += emb[item[b*SS+s]*DD+tid]; cnt+=1.f; }
  }
  g_sess[b*DD+tid]=acc/cnt;
}

// ---------------- k_logits: bf16 TC logits, all 3 modes (256 rows/CTA, 512 thr) ----------------
#define LROWS 256
__global__ void __launch_bounds__(512) k_logits(
    const int* __restrict__ inputs, const int* __restrict__ adj_all,
    const float* __restrict__ num, const float* __restrict__ src,
    const __nv_bfloat16* __restrict__ w1b,
    const float* __restrict__ w1last, const float* __restrict__ w2,
    float* __restrict__ logits, int rowsPerB, int mode)
{
  extern __shared__ char smem[];
  const int LDAB = 136;
  __nv_bfloat16* As = (__nv_bfloat16*)smem;                 // [256][136]
  __nv_bfloat16* Bs = (__nv_bfloat16*)(smem + 69632);       // [128][136]
  float* sess_s = (float*)(smem + 104448);
  float* wl_s   = sess_s + DD;
  float* w2_s   = wl_s + DD;
  float* nw_s   = w2_s + DD;
  int*   ci_s   = (int*)(nw_s + LROWS);

  int b = blockIdx.y;
  int row0 = blockIdx.x*LROWS;
  int tid = threadIdx.x, warp = tid>>5, lane = tid&31;

  if(tid<DD){
    sess_s[tid]=g_sess[b*DD+tid];
    wl_s[tid]  =w1last[tid];
    w2_s[tid]  =w2[tid];
  }
  if(tid<LROWS){
    int r = row0 + tid;
    int rr = (r<rowsPerB)? r : rowsPerB-1;
    int gi=rr/SAMP, s=rr-gi*SAMP;
    int node, ci;
    if(mode==1){
      int pi=gi/SAMP, ps=gi-pi*SAMP;
      node = adj_all[inputs[b*SS+pi]*SAMP+ps];
      ci = adj_all[node*SAMP+s];
    } else if(mode==0){
      node = inputs[b*SS+gi];
      ci = adj_all[node*SAMP+s];
    } else {
      node = inputs[b*SS+gi];
      ci = b*600 + rr;
    }
    ci_s[tid]=ci;
    nw_s[tid]=num[node*SAMP+s];
  }
  {
    int row=tid>>2, qb=(tid&3)*32;
    const uint4* srcw=(const uint4*)(w1b + row*DD + qb);
    uint4* dst=(uint4*)(Bs + row*LDAB + qb);
    #pragma unroll
    for(int j=0;j<4;j++) dst[j]=srcw[j];
  }
  __syncthreads();
  {
    int row=tid>>1, cb=(tid&1)*64;
    const float* ap = src + (size_t)ci_s[row]*DD + cb;
    __nv_bfloat16* dst = As + row*LDAB + cb;
    #pragma unroll
    for(int j=0;j<16;j++){
      float4 v=*(const float4*)&ap[j*4];
      float4 se=*(const float4*)&sess_s[cb+j*4];
      *(__nv_bfloat162*)&dst[j*4]   = __floats2bfloat162_rn(v.x*se.x, v.y*se.y);
      *(__nv_bfloat162*)&dst[j*4+2] = __floats2bfloat162_rn(v.z*se.z, v.w*se.w);
    }
  }
  __syncthreads();

  wmma::fragment<wmma::accumulator,16,16,16,float> acc[8];
  #pragma unroll
  for(int n=0;n<8;n++) wmma::fill_fragment(acc[n], 0.0f);

  #pragma unroll
  for(int k=0;k<DD;k+=16){
    wmma::fragment<wmma::matrix_a,16,16,16,__nv_bfloat16,wmma::row_major> af;
    wmma::load_matrix_sync(af, As + (warp*16)*LDAB + k, LDAB);
    #pragma unroll
    for(int n=0;n<8;n++){
      wmma::fragment<wmma::matrix_b,16,16,16,__nv_bfloat16,wmma::row_major> bf;
      wmma::load_matrix_sync(bf, Bs + k*LDAB + n*16, LDAB);
      wmma::mma_sync(acc[n], af, bf, acc[n]);
    }
  }
  __syncthreads();

  float* epi = (float*)Bs + warp*320;
  int r2=lane>>1, half=lane&1;
  float nw = nw_s[warp*16+r2];
  float v=0.f;
  #pragma unroll
  for(int n=0;n<8;n++){
    wmma::store_matrix_sync(epi, acc[n], 20, wmma::mem_row_major);
    __syncwarp();
    const float* crow = epi + r2*20 + half*8;
    int cb = n*16 + half*8;
    #pragma unroll
    for(int j=0;j<8;j++){
      float t = crow[j] + nw*wl_s[cb+j];
      t = (t>0.f)?t:(LEAKC*t);
      v = fmaf(t, w2_s[cb+j], v);
    }
    __syncwarp();
  }
  v += __shfl_xor_sync(0xffffffffu, v, 1);
  int rg = row0 + warp*16 + r2;
  if(half==0 && rg<rowsPerB) logits[(size_t)b*rowsPerB + rg] = v;
}

// ---------------- k_soft_agg_f: softmax + fused W3 via E3 tables (modes 0 and 1) ----------------
__global__ void __launch_bounds__(32) k_soft_agg_f(
    const int* __restrict__ inputs, const int* __restrict__ adj_all,
    const float* __restrict__ logits, float* __restrict__ outbuf, int N, int mode)
{
  int blk=blockIdx.x; int b=blk/N; int i=blk-b*N; int tid=threadIdx.x;
  __shared__ int   ci_s[SAMP];
  __shared__ float lg_s[SAMP];
  int node;
  if(mode==1){
    int pi=i/SAMP, ps=i-pi*SAMP;
    node = adj_all[inputs[b*SS+pi]*SAMP+ps];
  } else {
    node = inputs[b*SS+i];
  }
  if(tid<SAMP){
    ci_s[tid] = adj_all[node*SAMP+tid];
    lg_s[tid] = logits[(size_t)b*(N*SAMP) + i*SAMP + tid];
  }
  __syncwarp();
  float lg[SAMP];
  #pragma unroll
  for(int s=0;s<SAMP;s++) lg[s]=lg_s[s];
  float m=-1e30f;
  #pragma unroll
  for(int s=0;s<SAMP;s++) m=fmaxf(m,lg[s]);
  float alpha[SAMP]; float den=0.f;
  #pragma unroll
  for(int s=0;s<SAMP;s++){ alpha[s]=expf(lg[s]-m); den+=alpha[s]; }
  float inv=1.f/den;
  float4 t4 = ((const float4*)&g_E3top[(size_t)node*DD])[tid];
  float a0=0.f,a1=0.f,a2=0.f,a3=0.f;
  #pragma unroll
  for(int s=0;s<SAMP;s++){
    float4 e4 = ((const float4*)&g_E3bot[(size_t)ci_s[s]*DD])[tid];
    float al = alpha[s];
    a0=fmaf(al,e4.x,a0); a1=fmaf(al,e4.y,a1); a2=fmaf(al,e4.z,a2); a3=fmaf(al,e4.w,a3);
  }
  float4 o;
  o.x = tanhf(t4.x + a0*inv);
  o.y = tanhf(t4.y + a1*inv);
  o.z = tanhf(t4.z + a2*inv);
  o.w = tanhf(t4.w + a3*inv);
  ((float4*)&outbuf[(size_t)blk*DD])[tid] = o;
}

// ---------------- k_soft_agg2: mode-2 softmax + cat row (sv=out0, nv=out1) ----------------
__global__ void __launch_bounds__(32) k_soft_agg2(const float* __restrict__ logits)
{
  int blk=blockIdx.x; int b=blk/SS; int i=blk-b*SS; int tid=threadIdx.x;
  __shared__ float lg_s[SAMP];
  if(tid<SAMP) lg_s[tid] = logits[(size_t)b*600 + i*SAMP + tid];
  __syncwarp();
  float lg[SAMP];
  #pragma unroll
  for(int s=0;s<SAMP;s++) lg[s]=lg_s[s];
  float m=-1e30f;
  #pragma unroll
  for(int s=0;s<SAMP;s++) m=fmaxf(m,lg[s]);
  float alpha[SAMP]; float den=0.f;
  #pragma unroll
  for(int s=0;s<SAMP;s++){ alpha[s]=expf(lg[s]-m); den+=alpha[s]; }
  float inv=1.f/den;
  float4 sv4 = ((const float4*)&g_out0[(size_t)blk*DD])[tid];
  const float* base = &g_out1[(size_t)(b*600 + i*SAMP)*DD];
  float a0=0.f,a1=0.f,a2=0.f,a3=0.f;
  #pragma unroll
  for(int s=0;s<SAMP;s++){
    float4 nv4 = ((const float4*)&base[(size_t)s*DD])[tid];
    float al = alpha[s];
    a0=fmaf(al,nv4.x,a0); a1=fmaf(al,nv4.y,a1); a2=fmaf(al,nv4.z,a2); a3=fmaf(al,nv4.w,a3);
  }
  float* crow = &g_cat[(size_t)blk*2*DD];
  ((float4*)crow)[tid] = sv4;
  float4 ag; ag.x=a0*inv; ag.y=a1*inv; ag.z=a2*inv; ag.w=a3*inv;
  ((float4*)(crow+DD))[tid] = ag;
}

// ---------------- k_gemm3: out = tanh(cat @ W3) (mode 2) ----------------
__global__ void __launch_bounds__(128) k_gemm3(const float* __restrict__ w3,
                                               float* __restrict__ out){
  int row0 = blockIdx.x*32; int tid=threadIdx.x;
  int c = tid;
  __shared__ __align__(16) float As[16][32];
  float acc[32];
  #pragma unroll
  for(int r=0;r<32;r++) acc[r]=0.f;
  int rld = tid & 31, kq = tid >> 5;
  for(int k0=0;k0<2*DD;k0+=16){
    float4 av = *(const float4*)&g_cat[(size_t)(row0+rld)*2*DD + k0 + kq*4];
    As[kq*4+0][rld]=av.x; As[kq*4+1][rld]=av.y; As[kq*4+2][rld]=av.z; As[kq*4+3][rld]=av.w;
    __syncthreads();
    const float* w3c = w3 + (size_t)k0*DD + c;
    #pragma unroll 4
    for(int k=0;k<16;k++){
      float bk = w3c[k*DD];
      #pragma unroll
      for(int r4=0;r4<8;r4++){
        float4 a = *(const float4*)&As[k][r4*4];
        acc[r4*4+0]=fmaf(a.x,bk,acc[r4*4+0]);
        acc[r4*4+1]=fmaf(a.y,bk,acc[r4*4+1]);
        acc[r4*4+2]=fmaf(a.z,bk,acc[r4*4+2]);
        acc[r4*4+3]=fmaf(a.w,bk,acc[r4*4+3]);
      }
    }
    __syncthreads();
  }
  #pragma unroll
  for(int r=0;r<32;r++)
    out[(size_t)(row0+r)*DD + c] = tanhf(acc[r]);
}

// ---------------- k_attx ----------------
__global__ void k_attx(const int* __restrict__ adj, const float* __restrict__ a_local){
  int b=blockIdx.x; int tid=threadIdx.x;  // 256 threads
  __shared__ __align__(16) float xs[SS][DD+4];
  __shared__ __align__(16) float al_s[4][DD];
  __shared__ float att[SS][SS+2];
  for(int idx=tid; idx<SS*DD; idx+=256){
    int i=idx>>7, d=idx&127;
    xs[i][d]=g_x[(b*SS+i)*DD+d];
  }
  for(int idx=tid; idx<4*DD; idx+=256)
    al_s[idx>>7][idx&127]=a_local[idx];
  __syncthreads();
  for(int p=tid;p<SS*SS;p+=256){
    int i=p/SS, j=p-i*SS;
    int k=adj[b*SS*SS+p];
    float e=-9e15f;
    if(k>=1 && k<=4){
      const float* al = al_s[k-1];
      float ds=0.f;
      #pragma unroll 8
      for(int d=0;d<DD;d+=4){
        float4 xi=*(const float4*)&xs[i][d];
        float4 xj=*(const float4*)&xs[j][d];
        float4 av=*(const float4*)&al[d];
        ds += xi.x*xj.x*av.x + xi.y*xj.y*av.y + xi.z*xj.z*av.z + xi.w*xj.w*av.w;
      }
      e = (ds>0.f)?ds:(LEAKC*ds);
    }
    att[i][j]=e;
  }
  __syncthreads();
  if(tid<SS){
    float m=-1e30f;
    for(int j=0;j<SS;j++) m=fmaxf(m,att[tid][j]);
    float den=0.f;
    for(int j=0;j<SS;j++){ float e=expf(att[tid][j]-m); att[tid][j]=e; den+=e; }
    float inv=1.f/den;
    for(int j=0;j<SS;j++) att[tid][j]*=inv;
  }
  __syncthreads();
  for(int q=tid;q<SS*DD;q+=256){
    int i=q>>7, d=q&127;
    float acc=0.f;
    for(int j=0;j<SS;j++) acc += att[i][j]*xs[j][d];
    g_xnew[(b*SS+i)*DD+d]=acc;
  }
}

// ---------------- k_gateT: tiled mirror gating (32 rows/block) ----------------
__global__ void __launch_bounds__(128) k_gateT(const float* __restrict__ w1,
                                               const float* __restrict__ w2){
  int row0 = blockIdx.x*32; int c = threadIdx.x;
  __shared__ __align__(16) float As[16][32];
  float acc[32];
  #pragma unroll
  for(int r=0;r<32;r++) acc[r]=0.f;
  int rld=c&31, kq=c>>5;
  for(int k0=0;k0<2*DD;k0+=16){
    const float* srcA = (k0<DD)? g_xnew : g_mirror;
    int kk = k0 & (DD-1);
    float4 av = *(const float4*)&srcA[(size_t)(row0+rld)*DD + kk + kq*4];
    As[kq*4+0][rld]=av.x; As[kq*4+1][rld]=av.y; As[kq*4+2][rld]=av.z; As[kq*4+3][rld]=av.w;
    __syncthreads();
    const float* wc = ((k0<DD)? w1 + (size_t)k0*DD : w2 + (size_t)(k0-DD)*DD) + c;
    #pragma unroll 4
    for(int k=0;k<16;k++){
      float bk = wc[k*DD];
      #pragma unroll
      for(int r4=0;r4<8;r4++){
        float4 a = *(const float4*)&As[k][r4*4];
        acc[r4*4+0]=fmaf(a.x,bk,acc[r4*4+0]);
        acc[r4*4+1]=fmaf(a.y,bk,acc[r4*4+1]);
        acc[r4*4+2]=fmaf(a.z,bk,acc[r4*4+2]);
        acc[r4*4+3]=fmaf(a.w,bk,acc[r4*4+3]);
      }
    }
    __syncthreads();
  }
  #pragma unroll
  for(int r=0;r<32;r++){
    size_t idx=(size_t)(row0+r)*DD + c;
    float gm=sigm(acc[r]);
    float xv=g_xnew[idx], mv=g_mirror[idx];
    g_x[idx]      = gm*xv + (1.f-gm)*mv;
    g_mirror[idx] = gm*mv + (1.f-gm)*xv;
  }
}

// ---------------- k_highwayT: tiled highway gate (32 rows/block) ----------------
__global__ void __launch_bounds__(128) k_highwayT(const float* __restrict__ hw){
  int row0 = blockIdx.x*32; int c = threadIdx.x;
  __shared__ __align__(16) float As[16][32];
  float acc[32];
  #pragma unroll
  for(int r=0;r<32;r++) acc[r]=0.f;
  int rld=c&31, kq=c>>5;
  for(int k0=0;k0<2*DD;k0+=16){
    const float* srcA = (k0<DD)? g_h : g_x;
    int kk = k0 & (DD-1);
    float4 av = *(const float4*)&srcA[(size_t)(row0+rld)*DD + kk + kq*4];
    As[kq*4+0][rld]=av.x; As[kq*4+1][rld]=av.y; As[kq*4+2][rld]=av.z; As[kq*4+3][rld]=av.w;
    __syncthreads();
    const float* wc = hw + (size_t)k0*DD + c;
    #pragma unroll 4
    for(int k=0;k<16;k++){
      float bk = wc[k*DD];
      #pragma unroll
      for(int r4=0;r4<8;r4++){
        float4 a = *(const float4*)&As[k][r4*4];
        acc[r4*4+0]=fmaf(a.x,bk,acc[r4*4+0]);
        acc[r4*4+1]=fmaf(a.y,bk,acc[r4*4+1]);
        acc[r4*4+2]=fmaf(a.z,bk,acc[r4*4+2]);
        acc[r4*4+3]=fmaf(a.w,bk,acc[r4*4+3]);
      }
    }
    __syncthreads();
  }
  #pragma unroll
  for(int r=0;r<32;r++){
    int row=row0+r;
    size_t idx=(size_t)row*DD + c;
    float g=sigm(acc[r]);
    float h=g_h[idx], xv=g_x[idx];
    float xd=g*h+(1.f-g)*xv;
    g_xdot[idx]=xd;
    if(row%SS==SS-1) g_hlocal[(row/SS)*DD+c]=xd;
  }
}

// ---------------- k_hs ----------------
__global__ void k_hs(const int* __restrict__ inputs){
  int b=blockIdx.x, tid=threadIdx.x;
  float acc=0.f, cnt=0.f;
  for(int s=0;s<SS;s++){
    if(inputs[b*SS+s]!=0){ acc += g_hglob[(b*SS+s)*DD+tid]; cnt+=1.f; }
  }
  g_hs[b*DD+tid]=acc/cnt;
}

// ---------------- k_c2 ----------------
__global__ void k_c2(const float* __restrict__ glu2, const float* __restrict__ glu4,
                     const float* __restrict__ glu4b){
  int b=blockIdx.x, tid=threadIdx.x;
  __shared__ __align__(16) float hsr[DD], hlr[DD];
  hsr[tid]=g_hs[b*DD+tid]; hlr[tid]=g_hlocal[b*DD+tid];
  __syncthreads();
  float acc=glu4b[tid];
  const float* w2t=glu2+tid; const float* w4t=glu4+tid;
  #pragma unroll 8
  for(int k=0;k<DD;k+=4){
    float4 s4=*(const float4*)&hsr[k];
    float4 l4=*(const float4*)&hlr[k];
    acc=fmaf(s4.x,w2t[(k  )*DD],acc); acc=fmaf(l4.x,w4t[(k  )*DD],acc);
    acc=fmaf(s4.y,w2t[(k+1)*DD],acc); acc=fmaf(l4.y,w4t[(k+1)*DD],acc);
    acc=fmaf(s4.z,w2t[(k+2)*DD],acc); acc=fmaf(l4.z,w4t[(k+2)*DD],acc);
    acc=fmaf(s4.w,w2t[(k+3)*DD],acc); acc=fmaf(l4.w,w4t[(k+3)*DD],acc);
  }
  g_c2[b*DD+tid]=acc;
}

// ---------------- k_beta ----------------
__global__ void k_beta(const int* __restrict__ inputs, const float* __restrict__ pos,
                       const float* __restrict__ glu1, const float* __restrict__ ws){
  int blk=blockIdx.x, tid=threadIdx.x;
  int s=blk%SS, b=blk/SS;
  __shared__ __align__(16) float hp[DD];
  __shared__ float red[DD];
  hp[tid]=g_xdot[blk*DD+tid] + pos[s*DD+tid];
  __syncthreads();
  const float* wt=glu1+tid;
  float acc=0.f;
  #pragma unroll 8
  for(int k=0;k<DD;k+=4){
    float4 h4=*(const float4*)&hp[k];
    acc=fmaf(h4.x,wt[(k  )*DD],acc); acc=fmaf(h4.y,wt[(k+1)*DD],acc);
    acc=fmaf(h4.z,wt[(k+2)*DD],acc); acc=fmaf(h4.w,wt[(k+3)*DD],acc);
  }
  float nh=sigm(acc + g_c2[b*DD+tid]);
  red[tid]=nh*ws[tid];
  __syncthreads();
  for(int off=64;off>0;off>>=1){ if(tid<off) red[tid]+=red[tid+off]; __syncthreads(); }
  if(tid==0){
    float mi=(inputs[blk]!=0)?1.f:0.f;
    g_beta[blk]=red[0]*mi;
  }
}

// ---------------- k_zg ----------------
__global__ void k_zg(const float* __restrict__ pos){
  int b=blockIdx.x, tid=threadIdx.x;
  float acc=0.f;
  for(int s=0;s<SS;s++)
    acc += g_beta[b*SS+s]*(g_xdot[(b*SS+s)*DD+tid]+pos[s*DD+tid]);
  g_zg[b*DD+tid]=acc;
}

// ---------------- k_zh ----------------
__global__ void k_zh(const float* __restrict__ gatew){
  int b=blockIdx.x, tid=threadIdx.x;
  __shared__ __align__(16) float zgr[DD], hlr[DD];
  zgr[tid]=g_zg[b*DD+tid]; hlr[tid]=g_hlocal[b*DD+tid];
  __syncthreads();
  const float* wt=gatew+tid;
  float acc=0.f;
  #pragma unroll 8
  for(int k=0;k<DD;k+=4){
    float4 z4=*(const float4*)&zgr[k];
    float4 l4=*(const float4*)&hlr[k];
    acc=fmaf(z4.x,wt[(k  )*DD],acc); acc=fmaf(l4.x,wt[(DD+k  )*DD],acc);
    acc=fmaf(z4.y,wt[(k+1)*DD],acc); acc=fmaf(l4.y,wt[(DD+k+1)*DD],acc);
    acc=fmaf(z4.z,wt[(k+2)*DD],acc); acc=fmaf(l4.z,wt[(DD+k+2)*DD],acc);
    acc=fmaf(z4.w,wt[(k+3)*DD],acc); acc=fmaf(l4.w,wt[(DD+k+3)*DD],acc);
  }
  float gf=sigm(acc)*0.1f;
  float zh=gf*hlr[tid]+(1.f-gf)*zgr[tid];
  g_zhT[tid*BB+b]=zh;
}

// ---------------- k_scores ----------------
__global__ void k_scores(const float* __restrict__ emb, float* __restrict__ out){
  int n0 = blockIdx.x*32; int tid=threadIdx.x;
  __shared__ __align__(16) float es[32][DD];
  int nmax = NSCORE - n0; if(nmax>32) nmax=32;
  for(int idx=tid; idx<nmax*DD; idx+=128){
    int nn=idx>>7, d=idx&127;
    es[nn][d]=emb[(size_t)(n0+nn+1)*DD+d];
  }
  __syncthreads();
  float accv[32];
  #pragma unroll
  for(int nn=0;nn<32;nn++) accv[nn]=0.f;
  for(int d=0;d<DD;d+=4){
    float z0=g_zhT[(d  )*BB+tid];
    float z1=g_zhT[(d+1)*BB+tid];
    float z2=g_zhT[(d+2)*BB+tid];
    float z3=g_zhT[(d+3)*BB+tid];
    #pragma unroll
    for(int nn=0;nn<32;nn++){
      float4 e=*reinterpret_cast<const float4*>(&es[nn][d]);
      accv[nn]=fmaf(z0,e.x,fmaf(z1,e.y,fmaf(z2,e.z,fmaf(z3,e.w,accv[nn]))));
    }
  }
  for(int nn=0;nn<nmax;nn++)
    out[1 + (size_t)tid*NSCORE + n0+nn] = accv[nn];
}

// ---------------- k_simi ----------------
__global__ void k_simi(const int* __restrict__ simi_mask){
  int blk=blockIdx.x; int b=blk/SS; int tid=threadIdx.x; // 64 threads
  __shared__ float f1[DD];
  __shared__ float sims[SS];
  f1[tid]   =g_hf1[blk*DD+tid];
  f1[tid+64]=g_hf1[blk*DD+tid+64];
  __syncthreads();
  if(tid<SS){
    const float* f2=&g_hf2[(b*SS+tid)*DD];
    float acc=0.f;
    for(int d=0;d<DD;d++) acc+=f1[d]*f2[d];
    sims[tid]=acc*2.0f;   // 1/TEMP
  }
  __syncthreads();
  if(tid==0){
    float m=-1e30f;
    for(int j=0;j<SS;j++) m=fmaxf(m,sims[j]);
    float den=0.f;
    for(int j=0;j<SS;j++) den+=expf(sims[j]-m);
    float loss=0.f;
    for(int j=0;j<SS;j++){
      float p=expf(sims[j]-m)/den;
      float l=-logf(p+1e-8f);
      if(simi_mask[blk*SS+j]==1) loss+=l;
    }
    g_partial[blk]=loss;
  }
}

__global__ void k_simi_final(float* __restrict__ out){
  int tid=threadIdx.x; // 128
  __shared__ float red[128];
  float a=0.f;
  for(int i=tid;i<BB*SS;i+=128) a+=g_partial[i];
  red[tid]=a; __syncthreads();
  for(int off=64;off>0;off>>=1){ if(tid<off) red[tid]+=red[tid+off]; __syncthreads(); }
  if(tid==0) out[0]=red[0]/(float)BB;
}

// ---------------- launch ----------------
extern "C" void kernel_launch(void* const* d_in, const int* in_sizes, int n_in,
                              void* d_out, int out_size){
  const int*   inputs =(const int*)  d_in[0];
  const int*   adj    =(const int*)  d_in[1];
  const int*   item   =(const int*)  d_in[2];
  const int*   simi   =(const int*)  d_in[3];
  const int*   as0    =(const int*)  d_in[4];
  const int*   as1    =(const int*)  d_in[5];
  const int*   ssl0   =(const int*)  d_in[6];
  const int*   ssl1   =(const int*)  d_in[7];
  // d_in[8] = last_item_mask (statically [:, -1]; unused)
  const int*   adj_all=(const int*)  d_in[9];
  const float* num    =(const float*)d_in[10];
  const float* emb    =(const float*)d_in[11];
  const float* pos    =(const float*)d_in[12];
  const float* a_local=(const float*)d_in[13];
  const float* mir1   =(const float*)d_in[14];
  const float* mir2   =(const float*)d_in[15];
  const float* gw1    =(const float*)d_in[16];
  const float* gw2    =(const float*)d_in[17];
  const float* gw3    =(const float*)d_in[18];
  const float* attr   =(const float*)d_in[19];
  const float* hww    =(const float*)d_in[20];
  const float* glu1   =(const float*)d_in[21];
  const float* glu2   =(const float*)d_in[22];
  const float* glu4   =(const float*)d_in[23];
  const float* glu4b  =(const float*)d_in[24];
  const float* ws     =(const float*)d_in[25];
  const float* gatew  =(const float*)d_in[26];
  float* out=(float*)d_out;

  float* p_out0;   cudaGetSymbolAddress((void**)&p_out0,  g_out0);
  float* p_out1;   cudaGetSymbolAddress((void**)&p_out1,  g_out1);
  float* p_hglob;  cudaGetSymbolAddress((void**)&p_hglob, g_hglob);
  float* p_logits; cudaGetSymbolAddress((void**)&p_logits,g_logits);
  __nv_bfloat16* p_w1b; cudaGetSymbolAddress((void**)&p_w1b, g_w1b);

  const int LOGITS_SMEM = 69632 + 34816 + (3*DD + LROWS)*4 + LROWS*4;  // 108032 B
  cudaFuncSetAttribute(k_logits, cudaFuncAttributeMaxDynamicSharedMemorySize, LOGITS_SMEM);

  k_w1bf<<<2*DD*DD/256,256>>>(gw1);
  k_e3<<<NNODE/32,128>>>(emb, gw3);          // hop-0 E3 tables (modes 0/1)
  k_pool<<<BB*SS,DD>>>(inputs, as0, as1, ssl0, ssl1, emb);
  k_attrT<<<BB*SS/32,128>>>(attr);
  k_sess<<<BB,DD>>>(inputs,item,emb);

  // mode 1: TC logits -> E3-fused soft_agg -> out1
  {
    dim3 g((7200+LROWS-1)/LROWS, BB);
    k_logits<<<g,512,LOGITS_SMEM>>>(inputs,adj_all,num, emb, p_w1b, gw1+DD*DD, gw2, p_logits, 7200, 1);
  }
  k_soft_agg_f<<<BB*600,32>>>(inputs,adj_all, p_logits, p_out1, 600, 1);

  // mode 0: TC logits -> E3-fused soft_agg -> out0
  {
    dim3 g((600+LROWS-1)/LROWS, BB);
    k_logits<<<g,512,LOGITS_SMEM>>>(inputs,adj_all,num, emb, p_w1b, gw1+DD*DD, gw2, p_logits, 600, 0);
  }
  k_soft_agg_f<<<BB*SS,32>>>(inputs,adj_all, p_logits, p_out0, SS, 0);

  // mode 2: TC logits (src=out1, hop-1 W1) -> cat -> gemm3 hop-1 -> hglob
  {
    dim3 g((600+LROWS-1)/LROWS, BB);
    k_logits<<<g,512,LOGITS_SMEM>>>(inputs,adj_all,num, p_out1, p_w1b+DD*DD, gw1+129*DD+DD*DD, gw2+DD, p_logits, 600, 2);
  }
  k_soft_agg2<<<BB*SS,32>>>(p_logits);
  k_gemm3<<<BB*SS/32,128>>>(gw3+256*DD, p_hglob);

  // local branch: 2 iterations
  for(int it=0; it<2; it++){
    k_attx<<<BB,256>>>(adj, a_local + it*4*DD);
    k_gateT<<<BB*SS/32,128>>>(mir1 + it*DD*DD, mir2 + it*DD*DD);
  }
  k_highwayT<<<BB*SS/32,128>>>(hww);
  k_hs<<<BB,DD>>>(inputs);
  k_c2<<<BB,DD>>>(glu2,glu4,glu4b);
  k_beta<<<BB*SS,DD>>>(inputs,pos,glu1,ws);
  k_zg<<<BB,DD>>>(pos);
  k_zh<<<BB,DD>>>(gatew);

  k_scores<<<(NSCORE+31)/32,128>>>(emb,out);
  k_simi<<<BB*SS,64>>>(simi);
  k_simi_final<<<1,128>>>(out);
}

// round 12
// speedup vs baseline: 1.0404x; 1.0404x over previous
#include <cuda_runtime.h>
#include <cuda_bf16.h>
#include <math.h>
#include <mma.h>
using namespace nvcuda;

#define BB 128
#define SS 50
#define DD 128
#define NNODE 40000
#define SAMP 12
#define NNEI 8
#define LEAKC 0.2f
#define NSCORE 39999

// ---------------- scratch (device globals; no allocation) ----------------
__device__ float g_h[BB*SS*DD];
__device__ float g_hf1[BB*SS*DD];
__device__ float g_hf2[BB*SS*DD];
__device__ float g_x[BB*SS*DD];
__device__ float g_mirror[BB*SS*DD];
__device__ float g_xnew[BB*SS*DD];
__device__ float g_xdot[BB*SS*DD];
__device__ float g_sess[BB*DD];
__device__ float g_out0[BB*SS*DD];
__device__ float g_out1[BB*600*DD];
__device__ float g_hglob[BB*SS*DD];
__device__ float g_hs[BB*DD];
__device__ float g_hlocal[BB*DD];
__device__ float g_c2[BB*DD];
__device__ float g_beta[BB*SS];
__device__ float g_zg[BB*DD];
__device__ float g_zhT[DD*BB];
__device__ float g_partial[BB*SS];
__device__ float g_cat[BB*SS*2*DD];
__device__ float g_logits[BB*7200];
__device__ __nv_bfloat16 g_w1b[2*DD*DD];
__device__ float g_E3top[NNODE*DD];
__device__ float g_E3bot[NNODE*DD];

__device__ __forceinline__ float sigm(float x){ return 1.0f/(1.0f+expf(-x)); }

// ---------------- k_w1bf ----------------
__global__ void k_w1bf(const float* __restrict__ w1){
  int i = blockIdx.x*256 + threadIdx.x;
  int hop = i/(DD*DD), within = i - hop*(DD*DD);
  g_w1b[i] = __float2bfloat16(w1[(size_t)hop*129*DD + within]);
}

// ---------------- k_e3 ----------------
__global__ void __launch_bounds__(128) k_e3(const float* __restrict__ emb,
                                            const float* __restrict__ w3){
  int row0 = blockIdx.x*32; int c = threadIdx.x;
  __shared__ __align__(16) float As[16][32];
  float accT[32], accB[32];
  #pragma unroll
  for(int r=0;r<32;r++){ accT[r]=0.f; accB[r]=0.f; }
  int rld = c & 31, kq = c >> 5;
  for(int k0=0;k0<DD;k0+=16){
    float4 av = *(const float4*)&emb[(size_t)(row0+rld)*DD + k0 + kq*4];
    As[kq*4+0][rld]=av.x; As[kq*4+1][rld]=av.y; As[kq*4+2][rld]=av.z; As[kq*4+3][rld]=av.w;
    __syncthreads();
    const float* wT = w3 + (size_t)k0*DD + c;
    const float* wB = w3 + (size_t)(k0+DD)*DD + c;
    #pragma unroll 4
    for(int k=0;k<16;k++){
      float bT = wT[k*DD], bB = wB[k*DD];
      #pragma unroll
      for(int r4=0;r4<8;r4++){
        float4 a = *(const float4*)&As[k][r4*4];
        accT[r4*4+0]=fmaf(a.x,bT,accT[r4*4+0]); accB[r4*4+0]=fmaf(a.x,bB,accB[r4*4+0]);
        accT[r4*4+1]=fmaf(a.y,bT,accT[r4*4+1]); accB[r4*4+1]=fmaf(a.y,bB,accB[r4*4+1]);
        accT[r4*4+2]=fmaf(a.z,bT,accT[r4*4+2]); accB[r4*4+2]=fmaf(a.z,bB,accB[r4*4+2]);
        accT[r4*4+3]=fmaf(a.w,bT,accT[r4*4+3]); accB[r4*4+3]=fmaf(a.w,bB,accB[r4*4+3]);
      }
    }
    __syncthreads();
  }
  #pragma unroll
  for(int r=0;r<32;r++){
    g_E3top[(size_t)(row0+r)*DD + c] = accT[r];
    g_E3bot[(size_t)(row0+r)*DD + c] = accB[r];
  }
}

// ---------------- k_pool ----------------
__global__ void k_pool(const int* __restrict__ inputs,
                       const int* __restrict__ as0, const int* __restrict__ as1,
                       const int* __restrict__ ssl0, const int* __restrict__ ssl1,
                       const float* __restrict__ emb){
  int blk = blockIdx.x; int tid = threadIdx.x;
  int node = inputs[blk];
  g_h[blk*DD+tid] = emb[node*DD+tid];
  float p1=0.f, p2=0.f;
  const int* L1[2] = {as0, as1};
  const int* L2[2] = {ssl0, ssl1};
  #pragma unroll
  for(int l=0;l<2;l++){
    float s=0.f,c=0.f;
    #pragma unroll
    for(int n=0;n<NNEI;n++){ int id=L1[l][blk*NNEI+n]; if(id!=0){ s+=emb[id*DD+tid]; c+=1.f; } }
    p1 += s/(c+1e-8f);
    s=0.f;c=0.f;
    #pragma unroll
    for(int n=0;n<NNEI;n++){ int id=L2[l][blk*NNEI+n]; if(id!=0){ s+=emb[id*DD+tid]; c+=1.f; } }
    p2 += s/(c+1e-8f);
  }
  g_hf1[blk*DD+tid] = p1*0.5f;
  g_hf2[blk*DD+tid] = p2*0.5f;
}

// ====== 16-row tiled matvec family (400 blocks, 128 thr, As[16][20]) ======
// staging: r=tid&15 (row), kp=tid>>4 (k-pair); FMA: c=tid (output col)

// ---------------- k_attrT ----------------
__global__ void __launch_bounds__(128) k_attrT(const float* __restrict__ attr_w){
  int row0 = blockIdx.x*16; int c = threadIdx.x;
  __shared__ __align__(16) float As[16][20];
  float acc[16];
  #pragma unroll
  for(int r=0;r<16;r++) acc[r]=0.f;
  int r=c&15, kp=c>>4;
  for(int k0=0;k0<2*DD;k0+=16){
    const float* srcA = (k0<DD)? g_h : g_hf1;
    int kk = k0 & (DD-1);
    float2 v = *(const float2*)&srcA[(size_t)(row0+r)*DD + kk + kp*2];
    As[kp*2  ][r]=v.x;
    As[kp*2+1][r]=v.y;
    __syncthreads();
    const float* wc = attr_w + (size_t)k0*DD + c;
    #pragma unroll 4
    for(int k=0;k<16;k++){
      float bk = wc[k*DD];
      #pragma unroll
      for(int r4=0;r4<4;r4++){
        float4 a = *(const float4*)&As[k][r4*4];
        acc[r4*4+0]=fmaf(a.x,bk,acc[r4*4+0]);
        acc[r4*4+1]=fmaf(a.y,bk,acc[r4*4+1]);
        acc[r4*4+2]=fmaf(a.z,bk,acc[r4*4+2]);
        acc[r4*4+3]=fmaf(a.w,bk,acc[r4*4+3]);
      }
    }
    __syncthreads();
  }
  #pragma unroll
  for(int rr=0;rr<16;rr++){
    size_t idx=(size_t)(row0+rr)*DD + c;
    float g=sigm(acc[rr]);
    float h=g_h[idx], f=g_hf1[idx];
    g_x[idx]=h;
    g_mirror[idx]=g*h+(1.f-g)*f;
  }
}

// ---------------- k_gateT ----------------
__global__ void __launch_bounds__(128) k_gateT(const float* __restrict__ w1,
                                               const float* __restrict__ w2){
  int row0 = blockIdx.x*16; int c = threadIdx.x;
  __shared__ __align__(16) float As[16][20];
  float acc[16];
  #pragma unroll
  for(int r=0;r<16;r++) acc[r]=0.f;
  int r=c&15, kp=c>>4;
  for(int k0=0;k0<2*DD;k0+=16){
    const float* srcA = (k0<DD)? g_xnew : g_mirror;
    int kk = k0 & (DD-1);
    float2 v = *(const float2*)&srcA[(size_t)(row0+r)*DD + kk + kp*2];
    As[kp*2  ][r]=v.x;
    As[kp*2+1][r]=v.y;
    __syncthreads();
    const float* wc = ((k0<DD)? w1 + (size_t)k0*DD : w2 + (size_t)(k0-DD)*DD) + c;
    #pragma unroll 4
    for(int k=0;k<16;k++){
      float bk = wc[k*DD];
      #pragma unroll
      for(int r4=0;r4<4;r4++){
        float4 a = *(const float4*)&As[k][r4*4];
        acc[r4*4+0]=fmaf(a.x,bk,acc[r4*4+0]);
        acc[r4*4+1]=fmaf(a.y,bk,acc[r4*4+1]);
        acc[r4*4+2]=fmaf(a.z,bk,acc[r4*4+2]);
        acc[r4*4+3]=fmaf(a.w,bk,acc[r4*4+3]);
      }
    }
    __syncthreads();
  }
  #pragma unroll
  for(int rr=0;rr<16;rr++){
    size_t idx=(size_t)(row0+rr)*DD + c;
    float gm=sigm(acc[rr]);
    float xv=g_xnew[idx], mv=g_mirror[idx];
    g_x[idx]      = gm*xv + (1.f-gm)*mv;
    g_mirror[idx] = gm*mv + (1.f-gm)*xv;
  }
}

// ---------------- k_highwayT ----------------
__global__ void __launch_bounds__(128) k_highwayT(const float* __restrict__ hw){
  int row0 = blockIdx.x*16; int c = threadIdx.x;
  __shared__ __align__(16) float As[16][20];
  float acc[16];
  #pragma unroll
  for(int r=0;r<16;r++) acc[r]=0.f;
  int r=c&15, kp=c>>4;
  for(int k0=0;k0<2*DD;k0+=16){
    const float* srcA = (k0<DD)? g_h : g_x;
    int kk = k0 & (DD-1);
    float2 v = *(const float2*)&srcA[(size_t)(row0+r)*DD + kk + kp*2];
    As[kp*2  ][r]=v.x;
    As[kp*2+1][r]=v.y;
    __syncthreads();
    const float* wc = hw + (size_t)k0*DD + c;
    #pragma unroll 4
    for(int k=0;k<16;k++){
      float bk = wc[k*DD];
      #pragma unroll
      for(int r4=0;r4<4;r4++){
        float4 a = *(const float4*)&As[k][r4*4];
        acc[r4*4+0]=fmaf(a.x,bk,acc[r4*4+0]);
        acc[r4*4+1]=fmaf(a.y,bk,acc[r4*4+1]);
        acc[r4*4+2]=fmaf(a.z,bk,acc[r4*4+2]);
        acc[r4*4+3]=fmaf(a.w,bk,acc[r4*4+3]);
      }
    }
    __syncthreads();
  }
  #pragma unroll
  for(int rr=0;rr<16;rr++){
    int row=row0+rr;
    size_t idx=(size_t)row*DD + c;
    float g=sigm(acc[rr]);
    float h=g_h[idx], xv=g_x[idx];
    float xd=g*h+(1.f-g)*xv;
    g_xdot[idx]=xd;
    if(row%SS==SS-1) g_hlocal[(row/SS)*DD+c]=xd;
  }
}

// ---------------- k_betaT: tiled GLU-beta (16 rows/block) ----------------
__global__ void __launch_bounds__(128) k_betaT(const int* __restrict__ inputs,
                                               const float* __restrict__ pos,
                                               const float* __restrict__ glu1,
                                               const float* __restrict__ ws){
  int row0 = blockIdx.x*16; int c = threadIdx.x;
  __shared__ __align__(16) float As[16][20];
  __shared__ float pr[16][132];
  __shared__ float red2[16][8];
  float acc[16];
  #pragma unroll
  for(int r=0;r<16;r++) acc[r]=0.f;
  int r=c&15, kp=c>>4;
  int rowr = row0 + r;
  int sr = rowr % SS;
  for(int k0=0;k0<DD;k0+=16){
    float2 v = *(const float2*)&g_xdot[(size_t)rowr*DD + k0 + kp*2];
    float2 p = *(const float2*)&pos[(size_t)sr*DD + k0 + kp*2];
    As[kp*2  ][r]=v.x+p.x;
    As[kp*2+1][r]=v.y+p.y;
    __syncthreads();
    const float* wc = glu1 + (size_t)k0*DD + c;
    #pragma unroll 4
    for(int k=0;k<16;k++){
      float bk = wc[k*DD];
      #pragma unroll
      for(int r4=0;r4<4;r4++){
        float4 a = *(const float4*)&As[k][r4*4];
        acc[r4*4+0]=fmaf(a.x,bk,acc[r4*4+0]);
        acc[r4*4+1]=fmaf(a.y,bk,acc[r4*4+1]);
        acc[r4*4+2]=fmaf(a.z,bk,acc[r4*4+2]);
        acc[r4*4+3]=fmaf(a.w,bk,acc[r4*4+3]);
      }
    }
    __syncthreads();
  }
  float wsc = ws[c];
  #pragma unroll
  for(int rr=0;rr<16;rr++){
    int row=row0+rr;
    int b=row/SS;
    float nh=sigm(acc[rr] + g_c2[b*DD+c]);
    pr[rr][c]=nh*wsc;
  }
  __syncthreads();
  {
    int rr=c>>3, seg=c&7;
    float s=0.f;
    #pragma unroll
    for(int j=0;j<16;j++) s+=pr[rr][seg*16+j];
    red2[rr][seg]=s;
  }
  __syncthreads();
  if(c<16){
    float s=0.f;
    #pragma unroll
    for(int j=0;j<8;j++) s+=red2[c][j];
    int row=row0+c;
    float mi=(inputs[row]!=0)?1.f:0.f;
    g_beta[row]=s*mi;
  }
}

// ---------------- k_sess ----------------
__global__ void k_sess(const int* __restrict__ inputs, const int* __restrict__ item,
                       const float* __restrict__ emb){
  int b=blockIdx.x, tid=threadIdx.x;
  float acc=0.f, cnt=0.f;
  for(int s=0;s<SS;s++){
    int inp=inputs[b*SS+s];
    if(inp!=0){ acc += emb[item[b*SS+s]*DD+tid]; cnt+=1.f; }
  }
  g_sess[b*DD+tid]=acc/cnt;
}

// ---------------- k_logits (unchanged from round 10/11) ----------------
#define LROWS 256
__global__ void __launch_bounds__(512) k_logits(
    const int* __restrict__ inputs, const int* __restrict__ adj_all,
    const float* __restrict__ num, const float* __restrict__ src,
    const __nv_bfloat16* __restrict__ w1b,
    const float* __restrict__ w1last, const float* __restrict__ w2,
    float* __restrict__ logits, int rowsPerB, int mode)
{
  extern __shared__ char smem[];
  const int LDAB = 136;
  __nv_bfloat16* As = (__nv_bfloat16*)smem;
  __nv_bfloat16* Bs = (__nv_bfloat16*)(smem + 69632);
  float* sess_s = (float*)(smem + 104448);
  float* wl_s   = sess_s + DD;
  float* w2_s   = wl_s + DD;
  float* nw_s   = w2_s + DD;
  int*   ci_s   = (int*)(nw_s + LROWS);

  int b = blockIdx.y;
  int row0 = blockIdx.x*LROWS;
  int tid = threadIdx.x, warp = tid>>5, lane = tid&31;

  if(tid<DD){
    sess_s[tid]=g_sess[b*DD+tid];
    wl_s[tid]  =w1last[tid];
    w2_s[tid]  =w2[tid];
  }
  if(tid<LROWS){
    int r = row0 + tid;
    int rr = (r<rowsPerB)? r : rowsPerB-1;
    int gi=rr/SAMP, s=rr-gi*SAMP;
    int node, ci;
    if(mode==1){
      int pi=gi/SAMP, ps=gi-pi*SAMP;
      node = adj_all[inputs[b*SS+pi]*SAMP+ps];
      ci = adj_all[node*SAMP+s];
    } else if(mode==0){
      node = inputs[b*SS+gi];
      ci = adj_all[node*SAMP+s];
    } else {
      node = inputs[b*SS+gi];
      ci = b*600 + rr;
    }
    ci_s[tid]=ci;
    nw_s[tid]=num[node*SAMP+s];
  }
  {
    int row=tid>>2, qb=(tid&3)*32;
    const uint4* srcw=(const uint4*)(w1b + row*DD + qb);
    uint4* dst=(uint4*)(Bs + row*LDAB + qb);
    #pragma unroll
    for(int j=0;j<4;j++) dst[j]=srcw[j];
  }
  __syncthreads();
  {
    int row=tid>>1, cb=(tid&1)*64;
    const float* ap = src + (size_t)ci_s[row]*DD + cb;
    __nv_bfloat16* dst = As + row*LDAB + cb;
    #pragma unroll
    for(int j=0;j<16;j++){
      float4 v=*(const float4*)&ap[j*4];
      float4 se=*(const float4*)&sess_s[cb+j*4];
      *(__nv_bfloat162*)&dst[j*4]   = __floats2bfloat162_rn(v.x*se.x, v.y*se.y);
      *(__nv_bfloat162*)&dst[j*4+2] = __floats2bfloat162_rn(v.z*se.z, v.w*se.w);
    }
  }
  __syncthreads();

  wmma::fragment<wmma::accumulator,16,16,16,float> acc[8];
  #pragma unroll
  for(int n=0;n<8;n++) wmma::fill_fragment(acc[n], 0.0f);

  #pragma unroll
  for(int k=0;k<DD;k+=16){
    wmma::fragment<wmma::matrix_a,16,16,16,__nv_bfloat16,wmma::row_major> af;
    wmma::load_matrix_sync(af, As + (warp*16)*LDAB + k, LDAB);
    #pragma unroll
    for(int n=0;n<8;n++){
      wmma::fragment<wmma::matrix_b,16,16,16,__nv_bfloat16,wmma::row_major> bf;
      wmma::load_matrix_sync(bf, Bs + k*LDAB + n*16, LDAB);
      wmma::mma_sync(acc[n], af, bf, acc[n]);
    }
  }
  __syncthreads();

  float* epi = (float*)Bs + warp*320;
  int r2=lane>>1, half=lane&1;
  float nw = nw_s[warp*16+r2];
  float v=0.f;
  #pragma unroll
  for(int n=0;n<8;n++){
    wmma::store_matrix_sync(epi, acc[n], 20, wmma::mem_row_major);
    __syncwarp();
    const float* crow = epi + r2*20 + half*8;
    int cb = n*16 + half*8;
    #pragma unroll
    for(int j=0;j<8;j++){
      float t = crow[j] + nw*wl_s[cb+j];
      t = (t>0.f)?t:(LEAKC*t);
      v = fmaf(t, w2_s[cb+j], v);
    }
    __syncwarp();
  }
  v += __shfl_xor_sync(0xffffffffu, v, 1);
  int rg = row0 + warp*16 + r2;
  if(half==0 && rg<rowsPerB) logits[(size_t)b*rowsPerB + rg] = v;
}

// ---------------- k_soft_agg_f ----------------
__global__ void __launch_bounds__(32) k_soft_agg_f(
    const int* __restrict__ inputs, const int* __restrict__ adj_all,
    const float* __restrict__ logits, float* __restrict__ outbuf, int N, int mode)
{
  int blk=blockIdx.x; int b=blk/N; int i=blk-b*N; int tid=threadIdx.x;
  __shared__ int   ci_s[SAMP];
  __shared__ float lg_s[SAMP];
  int node;
  if(mode==1){
    int pi=i/SAMP, ps=i-pi*SAMP;
    node = adj_all[inputs[b*SS+pi]*SAMP+ps];
  } else {
    node = inputs[b*SS+i];
  }
  if(tid<SAMP){
    ci_s[tid] = adj_all[node*SAMP+tid];
    lg_s[tid] = logits[(size_t)b*(N*SAMP) + i*SAMP + tid];
  }
  __syncwarp();
  float lg[SAMP];
  #pragma unroll
  for(int s=0;s<SAMP;s++) lg[s]=lg_s[s];
  float m=-1e30f;
  #pragma unroll
  for(int s=0;s<SAMP;s++) m=fmaxf(m,lg[s]);
  float alpha[SAMP]; float den=0.f;
  #pragma unroll
  for(int s=0;s<SAMP;s++){ alpha[s]=expf(lg[s]-m); den+=alpha[s]; }
  float inv=1.f/den;
  float4 t4 = ((const float4*)&g_E3top[(size_t)node*DD])[tid];
  float a0=0.f,a1=0.f,a2=0.f,a3=0.f;
  #pragma unroll
  for(int s=0;s<SAMP;s++){
    float4 e4 = ((const float4*)&g_E3bot[(size_t)ci_s[s]*DD])[tid];
    float al = alpha[s];
    a0=fmaf(al,e4.x,a0); a1=fmaf(al,e4.y,a1); a2=fmaf(al,e4.z,a2); a3=fmaf(al,e4.w,a3);
  }
  float4 o;
  o.x = tanhf(t4.x + a0*inv);
  o.y = tanhf(t4.y + a1*inv);
  o.z = tanhf(t4.z + a2*inv);
  o.w = tanhf(t4.w + a3*inv);
  ((float4*)&outbuf[(size_t)blk*DD])[tid] = o;
}

// ---------------- k_soft_agg2 ----------------
__global__ void __launch_bounds__(32) k_soft_agg2(const float* __restrict__ logits)
{
  int blk=blockIdx.x; int b=blk/SS; int i=blk-b*SS; int tid=threadIdx.x;
  __shared__ float lg_s[SAMP];
  if(tid<SAMP) lg_s[tid] = logits[(size_t)b*600 + i*SAMP + tid];
  __syncwarp();
  float lg[SAMP];
  #pragma unroll
  for(int s=0;s<SAMP;s++) lg[s]=lg_s[s];
  float m=-1e30f;
  #pragma unroll
  for(int s=0;s<SAMP;s++) m=fmaxf(m,lg[s]);
  float alpha[SAMP]; float den=0.f;
  #pragma unroll
  for(int s=0;s<SAMP;s++){ alpha[s]=expf(lg[s]-m); den+=alpha[s]; }
  float inv=1.f/den;
  float4 sv4 = ((const float4*)&g_out0[(size_t)blk*DD])[tid];
  const float* base = &g_out1[(size_t)(b*600 + i*SAMP)*DD];
  float a0=0.f,a1=0.f,a2=0.f,a3=0.f;
  #pragma unroll
  for(int s=0;s<SAMP;s++){
    float4 nv4 = ((const float4*)&base[(size_t)s*DD])[tid];
    float al = alpha[s];
    a0=fmaf(al,nv4.x,a0); a1=fmaf(al,nv4.y,a1); a2=fmaf(al,nv4.z,a2); a3=fmaf(al,nv4.w,a3);
  }
  float* crow = &g_cat[(size_t)blk*2*DD];
  ((float4*)crow)[tid] = sv4;
  float4 ag; ag.x=a0*inv; ag.y=a1*inv; ag.z=a2*inv; ag.w=a3*inv;
  ((float4*)(crow+DD))[tid] = ag;
}

// ---------------- k_gemm3 (mode 2) ----------------
__global__ void __launch_bounds__(128) k_gemm3(const float* __restrict__ w3,
                                               float* __restrict__ out){
  int row0 = blockIdx.x*32; int tid=threadIdx.x;
  int c = tid;
  __shared__ __align__(16) float As[16][32];
  float acc[32];
  #pragma unroll
  for(int r=0;r<32;r++) acc[r]=0.f;
  int rld = tid & 31, kq = tid >> 5;
  for(int k0=0;k0<2*DD;k0+=16){
    float4 av = *(const float4*)&g_cat[(size_t)(row0+rld)*2*DD + k0 + kq*4];
    As[kq*4+0][rld]=av.x; As[kq*4+1][rld]=av.y; As[kq*4+2][rld]=av.z; As[kq*4+3][rld]=av.w;
    __syncthreads();
    const float* w3c = w3 + (size_t)k0*DD + c;
    #pragma unroll 4
    for(int k=0;k<16;k++){
      float bk = w3c[k*DD];
      #pragma unroll
      for(int r4=0;r4<8;r4++){
        float4 a = *(const float4*)&As[k][r4*4];
        acc[r4*4+0]=fmaf(a.x,bk,acc[r4*4+0]);
        acc[r4*4+1]=fmaf(a.y,bk,acc[r4*4+1]);
        acc[r4*4+2]=fmaf(a.z,bk,acc[r4*4+2]);
        acc[r4*4+3]=fmaf(a.w,bk,acc[r4*4+3]);
      }
    }
    __syncthreads();
  }
  #pragma unroll
  for(int r=0;r<32;r++)
    out[(size_t)(row0+r)*DD + c] = tanhf(acc[r]);
}

// ---------------- k_attx ----------------
__global__ void k_attx(const int* __restrict__ adj, const float* __restrict__ a_local){
  int b=blockIdx.x; int tid=threadIdx.x;
  __shared__ __align__(16) float xs[SS][DD+4];
  __shared__ __align__(16) float al_s[4][DD];
  __shared__ float att[SS][SS+2];
  for(int idx=tid; idx<SS*DD; idx+=256){
    int i=idx>>7, d=idx&127;
    xs[i][d]=g_x[(b*SS+i)*DD+d];
  }
  for(int idx=tid; idx<4*DD; idx+=256)
    al_s[idx>>7][idx&127]=a_local[idx];
  __syncthreads();
  for(int p=tid;p<SS*SS;p+=256){
    int i=p/SS, j=p-i*SS;
    int k=adj[b*SS*SS+p];
    float e=-9e15f;
    if(k>=1 && k<=4){
      const float* al = al_s[k-1];
      float ds=0.f;
      #pragma unroll 8
      for(int d=0;d<DD;d+=4){
        float4 xi=*(const float4*)&xs[i][d];
        float4 xj=*(const float4*)&xs[j][d];
        float4 av=*(const float4*)&al[d];
        ds += xi.x*xj.x*av.x + xi.y*xj.y*av.y + xi.z*xj.z*av.z + xi.w*xj.w*av.w;
      }
      e = (ds>0.f)?ds:(LEAKC*ds);
    }
    att[i][j]=e;
  }
  __syncthreads();
  if(tid<SS){
    float m=-1e30f;
    for(int j=0;j<SS;j++) m=fmaxf(m,att[tid][j]);
    float den=0.f;
    for(int j=0;j<SS;j++){ float e=expf(att[tid][j]-m); att[tid][j]=e; den+=e; }
    float inv=1.f/den;
    for(int j=0;j<SS;j++) att[tid][j]*=inv;
  }
  __syncthreads();
  for(int q=tid;q<SS*DD;q+=256){
    int i=q>>7, d=q&127;
    float acc=0.f;
    for(int j=0;j<SS;j++) acc += att[i][j]*xs[j][d];
    g_xnew[(b*SS+i)*DD+d]=acc;
  }
}

// ---------------- k_hs ----------------
__global__ void k_hs(const int* __restrict__ inputs){
  int b=blockIdx.x, tid=threadIdx.x;
  float acc=0.f, cnt=0.f;
  for(int s=0;s<SS;s++){
    if(inputs[b*SS+s]!=0){ acc += g_hglob[(b*SS+s)*DD+tid]; cnt+=1.f; }
  }
  g_hs[b*DD+tid]=acc/cnt;
}

// ---------------- k_c2 ----------------
__global__ void k_c2(const float* __restrict__ glu2, const float* __restrict__ glu4,
                     const float* __restrict__ glu4b){
  int b=blockIdx.x, tid=threadIdx.x;
  __shared__ __align__(16) float hsr[DD], hlr[DD];
  hsr[tid]=g_hs[b*DD+tid]; hlr[tid]=g_hlocal[b*DD+tid];
  __syncthreads();
  float acc=glu4b[tid];
  const float* w2t=glu2+tid; const float* w4t=glu4+tid;
  #pragma unroll 8
  for(int k=0;k<DD;k+=4){
    float4 s4=*(const float4*)&hsr[k];
    float4 l4=*(const float4*)&hlr[k];
    acc=fmaf(s4.x,w2t[(k  )*DD],acc); acc=fmaf(l4.x,w4t[(k  )*DD],acc);
    acc=fmaf(s4.y,w2t[(k+1)*DD],acc); acc=fmaf(l4.y,w4t[(k+1)*DD],acc);
    acc=fmaf(s4.z,w2t[(k+2)*DD],acc); acc=fmaf(l4.z,w4t[(k+2)*DD],acc);
    acc=fmaf(s4.w,w2t[(k+3)*DD],acc); acc=fmaf(l4.w,w4t[(k+3)*DD],acc);
  }
  g_c2[b*DD+tid]=acc;
}

// ---------------- k_zg ----------------
__global__ void k_zg(const float* __restrict__ pos){
  int b=blockIdx.x, tid=threadIdx.x;
  float acc=0.f;
  for(int s=0;s<SS;s++)
    acc += g_beta[b*SS+s]*(g_xdot[(b*SS+s)*DD+tid]+pos[s*DD+tid]);
  g_zg[b*DD+tid]=acc;
}

// ---------------- k_zh ----------------
__global__ void k_zh(const float* __restrict__ gatew){
  int b=blockIdx.x, tid=threadIdx.x;
  __shared__ __align__(16) float zgr[DD], hlr[DD];
  zgr[tid]=g_zg[b*DD+tid]; hlr[tid]=g_hlocal[b*DD+tid];
  __syncthreads();
  const float* wt=gatew+tid;
  float acc=0.f;
  #pragma unroll 8
  for(int k=0;k<DD;k+=4){
    float4 z4=*(const float4*)&zgr[k];
    float4 l4=*(const float4*)&hlr[k];
    acc=fmaf(z4.x,wt[(k  )*DD],acc); acc=fmaf(l4.x,wt[(DD+k  )*DD],acc);
    acc=fmaf(z4.y,wt[(k+1)*DD],acc); acc=fmaf(l4.y,wt[(DD+k+1)*DD],acc);
    acc=fmaf(z4.z,wt[(k+2)*DD],acc); acc=fmaf(l4.z,wt[(DD+k+2)*DD],acc);
    acc=fmaf(z4.w,wt[(k+3)*DD],acc); acc=fmaf(l4.w,wt[(DD+k+3)*DD],acc);
  }
  float gf=sigm(acc)*0.1f;
  float zh=gf*hlr[tid]+(1.f-gf)*zgr[tid];
  g_zhT[tid*BB+b]=zh;
}

// ---------------- k_scores ----------------
__global__ void k_scores(const float* __restrict__ emb, float* __restrict__ out){
  int n0 = blockIdx.x*32; int tid=threadIdx.x;
  __shared__ __align__(16) float es[32][DD];
  int nmax = NSCORE - n0; if(nmax>32) nmax=32;
  for(int idx=tid; idx<nmax*DD; idx+=128){
    int nn=idx>>7, d=idx&127;
    es[nn][d]=emb[(size_t)(n0+nn+1)*DD+d];
  }
  __syncthreads();
  float accv[32];
  #pragma unroll
  for(int nn=0;nn<32;nn++) accv[nn]=0.f;
  for(int d=0;d<DD;d+=4){
    float z0=g_zhT[(d  )*BB+tid];
    float z1=g_zhT[(d+1)*BB+tid];
    float z2=g_zhT[(d+2)*BB+tid];
    float z3=g_zhT[(d+3)*BB+tid];
    #pragma unroll
    for(int nn=0;nn<32;nn++){
      float4 e=*reinterpret_cast<const float4*>(&es[nn][d]);
      accv[nn]=fmaf(z0,e.x,fmaf(z1,e.y,fmaf(z2,e.z,fmaf(z3,e.w,accv[nn]))));
    }
  }
  for(int nn=0;nn<nmax;nn++)
    out[1 + (size_t)tid*NSCORE + n0+nn] = accv[nn];
}

// ---------------- k_simi ----------------
__global__ void k_simi(const int* __restrict__ simi_mask){
  int blk=blockIdx.x; int b=blk/SS; int tid=threadIdx.x;
  __shared__ float f1[DD];
  __shared__ float sims[SS];
  f1[tid]   =g_hf1[blk*DD+tid];
  f1[tid+64]=g_hf1[blk*DD+tid+64];
  __syncthreads();
  if(tid<SS){
    const float* f2=&g_hf2[(b*SS+tid)*DD];
    float acc=0.f;
    for(int d=0;d<DD;d++) acc+=f1[d]*f2[d];
    sims[tid]=acc*2.0f;
  }
  __syncthreads();
  if(tid==0){
    float m=-1e30f;
    for(int j=0;j<SS;j++) m=fmaxf(m,sims[j]);
    float den=0.f;
    for(int j=0;j<SS;j++) den+=expf(sims[j]-m);
    float loss=0.f;
    for(int j=0;j<SS;j++){
      float p=expf(sims[j]-m)/den;
      float l=-logf(p+1e-8f);
      if(simi_mask[blk*SS+j]==1) loss+=l;
    }
    g_partial[blk]=loss;
  }
}

__global__ void k_simi_final(float* __restrict__ out){
  int tid=threadIdx.x;
  __shared__ float red[128];
  float a=0.f;
  for(int i=tid;i<BB*SS;i+=128) a+=g_partial[i];
  red[tid]=a; __syncthreads();
  for(int off=64;off>0;off>>=1){ if(tid<off) red[tid]+=red[tid+off]; __syncthreads(); }
  if(tid==0) out[0]=red[0]/(float)BB;
}

// ---------------- launch ----------------
extern "C" void kernel_launch(void* const* d_in, const int* in_sizes, int n_in,
                              void* d_out, int out_size){
  const int*   inputs =(const int*)  d_in[0];
  const int*   adj    =(const int*)  d_in[1];
  const int*   item   =(const int*)  d_in[2];
  const int*   simi   =(const int*)  d_in[3];
  const int*   as0    =(const int*)  d_in[4];
  const int*   as1    =(const int*)  d_in[5];
  const int*   ssl0   =(const int*)  d_in[6];
  const int*   ssl1   =(const int*)  d_in[7];
  const int*   adj_all=(const int*)  d_in[9];
  const float* num    =(const float*)d_in[10];
  const float* emb    =(const float*)d_in[11];
  const float* pos    =(const float*)d_in[12];
  const float* a_local=(const float*)d_in[13];
  const float* mir1   =(const float*)d_in[14];
  const float* mir2   =(const float*)d_in[15];
  const float* gw1    =(const float*)d_in[16];
  const float* gw2    =(const float*)d_in[17];
  const float* gw3    =(const float*)d_in[18];
  const float* attr   =(const float*)d_in[19];
  const float* hww    =(const float*)d_in[20];
  const float* glu1   =(const float*)d_in[21];
  const float* glu2   =(const float*)d_in[22];
  const float* glu4   =(const float*)d_in[23];
  const float* glu4b  =(const float*)d_in[24];
  const float* ws     =(const float*)d_in[25];
  const float* gatew  =(const float*)d_in[26];
  float* out=(float*)d_out;

  float* p_out0;   cudaGetSymbolAddress((void**)&p_out0,  g_out0);
  float* p_out1;   cudaGetSymbolAddress((void**)&p_out1,  g_out1);
  float* p_hglob;  cudaGetSymbolAddress((void**)&p_hglob, g_hglob);
  float* p_logits; cudaGetSymbolAddress((void**)&p_logits,g_logits);
  __nv_bfloat16* p_w1b; cudaGetSymbolAddress((void**)&p_w1b, g_w1b);

  const int LOGITS_SMEM = 69632 + 34816 + (3*DD + LROWS)*4 + LROWS*4;
  cudaFuncSetAttribute(k_logits, cudaFuncAttributeMaxDynamicSharedMemorySize, LOGITS_SMEM);

  k_w1bf<<<2*DD*DD/256,256>>>(gw1);
  k_e3<<<NNODE/32,128>>>(emb, gw3);
  k_pool<<<BB*SS,DD>>>(inputs, as0, as1, ssl0, ssl1, emb);
  k_attrT<<<BB*SS/16,128>>>(attr);
  k_sess<<<BB,DD>>>(inputs,item,emb);

  // mode 1: TC logits -> E3-fused soft_agg -> out1
  {
    dim3 g((7200+LROWS-1)/LROWS, BB);
    k_logits<<<g,512,LOGITS_SMEM>>>(inputs,adj_all,num, emb, p_w1b, gw1+DD*DD, gw2, p_logits, 7200, 1);
  }
  k_soft_agg_f<<<BB*600,32>>>(inputs,adj_all, p_logits, p_out1, 600, 1);

  // mode 0: TC logits -> E3-fused soft_agg -> out0
  {
    dim3 g((600+LROWS-1)/LROWS, BB);
    k_logits<<<g,512,LOGITS_SMEM>>>(inputs,adj_all,num, emb, p_w1b, gw1+DD*DD, gw2, p_logits, 600, 0);
  }
  k_soft_agg_f<<<BB*SS,32>>>(inputs,adj_all, p_logits, p_out0, SS, 0);

  // mode 2: TC logits (src=out1, hop-1 W1) -> cat -> gemm3 hop-1 -> hglob
  {
    dim3 g((600+LROWS-1)/LROWS, BB);
    k_logits<<<g,512,LOGITS_SMEM>>>(inputs,adj_all,num, p_out1, p_w1b+DD*DD, gw1+129*DD+DD*DD, gw2+DD, p_logits, 600, 2);
  }
  k_soft_agg2<<<BB*SS,32>>>(p_logits);
  k_gemm3<<<BB*SS/32,128>>>(gw3+256*DD, p_hglob);

  // local branch
  for(int it=0; it<2; it++){
    k_attx<<<BB,256>>>(adj, a_local + it*4*DD);
    k_gateT<<<BB*SS/16,128>>>(mir1 + it*DD*DD, mir2 + it*DD*DD);
  }
  k_highwayT<<<BB*SS/16,128>>>(hww);
  k_hs<<<BB,DD>>>(inputs);
  k_c2<<<BB,DD>>>(glu2,glu4,glu4b);
  k_betaT<<<BB*SS/16,128>>>(inputs,pos,glu1,ws);
  k_zg<<<BB,DD>>>(pos);
  k_zh<<<BB,DD>>>(gatew);

  k_scores<<<(NSCORE+31)/32,128>>>(emb,out);
  k_simi<<<BB*SS,64>>>(simi);
  k_simi_final<<<1,128>>>(out);
}

// round 13
// speedup vs baseline: 1.0528x; 1.0119x over previous
#include <cuda_runtime.h>
#include <cuda_bf16.h>
#include <math.h>
#include <mma.h>
using namespace nvcuda;

#define BB 128
#define SS 50
#define DD 128
#define NNODE 40000
#define SAMP 12
#define NNEI 8
#define LEAKC 0.2f
#define NSCORE 39999

// ---------------- scratch (device globals; no allocation) ----------------
__device__ float g_h[BB*SS*DD];
__device__ float g_hf1[BB*SS*DD];
__device__ float g_hf2[BB*SS*DD];
__device__ float g_x[BB*SS*DD];
__device__ float g_mirror[BB*SS*DD];
__device__ float g_xnew[BB*SS*DD];
__device__ float g_xdot[BB*SS*DD];
__device__ float g_sess[BB*DD];
__device__ float g_out0[BB*SS*DD];
__device__ float g_out1[BB*600*DD];
__device__ float g_hglob[BB*SS*DD];
__device__ float g_hs[BB*DD];
__device__ float g_hlocal[BB*DD];
__device__ float g_c2[BB*DD];
__device__ float g_beta[BB*SS];
__device__ float g_zg[BB*DD];
__device__ float g_zhT[DD*BB];
__device__ float g_partial[BB*SS];
__device__ float g_cat[BB*SS*2*DD];
__device__ float g_logits[BB*7200];
__device__ __nv_bfloat16 g_w1b[2*DD*DD];
__device__ float g_E3top[NNODE*DD];
__device__ float g_E3bot[NNODE*DD];

__device__ __forceinline__ float sigm(float x){ return 1.0f/(1.0f+expf(-x)); }

// ---------------- k_w1bf ----------------
__global__ void k_w1bf(const float* __restrict__ w1){
  int i = blockIdx.x*256 + threadIdx.x;
  int hop = i/(DD*DD), within = i - hop*(DD*DD);
  g_w1b[i] = __float2bfloat16(w1[(size_t)hop*129*DD + within]);
}

// ---------------- k_e3 ----------------
__global__ void __launch_bounds__(128) k_e3(const float* __restrict__ emb,
                                            const float* __restrict__ w3){
  int row0 = blockIdx.x*32; int c = threadIdx.x;
  __shared__ __align__(16) float As[16][32];
  float accT[32], accB[32];
  #pragma unroll
  for(int r=0;r<32;r++){ accT[r]=0.f; accB[r]=0.f; }
  int rld = c & 31, kq = c >> 5;
  for(int k0=0;k0<DD;k0+=16){
    float4 av = *(const float4*)&emb[(size_t)(row0+rld)*DD + k0 + kq*4];
    As[kq*4+0][rld]=av.x; As[kq*4+1][rld]=av.y; As[kq*4+2][rld]=av.z; As[kq*4+3][rld]=av.w;
    __syncthreads();
    const float* wT = w3 + (size_t)k0*DD + c;
    const float* wB = w3 + (size_t)(k0+DD)*DD + c;
    #pragma unroll 4
    for(int k=0;k<16;k++){
      float bT = wT[k*DD], bB = wB[k*DD];
      #pragma unroll
      for(int r4=0;r4<8;r4++){
        float4 a = *(const float4*)&As[k][r4*4];
        accT[r4*4+0]=fmaf(a.x,bT,accT[r4*4+0]); accB[r4*4+0]=fmaf(a.x,bB,accB[r4*4+0]);
        accT[r4*4+1]=fmaf(a.y,bT,accT[r4*4+1]); accB[r4*4+1]=fmaf(a.y,bB,accB[r4*4+1]);
        accT[r4*4+2]=fmaf(a.z,bT,accT[r4*4+2]); accB[r4*4+2]=fmaf(a.z,bB,accB[r4*4+2]);
        accT[r4*4+3]=fmaf(a.w,bT,accT[r4*4+3]); accB[r4*4+3]=fmaf(a.w,bB,accB[r4*4+3]);
      }
    }
    __syncthreads();
  }
  #pragma unroll
  for(int r=0;r<32;r++){
    g_E3top[(size_t)(row0+r)*DD + c] = accT[r];
    g_E3bot[(size_t)(row0+r)*DD + c] = accB[r];
  }
}

// ---------------- k_pool ----------------
__global__ void k_pool(const int* __restrict__ inputs,
                       const int* __restrict__ as0, const int* __restrict__ as1,
                       const int* __restrict__ ssl0, const int* __restrict__ ssl1,
                       const float* __restrict__ emb){
  int blk = blockIdx.x; int tid = threadIdx.x;
  int node = inputs[blk];
  g_h[blk*DD+tid] = emb[node*DD+tid];
  float p1=0.f, p2=0.f;
  const int* L1[2] = {as0, as1};
  const int* L2[2] = {ssl0, ssl1};
  #pragma unroll
  for(int l=0;l<2;l++){
    float s=0.f,c=0.f;
    #pragma unroll
    for(int n=0;n<NNEI;n++){ int id=L1[l][blk*NNEI+n]; if(id!=0){ s+=emb[id*DD+tid]; c+=1.f; } }
    p1 += s/(c+1e-8f);
    s=0.f;c=0.f;
    #pragma unroll
    for(int n=0;n<NNEI;n++){ int id=L2[l][blk*NNEI+n]; if(id!=0){ s+=emb[id*DD+tid]; c+=1.f; } }
    p2 += s/(c+1e-8f);
  }
  g_hf1[blk*DD+tid] = p1*0.5f;
  g_hf2[blk*DD+tid] = p2*0.5f;
}

// ====== 16-row, 256-thread, double-buffered matvec family ======
// half = tid>>7 selects rows 0-7 / 8-15; c = tid&127 output col.
// staging: sk=tid&15 (k within chunk, coalesced), sr=tid>>4 (row).

// ---------------- k_attrT ----------------
__global__ void __launch_bounds__(256) k_attrT(const float* __restrict__ attr_w){
  int row0 = blockIdx.x*16;
  int tid=threadIdx.x;
  int half = tid>>7, c = tid & 127;
  int sk = tid & 15, sr = tid >> 4;
  __shared__ __align__(16) float As[2][16][17];
  float acc[8];
  #pragma unroll
  for(int r=0;r<8;r++) acc[r]=0.f;

  float stage = g_h[(size_t)(row0+sr)*DD + sk];
  As[0][sk][sr] = stage;
  __syncthreads();

  for(int ch=0; ch<16; ch++){
    int buf = ch & 1;
    if(ch<15){
      int k0n = (ch+1)*16;
      const float* srcA = (k0n<DD)? g_h : g_hf1;
      stage = srcA[(size_t)(row0+sr)*DD + (k0n & (DD-1)) + sk];
    }
    const float* wc = attr_w + (size_t)(ch*16)*DD + c;
    #pragma unroll 4
    for(int k=0;k<16;k++){
      float bk = wc[k*DD];
      #pragma unroll
      for(int r=0;r<8;r++)
        acc[r] = fmaf(As[buf][k][half*8+r], bk, acc[r]);
    }
    if(ch<15){
      As[buf^1][sk][sr] = stage;
      __syncthreads();
    }
  }
  #pragma unroll
  for(int r=0;r<8;r++){
    int row = row0 + half*8 + r;
    size_t idx=(size_t)row*DD + c;
    float g=sigm(acc[r]);
    float h=g_h[idx], f=g_hf1[idx];
    g_x[idx]=h;
    g_mirror[idx]=g*h+(1.f-g)*f;
  }
}

// ---------------- k_gateT ----------------
__global__ void __launch_bounds__(256) k_gateT(const float* __restrict__ w1,
                                               const float* __restrict__ w2){
  int row0 = blockIdx.x*16;
  int tid=threadIdx.x;
  int half = tid>>7, c = tid & 127;
  int sk = tid & 15, sr = tid >> 4;
  __shared__ __align__(16) float As[2][16][17];
  float acc[8];
  #pragma unroll
  for(int r=0;r<8;r++) acc[r]=0.f;

  float stage = g_xnew[(size_t)(row0+sr)*DD + sk];
  As[0][sk][sr] = stage;
  __syncthreads();

  for(int ch=0; ch<16; ch++){
    int buf = ch & 1;
    if(ch<15){
      int k0n = (ch+1)*16;
      const float* srcA = (k0n<DD)? g_xnew : g_mirror;
      stage = srcA[(size_t)(row0+sr)*DD + (k0n & (DD-1)) + sk];
    }
    int k0 = ch*16;
    const float* wc = ((k0<DD)? w1 + (size_t)k0*DD : w2 + (size_t)(k0-DD)*DD) + c;
    #pragma unroll 4
    for(int k=0;k<16;k++){
      float bk = wc[k*DD];
      #pragma unroll
      for(int r=0;r<8;r++)
        acc[r] = fmaf(As[buf][k][half*8+r], bk, acc[r]);
    }
    if(ch<15){
      As[buf^1][sk][sr] = stage;
      __syncthreads();
    }
  }
  #pragma unroll
  for(int r=0;r<8;r++){
    int row = row0 + half*8 + r;
    size_t idx=(size_t)row*DD + c;
    float gm=sigm(acc[r]);
    float xv=g_xnew[idx], mv=g_mirror[idx];
    g_x[idx]      = gm*xv + (1.f-gm)*mv;
    g_mirror[idx] = gm*mv + (1.f-gm)*xv;
  }
}

// ---------------- k_highwayT ----------------
__global__ void __launch_bounds__(256) k_highwayT(const float* __restrict__ hw){
  int row0 = blockIdx.x*16;
  int tid=threadIdx.x;
  int half = tid>>7, c = tid & 127;
  int sk = tid & 15, sr = tid >> 4;
  __shared__ __align__(16) float As[2][16][17];
  float acc[8];
  #pragma unroll
  for(int r=0;r<8;r++) acc[r]=0.f;

  float stage = g_h[(size_t)(row0+sr)*DD + sk];
  As[0][sk][sr] = stage;
  __syncthreads();

  for(int ch=0; ch<16; ch++){
    int buf = ch & 1;
    if(ch<15){
      int k0n = (ch+1)*16;
      const float* srcA = (k0n<DD)? g_h : g_x;
      stage = srcA[(size_t)(row0+sr)*DD + (k0n & (DD-1)) + sk];
    }
    const float* wc = hw + (size_t)(ch*16)*DD + c;
    #pragma unroll 4
    for(int k=0;k<16;k++){
      float bk = wc[k*DD];
      #pragma unroll
      for(int r=0;r<8;r++)
        acc[r] = fmaf(As[buf][k][half*8+r], bk, acc[r]);
    }
    if(ch<15){
      As[buf^1][sk][sr] = stage;
      __syncthreads();
    }
  }
  #pragma unroll
  for(int r=0;r<8;r++){
    int row = row0 + half*8 + r;
    size_t idx=(size_t)row*DD + c;
    float g=sigm(acc[r]);
    float h=g_h[idx], xv=g_x[idx];
    float xd=g*h+(1.f-g)*xv;
    g_xdot[idx]=xd;
    if(row%SS==SS-1) g_hlocal[(row/SS)*DD+c]=xd;
  }
}

// ---------------- k_betaT: 16 rows, 256 thr, K=128 (8 chunks) ----------------
__global__ void __launch_bounds__(256) k_betaT(const int* __restrict__ inputs,
                                               const float* __restrict__ pos,
                                               const float* __restrict__ glu1,
                                               const float* __restrict__ ws){
  int row0 = blockIdx.x*16;
  int tid=threadIdx.x;
  int half = tid>>7, c = tid & 127;
  int sk = tid & 15, sr = tid >> 4;
  __shared__ __align__(16) float As[2][16][17];
  __shared__ float pr[16][132];
  __shared__ float red2[16][16];
  float acc[8];
  #pragma unroll
  for(int r=0;r<8;r++) acc[r]=0.f;

  int rowr = row0 + sr;
  int srx = rowr % SS;
  float stage = g_xdot[(size_t)rowr*DD + sk] + pos[(size_t)srx*DD + sk];
  As[0][sk][sr] = stage;
  __syncthreads();

  for(int ch=0; ch<8; ch++){
    int buf = ch & 1;
    if(ch<7){
      int k0n = (ch+1)*16;
      stage = g_xdot[(size_t)rowr*DD + k0n + sk] + pos[(size_t)srx*DD + k0n + sk];
    }
    const float* wc = glu1 + (size_t)(ch*16)*DD + c;
    #pragma unroll 4
    for(int k=0;k<16;k++){
      float bk = wc[k*DD];
      #pragma unroll
      for(int r=0;r<8;r++)
        acc[r] = fmaf(As[buf][k][half*8+r], bk, acc[r]);
    }
    if(ch<7){
      As[buf^1][sk][sr] = stage;
      __syncthreads();
    }
  }
  float wsc = ws[c];
  #pragma unroll
  for(int r=0;r<8;r++){
    int row = row0 + half*8 + r;
    int b=row/SS;
    float nh=sigm(acc[r] + g_c2[b*DD+c]);
    pr[half*8+r][c]=nh*wsc;
  }
  __syncthreads();
  {
    int rr=tid>>4, seg=tid&15;   // 16 rows x 16 segments of 8
    float s=0.f;
    #pragma unroll
    for(int j=0;j<8;j++) s+=pr[rr][seg*8+j];
    red2[rr][seg]=s;
  }
  __syncthreads();
  if(tid<16){
    float s=0.f;
    #pragma unroll
    for(int j=0;j<16;j++) s+=red2[tid][j];
    int row=row0+tid;
    float mi=(inputs[row]!=0)?1.f:0.f;
    g_beta[row]=s*mi;
  }
}

// ---------------- k_sess ----------------
__global__ void k_sess(const int* __restrict__ inputs, const int* __restrict__ item,
                       const float* __restrict__ emb){
  int b=blockIdx.x, tid=threadIdx.x;
  float acc=0.f, cnt=0.f;
  for(int s=0;s<SS;s++){
    int inp=inputs[b*SS+s];
    if(inp!=0){ acc += emb[item[b*SS+s]*DD+tid]; cnt+=1.f; }
  }
  g_sess[b*DD+tid]=acc/cnt;
}

// ---------------- k_logits ----------------
#define LROWS 256
__global__ void __launch_bounds__(512) k_logits(
    const int* __restrict__ inputs, const int* __restrict__ adj_all,
    const float* __restrict__ num, const float* __restrict__ src,
    const __nv_bfloat16* __restrict__ w1b,
    const float* __restrict__ w1last, const float* __restrict__ w2,
    float* __restrict__ logits, int rowsPerB, int mode)
{
  extern __shared__ char smem[];
  const int LDAB = 136;
  __nv_bfloat16* As = (__nv_bfloat16*)smem;
  __nv_bfloat16* Bs = (__nv_bfloat16*)(smem + 69632);
  float* sess_s = (float*)(smem + 104448);
  float* wl_s   = sess_s + DD;
  float* w2_s   = wl_s + DD;
  float* nw_s   = w2_s + DD;
  int*   ci_s   = (int*)(nw_s + LROWS);

  int b = blockIdx.y;
  int row0 = blockIdx.x*LROWS;
  int tid = threadIdx.x, warp = tid>>5, lane = tid&31;

  if(tid<DD){
    sess_s[tid]=g_sess[b*DD+tid];
    wl_s[tid]  =w1last[tid];
    w2_s[tid]  =w2[tid];
  }
  if(tid<LROWS){
    int r = row0 + tid;
    int rr = (r<rowsPerB)? r : rowsPerB-1;
    int gi=rr/SAMP, s=rr-gi*SAMP;
    int node, ci;
    if(mode==1){
      int pi=gi/SAMP, ps=gi-pi*SAMP;
      node = adj_all[inputs[b*SS+pi]*SAMP+ps];
      ci = adj_all[node*SAMP+s];
    } else if(mode==0){
      node = inputs[b*SS+gi];
      ci = adj_all[node*SAMP+s];
    } else {
      node = inputs[b*SS+gi];
      ci = b*600 + rr;
    }
    ci_s[tid]=ci;
    nw_s[tid]=num[node*SAMP+s];
  }
  {
    int row=tid>>2, qb=(tid&3)*32;
    const uint4* srcw=(const uint4*)(w1b + row*DD + qb);
    uint4* dst=(uint4*)(Bs + row*LDAB + qb);
    #pragma unroll
    for(int j=0;j<4;j++) dst[j]=srcw[j];
  }
  __syncthreads();
  {
    int row=tid>>1, cb=(tid&1)*64;
    const float* ap = src + (size_t)ci_s[row]*DD + cb;
    __nv_bfloat16* dst = As + row*LDAB + cb;
    #pragma unroll
    for(int j=0;j<16;j++){
      float4 v=*(const float4*)&ap[j*4];
      float4 se=*(const float4*)&sess_s[cb+j*4];
      *(__nv_bfloat162*)&dst[j*4]   = __floats2bfloat162_rn(v.x*se.x, v.y*se.y);
      *(__nv_bfloat162*)&dst[j*4+2] = __floats2bfloat162_rn(v.z*se.z, v.w*se.w);
    }
  }
  __syncthreads();

  wmma::fragment<wmma::accumulator,16,16,16,float> acc[8];
  #pragma unroll
  for(int n=0;n<8;n++) wmma::fill_fragment(acc[n], 0.0f);

  #pragma unroll
  for(int k=0;k<DD;k+=16){
    wmma::fragment<wmma::matrix_a,16,16,16,__nv_bfloat16,wmma::row_major> af;
    wmma::load_matrix_sync(af, As + (warp*16)*LDAB + k, LDAB);
    #pragma unroll
    for(int n=0;n<8;n++){
      wmma::fragment<wmma::matrix_b,16,16,16,__nv_bfloat16,wmma::row_major> bf;
      wmma::load_matrix_sync(bf, Bs + k*LDAB + n*16, LDAB);
      wmma::mma_sync(acc[n], af, bf, acc[n]);
    }
  }
  __syncthreads();

  float* epi = (float*)Bs + warp*320;
  int r2=lane>>1, half=lane&1;
  float nw = nw_s[warp*16+r2];
  float v=0.f;
  #pragma unroll
  for(int n=0;n<8;n++){
    wmma::store_matrix_sync(epi, acc[n], 20, wmma::mem_row_major);
    __syncwarp();
    const float* crow = epi + r2*20 + half*8;
    int cb = n*16 + half*8;
    #pragma unroll
    for(int j=0;j<8;j++){
      float t = crow[j] + nw*wl_s[cb+j];
      t = (t>0.f)?t:(LEAKC*t);
      v = fmaf(t, w2_s[cb+j], v);
    }
    __syncwarp();
  }
  v += __shfl_xor_sync(0xffffffffu, v, 1);
  int rg = row0 + warp*16 + r2;
  if(half==0 && rg<rowsPerB) logits[(size_t)b*rowsPerB + rg] = v;
}

// ---------------- k_soft_agg_f ----------------
__global__ void __launch_bounds__(32) k_soft_agg_f(
    const int* __restrict__ inputs, const int* __restrict__ adj_all,
    const float* __restrict__ logits, float* __restrict__ outbuf, int N, int mode)
{
  int blk=blockIdx.x; int b=blk/N; int i=blk-b*N; int tid=threadIdx.x;
  __shared__ int   ci_s[SAMP];
  __shared__ float lg_s[SAMP];
  int node;
  if(mode==1){
    int pi=i/SAMP, ps=i-pi*SAMP;
    node = adj_all[inputs[b*SS+pi]*SAMP+ps];
  } else {
    node = inputs[b*SS+i];
  }
  if(tid<SAMP){
    ci_s[tid] = adj_all[node*SAMP+tid];
    lg_s[tid] = logits[(size_t)b*(N*SAMP) + i*SAMP + tid];
  }
  __syncwarp();
  float lg[SAMP];
  #pragma unroll
  for(int s=0;s<SAMP;s++) lg[s]=lg_s[s];
  float m=-1e30f;
  #pragma unroll
  for(int s=0;s<SAMP;s++) m=fmaxf(m,lg[s]);
  float alpha[SAMP]; float den=0.f;
  #pragma unroll
  for(int s=0;s<SAMP;s++){ alpha[s]=expf(lg[s]-m); den+=alpha[s]; }
  float inv=1.f/den;
  float4 t4 = ((const float4*)&g_E3top[(size_t)node*DD])[tid];
  float a0=0.f,a1=0.f,a2=0.f,a3=0.f;
  #pragma unroll
  for(int s=0;s<SAMP;s++){
    float4 e4 = ((const float4*)&g_E3bot[(size_t)ci_s[s]*DD])[tid];
    float al = alpha[s];
    a0=fmaf(al,e4.x,a0); a1=fmaf(al,e4.y,a1); a2=fmaf(al,e4.z,a2); a3=fmaf(al,e4.w,a3);
  }
  float4 o;
  o.x = tanhf(t4.x + a0*inv);
  o.y = tanhf(t4.y + a1*inv);
  o.z = tanhf(t4.z + a2*inv);
  o.w = tanhf(t4.w + a3*inv);
  ((float4*)&outbuf[(size_t)blk*DD])[tid] = o;
}

// ---------------- k_soft_agg2 ----------------
__global__ void __launch_bounds__(32) k_soft_agg2(const float* __restrict__ logits)
{
  int blk=blockIdx.x; int b=blk/SS; int i=blk-b*SS; int tid=threadIdx.x;
  __shared__ float lg_s[SAMP];
  if(tid<SAMP) lg_s[tid] = logits[(size_t)b*600 + i*SAMP + tid];
  __syncwarp();
  float lg[SAMP];
  #pragma unroll
  for(int s=0;s<SAMP;s++) lg[s]=lg_s[s];
  float m=-1e30f;
  #pragma unroll
  for(int s=0;s<SAMP;s++) m=fmaxf(m,lg[s]);
  float alpha[SAMP]; float den=0.f;
  #pragma unroll
  for(int s=0;s<SAMP;s++){ alpha[s]=expf(lg[s]-m); den+=alpha[s]; }
  float inv=1.f/den;
  float4 sv4 = ((const float4*)&g_out0[(size_t)blk*DD])[tid];
  const float* base = &g_out1[(size_t)(b*600 + i*SAMP)*DD];
  float a0=0.f,a1=0.f,a2=0.f,a3=0.f;
  #pragma unroll
  for(int s=0;s<SAMP;s++){
    float4 nv4 = ((const float4*)&base[(size_t)s*DD])[tid];
    float al = alpha[s];
    a0=fmaf(al,nv4.x,a0); a1=fmaf(al,nv4.y,a1); a2=fmaf(al,nv4.z,a2); a3=fmaf(al,nv4.w,a3);
  }
  float* crow = &g_cat[(size_t)blk*2*DD];
  ((float4*)crow)[tid] = sv4;
  float4 ag; ag.x=a0*inv; ag.y=a1*inv; ag.z=a2*inv; ag.w=a3*inv;
  ((float4*)(crow+DD))[tid] = ag;
}

// ---------------- k_gemm3 (mode 2) ----------------
__global__ void __launch_bounds__(128) k_gemm3(const float* __restrict__ w3,
                                               float* __restrict__ out){
  int row0 = blockIdx.x*32; int tid=threadIdx.x;
  int c = tid;
  __shared__ __align__(16) float As[16][32];
  float acc[32];
  #pragma unroll
  for(int r=0;r<32;r++) acc[r]=0.f;
  int rld = tid & 31, kq = tid >> 5;
  for(int k0=0;k0<2*DD;k0+=16){
    float4 av = *(const float4*)&g_cat[(size_t)(row0+rld)*2*DD + k0 + kq*4];
    As[kq*4+0][rld]=av.x; As[kq*4+1][rld]=av.y; As[kq*4+2][rld]=av.z; As[kq*4+3][rld]=av.w;
    __syncthreads();
    const float* w3c = w3 + (size_t)k0*DD + c;
    #pragma unroll 4
    for(int k=0;k<16;k++){
      float bk = w3c[k*DD];
      #pragma unroll
      for(int r4=0;r4<8;r4++){
        float4 a = *(const float4*)&As[k][r4*4];
        acc[r4*4+0]=fmaf(a.x,bk,acc[r4*4+0]);
        acc[r4*4+1]=fmaf(a.y,bk,acc[r4*4+1]);
        acc[r4*4+2]=fmaf(a.z,bk,acc[r4*4+2]);
        acc[r4*4+3]=fmaf(a.w,bk,acc[r4*4+3]);
      }
    }
    __syncthreads();
  }
  #pragma unroll
  for(int r=0;r<32;r++)
    out[(size_t)(row0+r)*DD + c] = tanhf(acc[r]);
}

// ---------------- k_attx ----------------
__global__ void k_attx(const int* __restrict__ adj, const float* __restrict__ a_local){
  int b=blockIdx.x; int tid=threadIdx.x;
  __shared__ __align__(16) float xs[SS][DD+4];
  __shared__ __align__(16) float al_s[4][DD];
  __shared__ float att[SS][SS+2];
  for(int idx=tid; idx<SS*DD; idx+=256){
    int i=idx>>7, d=idx&127;
    xs[i][d]=g_x[(b*SS+i)*DD+d];
  }
  for(int idx=tid; idx<4*DD; idx+=256)
    al_s[idx>>7][idx&127]=a_local[idx];
  __syncthreads();
  for(int p=tid;p<SS*SS;p+=256){
    int i=p/SS, j=p-i*SS;
    int k=adj[b*SS*SS+p];
    float e=-9e15f;
    if(k>=1 && k<=4){
      const float* al = al_s[k-1];
      float ds=0.f;
      #pragma unroll 8
      for(int d=0;d<DD;d+=4){
        float4 xi=*(const float4*)&xs[i][d];
        float4 xj=*(const float4*)&xs[j][d];
        float4 av=*(const float4*)&al[d];
        ds += xi.x*xj.x*av.x + xi.y*xj.y*av.y + xi.z*xj.z*av.z + xi.w*xj.w*av.w;
      }
      e = (ds>0.f)?ds:(LEAKC*ds);
    }
    att[i][j]=e;
  }
  __syncthreads();
  if(tid<SS){
    float m=-1e30f;
    for(int j=0;j<SS;j++) m=fmaxf(m,att[tid][j]);
    float den=0.f;
    for(int j=0;j<SS;j++){ float e=expf(att[tid][j]-m); att[tid][j]=e; den+=e; }
    float inv=1.f/den;
    for(int j=0;j<SS;j++) att[tid][j]*=inv;
  }
  __syncthreads();
  for(int q=tid;q<SS*DD;q+=256){
    int i=q>>7, d=q&127;
    float acc=0.f;
    for(int j=0;j<SS;j++) acc += att[i][j]*xs[j][d];
    g_xnew[(b*SS+i)*DD+d]=acc;
  }
}

// ---------------- k_hs ----------------
__global__ void k_hs(const int* __restrict__ inputs){
  int b=blockIdx.x, tid=threadIdx.x;
  float acc=0.f, cnt=0.f;
  for(int s=0;s<SS;s++){
    if(inputs[b*SS+s]!=0){ acc += g_hglob[(b*SS+s)*DD+tid]; cnt+=1.f; }
  }
  g_hs[b*DD+tid]=acc/cnt;
}

// ---------------- k_c2 ----------------
__global__ void k_c2(const float* __restrict__ glu2, const float* __restrict__ glu4,
                     const float* __restrict__ glu4b){
  int b=blockIdx.x, tid=threadIdx.x;
  __shared__ __align__(16) float hsr[DD], hlr[DD];
  hsr[tid]=g_hs[b*DD+tid]; hlr[tid]=g_hlocal[b*DD+tid];
  __syncthreads();
  float acc=glu4b[tid];
  const float* w2t=glu2+tid; const float* w4t=glu4+tid;
  #pragma unroll 8
  for(int k=0;k<DD;k+=4){
    float4 s4=*(const float4*)&hsr[k];
    float4 l4=*(const float4*)&hlr[k];
    acc=fmaf(s4.x,w2t[(k  )*DD],acc); acc=fmaf(l4.x,w4t[(k  )*DD],acc);
    acc=fmaf(s4.y,w2t[(k+1)*DD],acc); acc=fmaf(l4.y,w4t[(k+1)*DD],acc);
    acc=fmaf(s4.z,w2t[(k+2)*DD],acc); acc=fmaf(l4.z,w4t[(k+2)*DD],acc);
    acc=fmaf(s4.w,w2t[(k+3)*DD],acc); acc=fmaf(l4.w,w4t[(k+3)*DD],acc);
  }
  g_c2[b*DD+tid]=acc;
}

// ---------------- k_zg ----------------
__global__ void k_zg(const float* __restrict__ pos){
  int b=blockIdx.x, tid=threadIdx.x;
  float acc=0.f;
  for(int s=0;s<SS;s++)
    acc += g_beta[b*SS+s]*(g_xdot[(b*SS+s)*DD+tid]+pos[s*DD+tid]);
  g_zg[b*DD+tid]=acc;
}

// ---------------- k_zh ----------------
__global__ void k_zh(const float* __restrict__ gatew){
  int b=blockIdx.x, tid=threadIdx.x;
  __shared__ __align__(16) float zgr[DD], hlr[DD];
  zgr[tid]=g_zg[b*DD+tid]; hlr[tid]=g_hlocal[b*DD+tid];
  __syncthreads();
  const float* wt=gatew+tid;
  float acc=0.f;
  #pragma unroll 8
  for(int k=0;k<DD;k+=4){
    float4 z4=*(const float4*)&zgr[k];
    float4 l4=*(const float4*)&hlr[k];
    acc=fmaf(z4.x,wt[(k  )*DD],acc); acc=fmaf(l4.x,wt[(DD+k  )*DD],acc);
    acc=fmaf(z4.y,wt[(k+1)*DD],acc); acc=fmaf(l4.y,wt[(DD+k+1)*DD],acc);
    acc=fmaf(z4.z,wt[(k+2)*DD],acc); acc=fmaf(l4.z,wt[(DD+k+2)*DD],acc);
    acc=fmaf(z4.w,wt[(k+3)*DD],acc); acc=fmaf(l4.w,wt[(DD+k+3)*DD],acc);
  }
  float gf=sigm(acc)*0.1f;
  float zh=gf*hlr[tid]+(1.f-gf)*zgr[tid];
  g_zhT[tid*BB+b]=zh;
}

// ---------------- k_scores ----------------
__global__ void k_scores(const float* __restrict__ emb, float* __restrict__ out){
  int n0 = blockIdx.x*32; int tid=threadIdx.x;
  __shared__ __align__(16) float es[32][DD];
  int nmax = NSCORE - n0; if(nmax>32) nmax=32;
  for(int idx=tid; idx<nmax*DD; idx+=128){
    int nn=idx>>7, d=idx&127;
    es[nn][d]=emb[(size_t)(n0+nn+1)*DD+d];
  }
  __syncthreads();
  float accv[32];
  #pragma unroll
  for(int nn=0;nn<32;nn++) accv[nn]=0.f;
  for(int d=0;d<DD;d+=4){
    float z0=g_zhT[(d  )*BB+tid];
    float z1=g_zhT[(d+1)*BB+tid];
    float z2=g_zhT[(d+2)*BB+tid];
    float z3=g_zhT[(d+3)*BB+tid];
    #pragma unroll
    for(int nn=0;nn<32;nn++){
      float4 e=*reinterpret_cast<const float4*>(&es[nn][d]);
      accv[nn]=fmaf(z0,e.x,fmaf(z1,e.y,fmaf(z2,e.z,fmaf(z3,e.w,accv[nn]))));
    }
  }
  for(int nn=0;nn<nmax;nn++)
    out[1 + (size_t)tid*NSCORE + n0+nn] = accv[nn];
}

// ---------------- k_simi ----------------
__global__ void k_simi(const int* __restrict__ simi_mask){
  int blk=blockIdx.x; int b=blk/SS; int tid=threadIdx.x;
  __shared__ float f1[DD];
  __shared__ float sims[SS];
  f1[tid]   =g_hf1[blk*DD+tid];
  f1[tid+64]=g_hf1[blk*DD+tid+64];
  __syncthreads();
  if(tid<SS){
    const float* f2=&g_hf2[(b*SS+tid)*DD];
    float acc=0.f;
    for(int d=0;d<DD;d++) acc+=f1[d]*f2[d];
    sims[tid]=acc*2.0f;
  }
  __syncthreads();
  if(tid==0){
    float m=-1e30f;
    for(int j=0;j<SS;j++) m=fmaxf(m,sims[j]);
    float den=0.f;
    for(int j=0;j<SS;j++) den+=expf(sims[j]-m);
    float loss=0.f;
    for(int j=0;j<SS;j++){
      float p=expf(sims[j]-m)/den;
      float l=-logf(p+1e-8f);
      if(simi_mask[blk*SS+j]==1) loss+=l;
    }
    g_partial[blk]=loss;
  }
}

__global__ void k_simi_final(float* __restrict__ out){
  int tid=threadIdx.x;
  __shared__ float red[128];
  float a=0.f;
  for(int i=tid;i<BB*SS;i+=128) a+=g_partial[i];
  red[tid]=a; __syncthreads();
  for(int off=64;off>0;off>>=1){ if(tid<off) red[tid]+=red[tid+off]; __syncthreads(); }
  if(tid==0) out[0]=red[0]/(float)BB;
}

// ---------------- launch ----------------
extern "C" void kernel_launch(void* const* d_in, const int* in_sizes, int n_in,
                              void* d_out, int out_size){
  const int*   inputs =(const int*)  d_in[0];
  const int*   adj    =(const int*)  d_in[1];
  const int*   item   =(const int*)  d_in[2];
  const int*   simi   =(const int*)  d_in[3];
  const int*   as0    =(const int*)  d_in[4];
  const int*   as1    =(const int*)  d_in[5];
  const int*   ssl0   =(const int*)  d_in[6];
  const int*   ssl1   =(const int*)  d_in[7];
  const int*   adj_all=(const int*)  d_in[9];
  const float* num    =(const float*)d_in[10];
  const float* emb    =(const float*)d_in[11];
  const float* pos    =(const float*)d_in[12];
  const float* a_local=(const float*)d_in[13];
  const float* mir1   =(const float*)d_in[14];
  const float* mir2   =(const float*)d_in[15];
  const float* gw1    =(const float*)d_in[16];
  const float* gw2    =(const float*)d_in[17];
  const float* gw3    =(const float*)d_in[18];
  const float* attr   =(const float*)d_in[19];
  const float* hww    =(const float*)d_in[20];
  const float* glu1   =(const float*)d_in[21];
  const float* glu2   =(const float*)d_in[22];
  const float* glu4   =(const float*)d_in[23];
  const float* glu4b  =(const float*)d_in[24];
  const float* ws     =(const float*)d_in[25];
  const float* gatew  =(const float*)d_in[26];
  float* out=(float*)d_out;

  float* p_out0;   cudaGetSymbolAddress((void**)&p_out0,  g_out0);
  float* p_out1;   cudaGetSymbolAddress((void**)&p_out1,  g_out1);
  float* p_hglob;  cudaGetSymbolAddress((void**)&p_hglob, g_hglob);
  float* p_logits; cudaGetSymbolAddress((void**)&p_logits,g_logits);
  __nv_bfloat16* p_w1b; cudaGetSymbolAddress((void**)&p_w1b, g_w1b);

  const int LOGITS_SMEM = 69632 + 34816 + (3*DD + LROWS)*4 + LROWS*4;
  cudaFuncSetAttribute(k_logits, cudaFuncAttributeMaxDynamicSharedMemorySize, LOGITS_SMEM);

  k_w1bf<<<2*DD*DD/256,256>>>(gw1);
  k_e3<<<NNODE/32,128>>>(emb, gw3);
  k_pool<<<BB*SS,DD>>>(inputs, as0, as1, ssl0, ssl1, emb);
  k_attrT<<<BB*SS/16,256>>>(attr);
  k_sess<<<BB,DD>>>(inputs,item,emb);

  // mode 1: TC logits -> E3-fused soft_agg -> out1
  {
    dim3 g((7200+LROWS-1)/LROWS, BB);
    k_logits<<<g,512,LOGITS_SMEM>>>(inputs,adj_all,num, emb, p_w1b, gw1+DD*DD, gw2, p_logits, 7200, 1);
  }
  k_soft_agg_f<<<BB*600,32>>>(inputs,adj_all, p_logits, p_out1, 600, 1);

  // mode 0: TC logits -> E3-fused soft_agg -> out0
  {
    dim3 g((600+LROWS-1)/LROWS, BB);
    k_logits<<<g,512,LOGITS_SMEM>>>(inputs,adj_all,num, emb, p_w1b, gw1+DD*DD, gw2, p_logits, 600, 0);
  }
  k_soft_agg_f<<<BB*SS,32>>>(inputs,adj_all, p_logits, p_out0, SS, 0);

  // mode 2: TC logits (src=out1, hop-1 W1) -> cat -> gemm3 hop-1 -> hglob
  {
    dim3 g((600+LROWS-1)/LROWS, BB);
    k_logits<<<g,512,LOGITS_SMEM>>>(inputs,adj_all,num, p_out1, p_w1b+DD*DD, gw1+129*DD+DD*DD, gw2+DD, p_logits, 600, 2);
  }
  k_soft_agg2<<<BB*SS,32>>>(p_logits);
  k_gemm3<<<BB*SS/32,128>>>(gw3+256*DD, p_hglob);

  // local branch
  for(int it=0; it<2; it++){
    k_attx<<<BB,256>>>(adj, a_local + it*4*DD);
    k_gateT<<<BB*SS/16,256>>>(mir1 + it*DD*DD, mir2 + it*DD*DD);
  }
  k_highwayT<<<BB*SS/16,256>>>(hww);
  k_hs<<<BB,DD>>>(inputs);
  k_c2<<<BB,DD>>>(glu2,glu4,glu4b);
  k_betaT<<<BB*SS/16,256>>>(inputs,pos,glu1,ws);
  k_zg<<<BB,DD>>>(pos);
  k_zh<<<BB,DD>>>(gatew);

  k_scores<<<(NSCORE+31)/32,128>>>(emb,out);
  k_simi<<<BB*SS,64>>>(simi);
  k_simi_final<<<1,128>>>(out);
}

// round 14
// speedup vs baseline: 1.0905x; 1.0358x over previous
#include <cuda_runtime.h>
#include <cuda_bf16.h>
#include <math.h>
#include <mma.h>
using namespace nvcuda;

#define BB 128
#define SS 50
#define DD 128
#define NNODE 40000
#define SAMP 12
#define NNEI 8
#define LEAKC 0.2f
#define NSCORE 39999

// ---------------- scratch (device globals; no allocation) ----------------
__device__ float g_h[BB*SS*DD];
__device__ float g_hf1[BB*SS*DD];
__device__ float g_hf2[BB*SS*DD];
__device__ float g_x[BB*SS*DD];
__device__ float g_mirror[BB*SS*DD];
__device__ float g_xnew[BB*SS*DD];
__device__ float g_xdot[BB*SS*DD];
__device__ float g_sess[BB*DD];
__device__ float g_out0[BB*SS*DD];
__device__ float g_out1[BB*600*DD];
__device__ float g_hglob[BB*SS*DD];
__device__ float g_hs[BB*DD];
__device__ float g_hlocal[BB*DD];
__device__ float g_c2[BB*DD];
__device__ float g_beta[BB*SS];
__device__ float g_zg[BB*DD];
__device__ float g_zhT[DD*BB];
__device__ float g_partial[BB*SS];
__device__ float g_cat[BB*SS*2*DD];
__device__ float g_logits[BB*7200];
__device__ __nv_bfloat16 g_w1b[2*DD*DD];
__device__ float g_E3top[NNODE*DD];
__device__ float g_E3bot[NNODE*DD];

__device__ __forceinline__ float sigm(float x){ return 1.0f/(1.0f+expf(-x)); }

// ---------------- k_w1bf ----------------
__global__ void k_w1bf(const float* __restrict__ w1){
  int i = blockIdx.x*256 + threadIdx.x;
  int hop = i/(DD*DD), within = i - hop*(DD*DD);
  g_w1b[i] = __float2bfloat16(w1[(size_t)hop*129*DD + within]);
}

// ---------------- k_e3 ----------------
__global__ void __launch_bounds__(128) k_e3(const float* __restrict__ emb,
                                            const float* __restrict__ w3){
  int row0 = blockIdx.x*32; int c = threadIdx.x;
  __shared__ __align__(16) float As[16][32];
  float accT[32], accB[32];
  #pragma unroll
  for(int r=0;r<32;r++){ accT[r]=0.f; accB[r]=0.f; }
  int rld = c & 31, kq = c >> 5;
  for(int k0=0;k0<DD;k0+=16){
    float4 av = *(const float4*)&emb[(size_t)(row0+rld)*DD + k0 + kq*4];
    As[kq*4+0][rld]=av.x; As[kq*4+1][rld]=av.y; As[kq*4+2][rld]=av.z; As[kq*4+3][rld]=av.w;
    __syncthreads();
    const float* wT = w3 + (size_t)k0*DD + c;
    const float* wB = w3 + (size_t)(k0+DD)*DD + c;
    #pragma unroll 4
    for(int k=0;k<16;k++){
      float bT = wT[k*DD], bB = wB[k*DD];
      #pragma unroll
      for(int r4=0;r4<8;r4++){
        float4 a = *(const float4*)&As[k][r4*4];
        accT[r4*4+0]=fmaf(a.x,bT,accT[r4*4+0]); accB[r4*4+0]=fmaf(a.x,bB,accB[r4*4+0]);
        accT[r4*4+1]=fmaf(a.y,bT,accT[r4*4+1]); accB[r4*4+1]=fmaf(a.y,bB,accB[r4*4+1]);
        accT[r4*4+2]=fmaf(a.z,bT,accT[r4*4+2]); accB[r4*4+2]=fmaf(a.z,bB,accB[r4*4+2]);
        accT[r4*4+3]=fmaf(a.w,bT,accT[r4*4+3]); accB[r4*4+3]=fmaf(a.w,bB,accB[r4*4+3]);
      }
    }
    __syncthreads();
  }
  #pragma unroll
  for(int r=0;r<32;r++){
    g_E3top[(size_t)(row0+r)*DD + c] = accT[r];
    g_E3bot[(size_t)(row0+r)*DD + c] = accB[r];
  }
}

// ---------------- k_pool ----------------
__global__ void k_pool(const int* __restrict__ inputs,
                       const int* __restrict__ as0, const int* __restrict__ as1,
                       const int* __restrict__ ssl0, const int* __restrict__ ssl1,
                       const float* __restrict__ emb){
  int blk = blockIdx.x; int tid = threadIdx.x;
  int node = inputs[blk];
  g_h[blk*DD+tid] = emb[node*DD+tid];
  float p1=0.f, p2=0.f;
  const int* L1[2] = {as0, as1};
  const int* L2[2] = {ssl0, ssl1};
  #pragma unroll
  for(int l=0;l<2;l++){
    float s=0.f,c=0.f;
    #pragma unroll
    for(int n=0;n<NNEI;n++){ int id=L1[l][blk*NNEI+n]; if(id!=0){ s+=emb[id*DD+tid]; c+=1.f; } }
    p1 += s/(c+1e-8f);
    s=0.f;c=0.f;
    #pragma unroll
    for(int n=0;n<NNEI;n++){ int id=L2[l][blk*NNEI+n]; if(id!=0){ s+=emb[id*DD+tid]; c+=1.f; } }
    p2 += s/(c+1e-8f);
  }
  g_hf1[blk*DD+tid] = p1*0.5f;
  g_hf2[blk*DD+tid] = p2*0.5f;
}

// ====== 16-row, 256-thread matvec family, weight-register-batched ======
// half = tid>>7 rows 0-7/8-15; c = tid&127 output col.
// staging: sk=tid&15 (k, coalesced), sr=tid>>4 (row).

// ---------------- k_attrT ----------------
__global__ void __launch_bounds__(256) k_attrT(const float* __restrict__ attr_w){
  int row0 = blockIdx.x*16;
  int tid=threadIdx.x;
  int half = tid>>7, c = tid & 127;
  int sk = tid & 15, sr = tid >> 4;
  __shared__ __align__(16) float As[2][16][17];
  float acc[8];
  #pragma unroll
  for(int r=0;r<8;r++) acc[r]=0.f;

  float stage = g_h[(size_t)(row0+sr)*DD + sk];
  As[0][sk][sr] = stage;
  __syncthreads();

  for(int ch=0; ch<16; ch++){
    int buf = ch & 1;
    // batch 16 weight loads into regs (MLP=16)
    float bk[16];
    {
      const float* wc = attr_w + (size_t)(ch*16)*DD + c;
      #pragma unroll
      for(int k=0;k<16;k++) bk[k]=wc[k*DD];
    }
    if(ch<15){
      int k0n = (ch+1)*16;
      const float* srcA = (k0n<DD)? g_h : g_hf1;
      stage = srcA[(size_t)(row0+sr)*DD + (k0n & (DD-1)) + sk];
    }
    #pragma unroll
    for(int k=0;k<16;k++){
      #pragma unroll
      for(int r=0;r<8;r++)
        acc[r] = fmaf(As[buf][k][half*8+r], bk[k], acc[r]);
    }
    if(ch<15){
      As[buf^1][sk][sr] = stage;
      __syncthreads();
    }
  }
  #pragma unroll
  for(int r=0;r<8;r++){
    int row = row0 + half*8 + r;
    size_t idx=(size_t)row*DD + c;
    float g=sigm(acc[r]);
    float h=g_h[idx], f=g_hf1[idx];
    g_x[idx]=h;
    g_mirror[idx]=g*h+(1.f-g)*f;
  }
}

// ---------------- k_gateT ----------------
__global__ void __launch_bounds__(256) k_gateT(const float* __restrict__ w1,
                                               const float* __restrict__ w2){
  int row0 = blockIdx.x*16;
  int tid=threadIdx.x;
  int half = tid>>7, c = tid & 127;
  int sk = tid & 15, sr = tid >> 4;
  __shared__ __align__(16) float As[2][16][17];
  float acc[8];
  #pragma unroll
  for(int r=0;r<8;r++) acc[r]=0.f;

  float stage = g_xnew[(size_t)(row0+sr)*DD + sk];
  As[0][sk][sr] = stage;
  __syncthreads();

  for(int ch=0; ch<16; ch++){
    int buf = ch & 1;
    float bk[16];
    {
      int k0 = ch*16;
      const float* wc = ((k0<DD)? w1 + (size_t)k0*DD : w2 + (size_t)(k0-DD)*DD) + c;
      #pragma unroll
      for(int k=0;k<16;k++) bk[k]=wc[k*DD];
    }
    if(ch<15){
      int k0n = (ch+1)*16;
      const float* srcA = (k0n<DD)? g_xnew : g_mirror;
      stage = srcA[(size_t)(row0+sr)*DD + (k0n & (DD-1)) + sk];
    }
    #pragma unroll
    for(int k=0;k<16;k++){
      #pragma unroll
      for(int r=0;r<8;r++)
        acc[r] = fmaf(As[buf][k][half*8+r], bk[k], acc[r]);
    }
    if(ch<15){
      As[buf^1][sk][sr] = stage;
      __syncthreads();
    }
  }
  #pragma unroll
  for(int r=0;r<8;r++){
    int row = row0 + half*8 + r;
    size_t idx=(size_t)row*DD + c;
    float gm=sigm(acc[r]);
    float xv=g_xnew[idx], mv=g_mirror[idx];
    g_x[idx]      = gm*xv + (1.f-gm)*mv;
    g_mirror[idx] = gm*mv + (1.f-gm)*xv;
  }
}

// ---------------- k_highwayT ----------------
__global__ void __launch_bounds__(256) k_highwayT(const float* __restrict__ hw){
  int row0 = blockIdx.x*16;
  int tid=threadIdx.x;
  int half = tid>>7, c = tid & 127;
  int sk = tid & 15, sr = tid >> 4;
  __shared__ __align__(16) float As[2][16][17];
  float acc[8];
  #pragma unroll
  for(int r=0;r<8;r++) acc[r]=0.f;

  float stage = g_h[(size_t)(row0+sr)*DD + sk];
  As[0][sk][sr] = stage;
  __syncthreads();

  for(int ch=0; ch<16; ch++){
    int buf = ch & 1;
    float bk[16];
    {
      const float* wc = hw + (size_t)(ch*16)*DD + c;
      #pragma unroll
      for(int k=0;k<16;k++) bk[k]=wc[k*DD];
    }
    if(ch<15){
      int k0n = (ch+1)*16;
      const float* srcA = (k0n<DD)? g_h : g_x;
      stage = srcA[(size_t)(row0+sr)*DD + (k0n & (DD-1)) + sk];
    }
    #pragma unroll
    for(int k=0;k<16;k++){
      #pragma unroll
      for(int r=0;r<8;r++)
        acc[r] = fmaf(As[buf][k][half*8+r], bk[k], acc[r]);
    }
    if(ch<15){
      As[buf^1][sk][sr] = stage;
      __syncthreads();
    }
  }
  #pragma unroll
  for(int r=0;r<8;r++){
    int row = row0 + half*8 + r;
    size_t idx=(size_t)row*DD + c;
    float g=sigm(acc[r]);
    float h=g_h[idx], xv=g_x[idx];
    float xd=g*h+(1.f-g)*xv;
    g_xdot[idx]=xd;
    if(row%SS==SS-1) g_hlocal[(row/SS)*DD+c]=xd;
  }
}

// ---------------- k_betaT ----------------
__global__ void __launch_bounds__(256) k_betaT(const int* __restrict__ inputs,
                                               const float* __restrict__ pos,
                                               const float* __restrict__ glu1,
                                               const float* __restrict__ ws){
  int row0 = blockIdx.x*16;
  int tid=threadIdx.x;
  int half = tid>>7, c = tid & 127;
  int sk = tid & 15, sr = tid >> 4;
  __shared__ __align__(16) float As[2][16][17];
  __shared__ float pr[16][132];
  __shared__ float red2[16][16];
  float acc[8];
  #pragma unroll
  for(int r=0;r<8;r++) acc[r]=0.f;

  int rowr = row0 + sr;
  int srx = rowr % SS;
  float stage = g_xdot[(size_t)rowr*DD + sk] + pos[(size_t)srx*DD + sk];
  As[0][sk][sr] = stage;
  __syncthreads();

  for(int ch=0; ch<8; ch++){
    int buf = ch & 1;
    float bk[16];
    {
      const float* wc = glu1 + (size_t)(ch*16)*DD + c;
      #pragma unroll
      for(int k=0;k<16;k++) bk[k]=wc[k*DD];
    }
    if(ch<7){
      int k0n = (ch+1)*16;
      stage = g_xdot[(size_t)rowr*DD + k0n + sk] + pos[(size_t)srx*DD + k0n + sk];
    }
    #pragma unroll
    for(int k=0;k<16;k++){
      #pragma unroll
      for(int r=0;r<8;r++)
        acc[r] = fmaf(As[buf][k][half*8+r], bk[k], acc[r]);
    }
    if(ch<7){
      As[buf^1][sk][sr] = stage;
      __syncthreads();
    }
  }
  float wsc = ws[c];
  #pragma unroll
  for(int r=0;r<8;r++){
    int row = row0 + half*8 + r;
    int b=row/SS;
    float nh=sigm(acc[r] + g_c2[b*DD+c]);
    pr[half*8+r][c]=nh*wsc;
  }
  __syncthreads();
  {
    int rr=tid>>4, seg=tid&15;
    float s=0.f;
    #pragma unroll
    for(int j=0;j<8;j++) s+=pr[rr][seg*8+j];
    red2[rr][seg]=s;
  }
  __syncthreads();
  if(tid<16){
    float s=0.f;
    #pragma unroll
    for(int j=0;j<16;j++) s+=red2[tid][j];
    int row=row0+tid;
    float mi=(inputs[row]!=0)?1.f:0.f;
    g_beta[row]=s*mi;
  }
}

// ---------------- k_sess ----------------
__global__ void k_sess(const int* __restrict__ inputs, const int* __restrict__ item,
                       const float* __restrict__ emb){
  int b=blockIdx.x, tid=threadIdx.x;
  float acc=0.f, cnt=0.f;
  for(int s=0;s<SS;s++){
    int inp=inputs[b*SS+s];
    if(inp!=0){ acc += emb[item[b*SS+s]*DD+tid]; cnt+=1.f; }
  }
  g_sess[b*DD+tid]=acc/cnt;
}

// ---------------- k_logits ----------------
#define LROWS 256
__global__ void __launch_bounds__(512) k_logits(
    const int* __restrict__ inputs, const int* __restrict__ adj_all,
    const float* __restrict__ num, const float* __restrict__ src,
    const __nv_bfloat16* __restrict__ w1b,
    const float* __restrict__ w1last, const float* __restrict__ w2,
    float* __restrict__ logits, int rowsPerB, int mode)
{
  extern __shared__ char smem[];
  const int LDAB = 136;
  __nv_bfloat16* As = (__nv_bfloat16*)smem;
  __nv_bfloat16* Bs = (__nv_bfloat16*)(smem + 69632);
  float* sess_s = (float*)(smem + 104448);
  float* wl_s   = sess_s + DD;
  float* w2_s   = wl_s + DD;
  float* nw_s   = w2_s + DD;
  int*   ci_s   = (int*)(nw_s + LROWS);

  int b = blockIdx.y;
  int row0 = blockIdx.x*LROWS;
  int tid = threadIdx.x, warp = tid>>5, lane = tid&31;

  if(tid<DD){
    sess_s[tid]=g_sess[b*DD+tid];
    wl_s[tid]  =w1last[tid];
    w2_s[tid]  =w2[tid];
  }
  if(tid<LROWS){
    int r = row0 + tid;
    int rr = (r<rowsPerB)? r : rowsPerB-1;
    int gi=rr/SAMP, s=rr-gi*SAMP;
    int node, ci;
    if(mode==1){
      int pi=gi/SAMP, ps=gi-pi*SAMP;
      node = adj_all[inputs[b*SS+pi]*SAMP+ps];
      ci = adj_all[node*SAMP+s];
    } else if(mode==0){
      node = inputs[b*SS+gi];
      ci = adj_all[node*SAMP+s];
    } else {
      node = inputs[b*SS+gi];
      ci = b*600 + rr;
    }
    ci_s[tid]=ci;
    nw_s[tid]=num[node*SAMP+s];
  }
  {
    int row=tid>>2, qb=(tid&3)*32;
    const uint4* srcw=(const uint4*)(w1b + row*DD + qb);
    uint4* dst=(uint4*)(Bs + row*LDAB + qb);
    #pragma unroll
    for(int j=0;j<4;j++) dst[j]=srcw[j];
  }
  __syncthreads();
  {
    int row=tid>>1, cb=(tid&1)*64;
    const float* ap = src + (size_t)ci_s[row]*DD + cb;
    __nv_bfloat16* dst = As + row*LDAB + cb;
    #pragma unroll
    for(int j=0;j<16;j++){
      float4 v=*(const float4*)&ap[j*4];
      float4 se=*(const float4*)&sess_s[cb+j*4];
      *(__nv_bfloat162*)&dst[j*4]   = __floats2bfloat162_rn(v.x*se.x, v.y*se.y);
      *(__nv_bfloat162*)&dst[j*4+2] = __floats2bfloat162_rn(v.z*se.z, v.w*se.w);
    }
  }
  __syncthreads();

  wmma::fragment<wmma::accumulator,16,16,16,float> acc[8];
  #pragma unroll
  for(int n=0;n<8;n++) wmma::fill_fragment(acc[n], 0.0f);

  #pragma unroll
  for(int k=0;k<DD;k+=16){
    wmma::fragment<wmma::matrix_a,16,16,16,__nv_bfloat16,wmma::row_major> af;
    wmma::load_matrix_sync(af, As + (warp*16)*LDAB + k, LDAB);
    #pragma unroll
    for(int n=0;n<8;n++){
      wmma::fragment<wmma::matrix_b,16,16,16,__nv_bfloat16,wmma::row_major> bf;
      wmma::load_matrix_sync(bf, Bs + k*LDAB + n*16, LDAB);
      wmma::mma_sync(acc[n], af, bf, acc[n]);
    }
  }
  __syncthreads();

  float* epi = (float*)Bs + warp*320;
  int r2=lane>>1, half=lane&1;
  float nw = nw_s[warp*16+r2];
  float v=0.f;
  #pragma unroll
  for(int n=0;n<8;n++){
    wmma::store_matrix_sync(epi, acc[n], 20, wmma::mem_row_major);
    __syncwarp();
    const float* crow = epi + r2*20 + half*8;
    int cb = n*16 + half*8;
    #pragma unroll
    for(int j=0;j<8;j++){
      float t = crow[j] + nw*wl_s[cb+j];
      t = (t>0.f)?t:(LEAKC*t);
      v = fmaf(t, w2_s[cb+j], v);
    }
    __syncwarp();
  }
  v += __shfl_xor_sync(0xffffffffu, v, 1);
  int rg = row0 + warp*16 + r2;
  if(half==0 && rg<rowsPerB) logits[(size_t)b*rowsPerB + rg] = v;
}

// ---------------- k_soft_agg_f ----------------
__global__ void __launch_bounds__(32) k_soft_agg_f(
    const int* __restrict__ inputs, const int* __restrict__ adj_all,
    const float* __restrict__ logits, float* __restrict__ outbuf, int N, int mode)
{
  int blk=blockIdx.x; int b=blk/N; int i=blk-b*N; int tid=threadIdx.x;
  __shared__ int   ci_s[SAMP];
  __shared__ float lg_s[SAMP];
  int node;
  if(mode==1){
    int pi=i/SAMP, ps=i-pi*SAMP;
    node = adj_all[inputs[b*SS+pi]*SAMP+ps];
  } else {
    node = inputs[b*SS+i];
  }
  if(tid<SAMP){
    ci_s[tid] = adj_all[node*SAMP+tid];
    lg_s[tid] = logits[(size_t)b*(N*SAMP) + i*SAMP + tid];
  }
  __syncwarp();
  float lg[SAMP];
  #pragma unroll
  for(int s=0;s<SAMP;s++) lg[s]=lg_s[s];
  float m=-1e30f;
  #pragma unroll
  for(int s=0;s<SAMP;s++) m=fmaxf(m,lg[s]);
  float alpha[SAMP]; float den=0.f;
  #pragma unroll
  for(int s=0;s<SAMP;s++){ alpha[s]=expf(lg[s]-m); den+=alpha[s]; }
  float inv=1.f/den;
  float4 t4 = ((const float4*)&g_E3top[(size_t)node*DD])[tid];
  float a0=0.f,a1=0.f,a2=0.f,a3=0.f;
  #pragma unroll
  for(int s=0;s<SAMP;s++){
    float4 e4 = ((const float4*)&g_E3bot[(size_t)ci_s[s]*DD])[tid];
    float al = alpha[s];
    a0=fmaf(al,e4.x,a0); a1=fmaf(al,e4.y,a1); a2=fmaf(al,e4.z,a2); a3=fmaf(al,e4.w,a3);
  }
  float4 o;
  o.x = tanhf(t4.x + a0*inv);
  o.y = tanhf(t4.y + a1*inv);
  o.z = tanhf(t4.z + a2*inv);
  o.w = tanhf(t4.w + a3*inv);
  ((float4*)&outbuf[(size_t)blk*DD])[tid] = o;
}

// ---------------- k_soft_agg2 ----------------
__global__ void __launch_bounds__(32) k_soft_agg2(const float* __restrict__ logits)
{
  int blk=blockIdx.x; int b=blk/SS; int i=blk-b*SS; int tid=threadIdx.x;
  __shared__ float lg_s[SAMP];
  if(tid<SAMP) lg_s[tid] = logits[(size_t)b*600 + i*SAMP + tid];
  __syncwarp();
  float lg[SAMP];
  #pragma unroll
  for(int s=0;s<SAMP;s++) lg[s]=lg_s[s];
  float m=-1e30f;
  #pragma unroll
  for(int s=0;s<SAMP;s++) m=fmaxf(m,lg[s]);
  float alpha[SAMP]; float den=0.f;
  #pragma unroll
  for(int s=0;s<SAMP;s++){ alpha[s]=expf(lg[s]-m); den+=alpha[s]; }
  float inv=1.f/den;
  float4 sv4 = ((const float4*)&g_out0[(size_t)blk*DD])[tid];
  const float* base = &g_out1[(size_t)(b*600 + i*SAMP)*DD];
  float a0=0.f,a1=0.f,a2=0.f,a3=0.f;
  #pragma unroll
  for(int s=0;s<SAMP;s++){
    float4 nv4 = ((const float4*)&base[(size_t)s*DD])[tid];
    float al = alpha[s];
    a0=fmaf(al,nv4.x,a0); a1=fmaf(al,nv4.y,a1); a2=fmaf(al,nv4.z,a2); a3=fmaf(al,nv4.w,a3);
  }
  float* crow = &g_cat[(size_t)blk*2*DD];
  ((float4*)crow)[tid] = sv4;
  float4 ag; ag.x=a0*inv; ag.y=a1*inv; ag.z=a2*inv; ag.w=a3*inv;
  ((float4*)(crow+DD))[tid] = ag;
}

// ---------------- k_gemm3 (mode 2) ----------------
__global__ void __launch_bounds__(128) k_gemm3(const float* __restrict__ w3,
                                               float* __restrict__ out){
  int row0 = blockIdx.x*32; int tid=threadIdx.x;
  int c = tid;
  __shared__ __align__(16) float As[16][32];
  float acc[32];
  #pragma unroll
  for(int r=0;r<32;r++) acc[r]=0.f;
  int rld = tid & 31, kq = tid >> 5;
  for(int k0=0;k0<2*DD;k0+=16){
    float4 av = *(const float4*)&g_cat[(size_t)(row0+rld)*2*DD + k0 + kq*4];
    As[kq*4+0][rld]=av.x; As[kq*4+1][rld]=av.y; As[kq*4+2][rld]=av.z; As[kq*4+3][rld]=av.w;
    __syncthreads();
    const float* w3c = w3 + (size_t)k0*DD + c;
    #pragma unroll 4
    for(int k=0;k<16;k++){
      float bk = w3c[k*DD];
      #pragma unroll
      for(int r4=0;r4<8;r4++){
        float4 a = *(const float4*)&As[k][r4*4];
        acc[r4*4+0]=fmaf(a.x,bk,acc[r4*4+0]);
        acc[r4*4+1]=fmaf(a.y,bk,acc[r4*4+1]);
        acc[r4*4+2]=fmaf(a.z,bk,acc[r4*4+2]);
        acc[r4*4+3]=fmaf(a.w,bk,acc[r4*4+3]);
      }
    }
    __syncthreads();
  }
  #pragma unroll
  for(int r=0;r<32;r++)
    out[(size_t)(row0+r)*DD + c] = tanhf(acc[r]);
}

// ---------------- k_attx ----------------
__global__ void k_attx(const int* __restrict__ adj, const float* __restrict__ a_local){
  int b=blockIdx.x; int tid=threadIdx.x;
  __shared__ __align__(16) float xs[SS][DD+4];
  __shared__ __align__(16) float al_s[4][DD];
  __shared__ float att[SS][SS+2];
  for(int idx=tid; idx<SS*DD; idx+=256){
    int i=idx>>7, d=idx&127;
    xs[i][d]=g_x[(b*SS+i)*DD+d];
  }
  for(int idx=tid; idx<4*DD; idx+=256)
    al_s[idx>>7][idx&127]=a_local[idx];
  __syncthreads();
  for(int p=tid;p<SS*SS;p+=256){
    int i=p/SS, j=p-i*SS;
    int k=adj[b*SS*SS+p];
    float e=-9e15f;
    if(k>=1 && k<=4){
      const float* al = al_s[k-1];
      float ds=0.f;
      #pragma unroll 8
      for(int d=0;d<DD;d+=4){
        float4 xi=*(const float4*)&xs[i][d];
        float4 xj=*(const float4*)&xs[j][d];
        float4 av=*(const float4*)&al[d];
        ds += xi.x*xj.x*av.x + xi.y*xj.y*av.y + xi.z*xj.z*av.z + xi.w*xj.w*av.w;
      }
      e = (ds>0.f)?ds:(LEAKC*ds);
    }
    att[i][j]=e;
  }
  __syncthreads();
  if(tid<SS){
    float m=-1e30f;
    for(int j=0;j<SS;j++) m=fmaxf(m,att[tid][j]);
    float den=0.f;
    for(int j=0;j<SS;j++){ float e=expf(att[tid][j]-m); att[tid][j]=e; den+=e; }
    float inv=1.f/den;
    for(int j=0;j<SS;j++) att[tid][j]*=inv;
  }
  __syncthreads();
  for(int q=tid;q<SS*DD;q+=256){
    int i=q>>7, d=q&127;
    float acc=0.f;
    for(int j=0;j<SS;j++) acc += att[i][j]*xs[j][d];
    g_xnew[(b*SS+i)*DD+d]=acc;
  }
}

// ---------------- k_hs ----------------
__global__ void k_hs(const int* __restrict__ inputs){
  int b=blockIdx.x, tid=threadIdx.x;
  float acc=0.f, cnt=0.f;
  for(int s=0;s<SS;s++){
    if(inputs[b*SS+s]!=0){ acc += g_hglob[(b*SS+s)*DD+tid]; cnt+=1.f; }
  }
  g_hs[b*DD+tid]=acc/cnt;
}

// ---------------- k_c2 ----------------
__global__ void k_c2(const float* __restrict__ glu2, const float* __restrict__ glu4,
                     const float* __restrict__ glu4b){
  int b=blockIdx.x, tid=threadIdx.x;
  __shared__ __align__(16) float hsr[DD], hlr[DD];
  hsr[tid]=g_hs[b*DD+tid]; hlr[tid]=g_hlocal[b*DD+tid];
  __syncthreads();
  float acc=glu4b[tid];
  const float* w2t=glu2+tid; const float* w4t=glu4+tid;
  #pragma unroll 8
  for(int k=0;k<DD;k+=4){
    float4 s4=*(const float4*)&hsr[k];
    float4 l4=*(const float4*)&hlr[k];
    acc=fmaf(s4.x,w2t[(k  )*DD],acc); acc=fmaf(l4.x,w4t[(k  )*DD],acc);
    acc=fmaf(s4.y,w2t[(k+1)*DD],acc); acc=fmaf(l4.y,w4t[(k+1)*DD],acc);
    acc=fmaf(s4.z,w2t[(k+2)*DD],acc); acc=fmaf(l4.z,w4t[(k+2)*DD],acc);
    acc=fmaf(s4.w,w2t[(k+3)*DD],acc); acc=fmaf(l4.w,w4t[(k+3)*DD],acc);
  }
  g_c2[b*DD+tid]=acc;
}

// ---------------- k_zg ----------------
__global__ void k_zg(const float* __restrict__ pos){
  int b=blockIdx.x, tid=threadIdx.x;
  float acc=0.f;
  for(int s=0;s<SS;s++)
    acc += g_beta[b*SS+s]*(g_xdot[(b*SS+s)*DD+tid]+pos[s*DD+tid]);
  g_zg[b*DD+tid]=acc;
}

// ---------------- k_zh ----------------
__global__ void k_zh(const float* __restrict__ gatew){
  int b=blockIdx.x, tid=threadIdx.x;
  __shared__ __align__(16) float zgr[DD], hlr[DD];
  zgr[tid]=g_zg[b*DD+tid]; hlr[tid]=g_hlocal[b*DD+tid];
  __syncthreads();
  const float* wt=gatew+tid;
  float acc=0.f;
  #pragma unroll 8
  for(int k=0;k<DD;k+=4){
    float4 z4=*(const float4*)&zgr[k];
    float4 l4=*(const float4*)&hlr[k];
    acc=fmaf(z4.x,wt[(k  )*DD],acc); acc=fmaf(l4.x,wt[(DD+k  )*DD],acc);
    acc=fmaf(z4.y,wt[(k+1)*DD],acc); acc=fmaf(l4.y,wt[(DD+k+1)*DD],acc);
    acc=fmaf(z4.z,wt[(k+2)*DD],acc); acc=fmaf(l4.z,wt[(DD+k+2)*DD],acc);
    acc=fmaf(z4.w,wt[(k+3)*DD],acc); acc=fmaf(l4.w,wt[(DD+k+3)*DD],acc);
  }
  float gf=sigm(acc)*0.1f;
  float zh=gf*hlr[tid]+(1.f-gf)*zgr[tid];
  g_zhT[tid*BB+b]=zh;
}

// ---------------- k_scores ----------------
__global__ void k_scores(const float* __restrict__ emb, float* __restrict__ out){
  int n0 = blockIdx.x*32; int tid=threadIdx.x;
  __shared__ __align__(16) float es[32][DD];
  int nmax = NSCORE - n0; if(nmax>32) nmax=32;
  for(int idx=tid; idx<nmax*DD; idx+=128){
    int nn=idx>>7, d=idx&127;
    es[nn][d]=emb[(size_t)(n0+nn+1)*DD+d];
  }
  __syncthreads();
  float accv[32];
  #pragma unroll
  for(int nn=0;nn<32;nn++) accv[nn]=0.f;
  for(int d=0;d<DD;d+=4){
    float z0=g_zhT[(d  )*BB+tid];
    float z1=g_zhT[(d+1)*BB+tid];
    float z2=g_zhT[(d+2)*BB+tid];
    float z3=g_zhT[(d+3)*BB+tid];
    #pragma unroll
    for(int nn=0;nn<32;nn++){
      float4 e=*reinterpret_cast<const float4*>(&es[nn][d]);
      accv[nn]=fmaf(z0,e.x,fmaf(z1,e.y,fmaf(z2,e.z,fmaf(z3,e.w,accv[nn]))));
    }
  }
  for(int nn=0;nn<nmax;nn++)
    out[1 + (size_t)tid*NSCORE + n0+nn] = accv[nn];
}

// ---------------- k_simi ----------------
__global__ void k_simi(const int* __restrict__ simi_mask){
  int blk=blockIdx.x; int b=blk/SS; int tid=threadIdx.x;
  __shared__ float f1[DD];
  __shared__ float sims[SS];
  f1[tid]   =g_hf1[blk*DD+tid];
  f1[tid+64]=g_hf1[blk*DD+tid+64];
  __syncthreads();
  if(tid<SS){
    const float* f2=&g_hf2[(b*SS+tid)*DD];
    float acc=0.f;
    for(int d=0;d<DD;d++) acc+=f1[d]*f2[d];
    sims[tid]=acc*2.0f;
  }
  __syncthreads();
  if(tid==0){
    float m=-1e30f;
    for(int j=0;j<SS;j++) m=fmaxf(m,sims[j]);
    float den=0.f;
    for(int j=0;j<SS;j++) den+=expf(sims[j]-m);
    float loss=0.f;
    for(int j=0;j<SS;j++){
      float p=expf(sims[j]-m)/den;
      float l=-logf(p+1e-8f);
      if(simi_mask[blk*SS+j]==1) loss+=l;
    }
    g_partial[blk]=loss;
  }
}

__global__ void k_simi_final(float* __restrict__ out){
  int tid=threadIdx.x;
  __shared__ float red[128];
  float a=0.f;
  for(int i=tid;i<BB*SS;i+=128) a+=g_partial[i];
  red[tid]=a; __syncthreads();
  for(int off=64;off>0;off>>=1){ if(tid<off) red[tid]+=red[tid+off]; __syncthreads(); }
  if(tid==0) out[0]=red[0]/(float)BB;
}

// ---------------- launch ----------------
extern "C" void kernel_launch(void* const* d_in, const int* in_sizes, int n_in,
                              void* d_out, int out_size){
  const int*   inputs =(const int*)  d_in[0];
  const int*   adj    =(const int*)  d_in[1];
  const int*   item   =(const int*)  d_in[2];
  const int*   simi   =(const int*)  d_in[3];
  const int*   as0    =(const int*)  d_in[4];
  const int*   as1    =(const int*)  d_in[5];
  const int*   ssl0   =(const int*)  d_in[6];
  const int*   ssl1   =(const int*)  d_in[7];
  const int*   adj_all=(const int*)  d_in[9];
  const float* num    =(const float*)d_in[10];
  const float* emb    =(const float*)d_in[11];
  const float* pos    =(const float*)d_in[12];
  const float* a_local=(const float*)d_in[13];
  const float* mir1   =(const float*)d_in[14];
  const float* mir2   =(const float*)d_in[15];
  const float* gw1    =(const float*)d_in[16];
  const float* gw2    =(const float*)d_in[17];
  const float* gw3    =(const float*)d_in[18];
  const float* attr   =(const float*)d_in[19];
  const float* hww    =(const float*)d_in[20];
  const float* glu1   =(const float*)d_in[21];
  const float* glu2   =(const float*)d_in[22];
  const float* glu4   =(const float*)d_in[23];
  const float* glu4b  =(const float*)d_in[24];
  const float* ws     =(const float*)d_in[25];
  const float* gatew  =(const float*)d_in[26];
  float* out=(float*)d_out;

  float* p_out0;   cudaGetSymbolAddress((void**)&p_out0,  g_out0);
  float* p_out1;   cudaGetSymbolAddress((void**)&p_out1,  g_out1);
  float* p_hglob;  cudaGetSymbolAddress((void**)&p_hglob, g_hglob);
  float* p_logits; cudaGetSymbolAddress((void**)&p_logits,g_logits);
  __nv_bfloat16* p_w1b; cudaGetSymbolAddress((void**)&p_w1b, g_w1b);

  const int LOGITS_SMEM = 69632 + 34816 + (3*DD + LROWS)*4 + LROWS*4;
  cudaFuncSetAttribute(k_logits, cudaFuncAttributeMaxDynamicSharedMemorySize, LOGITS_SMEM);

  k_w1bf<<<2*DD*DD/256,256>>>(gw1);
  k_e3<<<NNODE/32,128>>>(emb, gw3);
  k_pool<<<BB*SS,DD>>>(inputs, as0, as1, ssl0, ssl1, emb);
  k_attrT<<<BB*SS/16,256>>>(attr);
  k_sess<<<BB,DD>>>(inputs,item,emb);

  // mode 1
  {
    dim3 g((7200+LROWS-1)/LROWS, BB);
    k_logits<<<g,512,LOGITS_SMEM>>>(inputs,adj_all,num, emb, p_w1b, gw1+DD*DD, gw2, p_logits, 7200, 1);
  }
  k_soft_agg_f<<<BB*600,32>>>(inputs,adj_all, p_logits, p_out1, 600, 1);

  // mode 0
  {
    dim3 g((600+LROWS-1)/LROWS, BB);
    k_logits<<<g,512,LOGITS_SMEM>>>(inputs,adj_all,num, emb, p_w1b, gw1+DD*DD, gw2, p_logits, 600, 0);
  }
  k_soft_agg_f<<<BB*SS,32>>>(inputs,adj_all, p_logits, p_out0, SS, 0);

  // mode 2
  {
    dim3 g((600+LROWS-1)/LROWS, BB);
    k_logits<<<g,512,LOGITS_SMEM>>>(inputs,adj_all,num, p_out1, p_w1b+DD*DD, gw1+129*DD+DD*DD, gw2+DD, p_logits, 600, 2);
  }
  k_soft_agg2<<<BB*SS,32>>>(p_logits);
  k_gemm3<<<BB*SS/32,128>>>(gw3+256*DD, p_hglob);

  // local branch
  for(int it=0; it<2; it++){
    k_attx<<<BB,256>>>(adj, a_local + it*4*DD);
    k_gateT<<<BB*SS/16,256>>>(mir1 + it*DD*DD, mir2 + it*DD*DD);
  }
  k_highwayT<<<BB*SS/16,256>>>(hww);
  k_hs<<<BB,DD>>>(inputs);
  k_c2<<<BB,DD>>>(glu2,glu4,glu4b);
  k_betaT<<<BB*SS/16,256>>>(inputs,pos,glu1,ws);
  k_zg<<<BB,DD>>>(pos);
  k_zh<<<BB,DD>>>(gatew);

  k_scores<<<(NSCORE+31)/32,128>>>(emb,out);
  k_simi<<<BB*SS,64>>>(simi);
  k_simi_final<<<1,128>>>(out);
}

// round 15
// speedup vs baseline: 1.1308x; 1.0370x over previous
#include <cuda_runtime.h>
#include <cuda_bf16.h>
#include <math.h>
#include <mma.h>
using namespace nvcuda;

#define BB 128
#define SS 50
#define DD 128
#define NNODE 40000
#define SAMP 12
#define NNEI 8
#define LEAKC 0.2f
#define NSCORE 39999

// ---------------- scratch (device globals; no allocation) ----------------
__device__ float g_h[BB*SS*DD];
__device__ float g_hf1[BB*SS*DD];
__device__ float g_hf2[BB*SS*DD];
__device__ float g_x[BB*SS*DD];
__device__ float g_mirror[BB*SS*DD];
__device__ float g_xnew[BB*SS*DD];
__device__ float g_xdot[BB*SS*DD];
__device__ float g_sess[BB*DD];
__device__ float g_out0[BB*SS*DD];
__device__ float g_out1[BB*600*DD];
__device__ float g_hglob[BB*SS*DD];
__device__ float g_hs[BB*DD];
__device__ float g_hlocal[BB*DD];
__device__ float g_c2[BB*DD];
__device__ float g_beta[BB*SS];
__device__ float g_zg[BB*DD];
__device__ float g_zhT[DD*BB];
__device__ float g_partial[BB*SS];
__device__ float g_cat[BB*SS*2*DD];
__device__ float g_logits[BB*7200];
__device__ __nv_bfloat16 g_w1b[2*DD*DD];
__device__ float g_E3top[NNODE*DD];
__device__ float g_E3bot[NNODE*DD];

__device__ __forceinline__ float sigm(float x){ return 1.0f/(1.0f+expf(-x)); }

// ---------------- k_w1bf ----------------
__global__ void k_w1bf(const float* __restrict__ w1){
  int i = blockIdx.x*256 + threadIdx.x;
  int hop = i/(DD*DD), within = i - hop*(DD*DD);
  g_w1b[i] = __float2bfloat16(w1[(size_t)hop*129*DD + within]);
}

// ---------------- k_e3 ----------------
__global__ void __launch_bounds__(128) k_e3(const float* __restrict__ emb,
                                            const float* __restrict__ w3){
  int row0 = blockIdx.x*32; int c = threadIdx.x;
  __shared__ __align__(16) float As[16][32];
  float accT[32], accB[32];
  #pragma unroll
  for(int r=0;r<32;r++){ accT[r]=0.f; accB[r]=0.f; }
  int rld = c & 31, kq = c >> 5;
  for(int k0=0;k0<DD;k0+=16){
    float4 av = *(const float4*)&emb[(size_t)(row0+rld)*DD + k0 + kq*4];
    As[kq*4+0][rld]=av.x; As[kq*4+1][rld]=av.y; As[kq*4+2][rld]=av.z; As[kq*4+3][rld]=av.w;
    __syncthreads();
    const float* wT = w3 + (size_t)k0*DD + c;
    const float* wB = w3 + (size_t)(k0+DD)*DD + c;
    #pragma unroll 4
    for(int k=0;k<16;k++){
      float bT = wT[k*DD], bB = wB[k*DD];
      #pragma unroll
      for(int r4=0;r4<8;r4++){
        float4 a = *(const float4*)&As[k][r4*4];
        accT[r4*4+0]=fmaf(a.x,bT,accT[r4*4+0]); accB[r4*4+0]=fmaf(a.x,bB,accB[r4*4+0]);
        accT[r4*4+1]=fmaf(a.y,bT,accT[r4*4+1]); accB[r4*4+1]=fmaf(a.y,bB,accB[r4*4+1]);
        accT[r4*4+2]=fmaf(a.z,bT,accT[r4*4+2]); accB[r4*4+2]=fmaf(a.z,bB,accB[r4*4+2]);
        accT[r4*4+3]=fmaf(a.w,bT,accT[r4*4+3]); accB[r4*4+3]=fmaf(a.w,bB,accB[r4*4+3]);
      }
    }
    __syncthreads();
  }
  #pragma unroll
  for(int r=0;r<32;r++){
    g_E3top[(size_t)(row0+r)*DD + c] = accT[r];
    g_E3bot[(size_t)(row0+r)*DD + c] = accB[r];
  }
}

// ---------------- k_pool ----------------
__global__ void k_pool(const int* __restrict__ inputs,
                       const int* __restrict__ as0, const int* __restrict__ as1,
                       const int* __restrict__ ssl0, const int* __restrict__ ssl1,
                       const float* __restrict__ emb){
  int blk = blockIdx.x; int tid = threadIdx.x;
  int node = inputs[blk];
  g_h[blk*DD+tid] = emb[node*DD+tid];
  float p1=0.f, p2=0.f;
  const int* L1[2] = {as0, as1};
  const int* L2[2] = {ssl0, ssl1};
  #pragma unroll
  for(int l=0;l<2;l++){
    float s=0.f,c=0.f;
    #pragma unroll
    for(int n=0;n<NNEI;n++){ int id=L1[l][blk*NNEI+n]; if(id!=0){ s+=emb[id*DD+tid]; c+=1.f; } }
    p1 += s/(c+1e-8f);
    s=0.f;c=0.f;
    #pragma unroll
    for(int n=0;n<NNEI;n++){ int id=L2[l][blk*NNEI+n]; if(id!=0){ s+=emb[id*DD+tid]; c+=1.f; } }
    p2 += s/(c+1e-8f);
  }
  g_hf1[blk*DD+tid] = p1*0.5f;
  g_hf2[blk*DD+tid] = p2*0.5f;
}

// ====== 16-row, 256-thread matvec family: 32-k chunks, bk[32] batch, dbl-buffer ======
// half = tid>>7 rows 0-7/8-15; c = tid&127 output col.
// staging: sk2=tid&31 (k), sr2=tid>>5 (row 0..7; also row+8).

// ---------------- k_attrT ----------------
__global__ void __launch_bounds__(256) k_attrT(const float* __restrict__ attr_w){
  int row0 = blockIdx.x*16;
  int tid=threadIdx.x;
  int half = tid>>7, c = tid & 127;
  int sk2 = tid & 31, sr2 = tid >> 5;
  __shared__ __align__(16) float As[2][32][17];
  float acc[8];
  #pragma unroll
  for(int r=0;r<8;r++) acc[r]=0.f;

  As[0][sk2][sr2]   = g_h[(size_t)(row0+sr2  )*DD + sk2];
  As[0][sk2][sr2+8] = g_h[(size_t)(row0+sr2+8)*DD + sk2];
  __syncthreads();

  for(int ch=0; ch<8; ch++){
    int buf = ch & 1;
    float bk[32];
    {
      const float* wc = attr_w + (size_t)(ch*32)*DD + c;
      #pragma unroll
      for(int k=0;k<32;k++) bk[k]=wc[k*DD];
    }
    float st0=0.f, st1=0.f;
    if(ch<7){
      int k0n = (ch+1)*32;
      const float* srcA = (k0n<DD)? g_h : g_hf1;
      int kk = k0n & (DD-1);
      st0 = srcA[(size_t)(row0+sr2  )*DD + kk + sk2];
      st1 = srcA[(size_t)(row0+sr2+8)*DD + kk + sk2];
    }
    #pragma unroll
    for(int k=0;k<32;k++){
      #pragma unroll
      for(int r=0;r<8;r++)
        acc[r] = fmaf(As[buf][k][half*8+r], bk[k], acc[r]);
    }
    if(ch<7){
      As[buf^1][sk2][sr2]   = st0;
      As[buf^1][sk2][sr2+8] = st1;
      __syncthreads();
    }
  }
  #pragma unroll
  for(int r=0;r<8;r++){
    int row = row0 + half*8 + r;
    size_t idx=(size_t)row*DD + c;
    float g=sigm(acc[r]);
    float h=g_h[idx], f=g_hf1[idx];
    g_x[idx]=h;
    g_mirror[idx]=g*h+(1.f-g)*f;
  }
}

// ---------------- k_gateT ----------------
__global__ void __launch_bounds__(256) k_gateT(const float* __restrict__ w1,
                                               const float* __restrict__ w2){
  int row0 = blockIdx.x*16;
  int tid=threadIdx.x;
  int half = tid>>7, c = tid & 127;
  int sk2 = tid & 31, sr2 = tid >> 5;
  __shared__ __align__(16) float As[2][32][17];
  float acc[8];
  #pragma unroll
  for(int r=0;r<8;r++) acc[r]=0.f;

  As[0][sk2][sr2]   = g_xnew[(size_t)(row0+sr2  )*DD + sk2];
  As[0][sk2][sr2+8] = g_xnew[(size_t)(row0+sr2+8)*DD + sk2];
  __syncthreads();

  for(int ch=0; ch<8; ch++){
    int buf = ch & 1;
    float bk[32];
    {
      int k0 = ch*32;
      const float* wc = ((k0<DD)? w1 + (size_t)k0*DD : w2 + (size_t)(k0-DD)*DD) + c;
      #pragma unroll
      for(int k=0;k<32;k++) bk[k]=wc[k*DD];
    }
    float st0=0.f, st1=0.f;
    if(ch<7){
      int k0n = (ch+1)*32;
      const float* srcA = (k0n<DD)? g_xnew : g_mirror;
      int kk = k0n & (DD-1);
      st0 = srcA[(size_t)(row0+sr2  )*DD + kk + sk2];
      st1 = srcA[(size_t)(row0+sr2+8)*DD + kk + sk2];
    }
    #pragma unroll
    for(int k=0;k<32;k++){
      #pragma unroll
      for(int r=0;r<8;r++)
        acc[r] = fmaf(As[buf][k][half*8+r], bk[k], acc[r]);
    }
    if(ch<7){
      As[buf^1][sk2][sr2]   = st0;
      As[buf^1][sk2][sr2+8] = st1;
      __syncthreads();
    }
  }
  #pragma unroll
  for(int r=0;r<8;r++){
    int row = row0 + half*8 + r;
    size_t idx=(size_t)row*DD + c;
    float gm=sigm(acc[r]);
    float xv=g_xnew[idx], mv=g_mirror[idx];
    g_x[idx]      = gm*xv + (1.f-gm)*mv;
    g_mirror[idx] = gm*mv + (1.f-gm)*xv;
  }
}

// ---------------- k_highwayT ----------------
__global__ void __launch_bounds__(256) k_highwayT(const float* __restrict__ hw){
  int row0 = blockIdx.x*16;
  int tid=threadIdx.x;
  int half = tid>>7, c = tid & 127;
  int sk2 = tid & 31, sr2 = tid >> 5;
  __shared__ __align__(16) float As[2][32][17];
  float acc[8];
  #pragma unroll
  for(int r=0;r<8;r++) acc[r]=0.f;

  As[0][sk2][sr2]   = g_h[(size_t)(row0+sr2  )*DD + sk2];
  As[0][sk2][sr2+8] = g_h[(size_t)(row0+sr2+8)*DD + sk2];
  __syncthreads();

  for(int ch=0; ch<8; ch++){
    int buf = ch & 1;
    float bk[32];
    {
      const float* wc = hw + (size_t)(ch*32)*DD + c;
      #pragma unroll
      for(int k=0;k<32;k++) bk[k]=wc[k*DD];
    }
    float st0=0.f, st1=0.f;
    if(ch<7){
      int k0n = (ch+1)*32;
      const float* srcA = (k0n<DD)? g_h : g_x;
      int kk = k0n & (DD-1);
      st0 = srcA[(size_t)(row0+sr2  )*DD + kk + sk2];
      st1 = srcA[(size_t)(row0+sr2+8)*DD + kk + sk2];
    }
    #pragma unroll
    for(int k=0;k<32;k++){
      #pragma unroll
      for(int r=0;r<8;r++)
        acc[r] = fmaf(As[buf][k][half*8+r], bk[k], acc[r]);
    }
    if(ch<7){
      As[buf^1][sk2][sr2]   = st0;
      As[buf^1][sk2][sr2+8] = st1;
      __syncthreads();
    }
  }
  #pragma unroll
  for(int r=0;r<8;r++){
    int row = row0 + half*8 + r;
    size_t idx=(size_t)row*DD + c;
    float g=sigm(acc[r]);
    float h=g_h[idx], xv=g_x[idx];
    float xd=g*h+(1.f-g)*xv;
    g_xdot[idx]=xd;
    if(row%SS==SS-1) g_hlocal[(row/SS)*DD+c]=xd;
  }
}

// ---------------- k_betaT: K=128 -> 4 chunks of 32 ----------------
__global__ void __launch_bounds__(256) k_betaT(const int* __restrict__ inputs,
                                               const float* __restrict__ pos,
                                               const float* __restrict__ glu1,
                                               const float* __restrict__ ws){
  int row0 = blockIdx.x*16;
  int tid=threadIdx.x;
  int half = tid>>7, c = tid & 127;
  int sk2 = tid & 31, sr2 = tid >> 5;
  __shared__ __align__(16) float As[2][32][17];
  __shared__ float pr[16][132];
  __shared__ float red2[16][16];
  float acc[8];
  #pragma unroll
  for(int r=0;r<8;r++) acc[r]=0.f;

  int rowA = row0 + sr2, rowB = row0 + sr2 + 8;
  int sA = rowA % SS, sB = rowB % SS;
  As[0][sk2][sr2]   = g_xdot[(size_t)rowA*DD + sk2] + pos[(size_t)sA*DD + sk2];
  As[0][sk2][sr2+8] = g_xdot[(size_t)rowB*DD + sk2] + pos[(size_t)sB*DD + sk2];
  __syncthreads();

  for(int ch=0; ch<4; ch++){
    int buf = ch & 1;
    float bk[32];
    {
      const float* wc = glu1 + (size_t)(ch*32)*DD + c;
      #pragma unroll
      for(int k=0;k<32;k++) bk[k]=wc[k*DD];
    }
    float st0=0.f, st1=0.f;
    if(ch<3){
      int k0n = (ch+1)*32;
      st0 = g_xdot[(size_t)rowA*DD + k0n + sk2] + pos[(size_t)sA*DD + k0n + sk2];
      st1 = g_xdot[(size_t)rowB*DD + k0n + sk2] + pos[(size_t)sB*DD + k0n + sk2];
    }
    #pragma unroll
    for(int k=0;k<32;k++){
      #pragma unroll
      for(int r=0;r<8;r++)
        acc[r] = fmaf(As[buf][k][half*8+r], bk[k], acc[r]);
    }
    if(ch<3){
      As[buf^1][sk2][sr2]   = st0;
      As[buf^1][sk2][sr2+8] = st1;
      __syncthreads();
    }
  }
  float wsc = ws[c];
  #pragma unroll
  for(int r=0;r<8;r++){
    int row = row0 + half*8 + r;
    int b=row/SS;
    float nh=sigm(acc[r] + g_c2[b*DD+c]);
    pr[half*8+r][c]=nh*wsc;
  }
  __syncthreads();
  {
    int rr=tid>>4, seg=tid&15;
    float s=0.f;
    #pragma unroll
    for(int j=0;j<8;j++) s+=pr[rr][seg*8+j];
    red2[rr][seg]=s;
  }
  __syncthreads();
  if(tid<16){
    float s=0.f;
    #pragma unroll
    for(int j=0;j<16;j++) s+=red2[tid][j];
    int row=row0+tid;
    float mi=(inputs[row]!=0)?1.f:0.f;
    g_beta[row]=s*mi;
  }
}

// ---------------- k_sess ----------------
__global__ void k_sess(const int* __restrict__ inputs, const int* __restrict__ item,
                       const float* __restrict__ emb){
  int b=blockIdx.x, tid=threadIdx.x;
  float acc=0.f, cnt=0.f;
  for(int s=0;s<SS;s++){
    int inp=inputs[b*SS+s];
    if(inp!=0){ acc += emb[item[b*SS+s]*DD+tid]; cnt+=1.f; }
  }
  g_sess[b*DD+tid]=acc/cnt;
}

// ---------------- k_logits ----------------
#define LROWS 256
__global__ void __launch_bounds__(512) k_logits(
    const int* __restrict__ inputs, const int* __restrict__ adj_all,
    const float* __restrict__ num, const float* __restrict__ src,
    const __nv_bfloat16* __restrict__ w1b,
    const float* __restrict__ w1last, const float* __restrict__ w2,
    float* __restrict__ logits, int rowsPerB, int mode)
{
  extern __shared__ char smem[];
  const int LDAB = 136;
  __nv_bfloat16* As = (__nv_bfloat16*)smem;
  __nv_bfloat16* Bs = (__nv_bfloat16*)(smem + 69632);
  float* sess_s = (float*)(smem + 104448);
  float* wl_s   = sess_s + DD;
  float* w2_s   = wl_s + DD;
  float* nw_s   = w2_s + DD;
  int*   ci_s   = (int*)(nw_s + LROWS);

  int b = blockIdx.y;
  int row0 = blockIdx.x*LROWS;
  int tid = threadIdx.x, warp = tid>>5, lane = tid&31;

  if(tid<DD){
    sess_s[tid]=g_sess[b*DD+tid];
    wl_s[tid]  =w1last[tid];
    w2_s[tid]  =w2[tid];
  }
  if(tid<LROWS){
    int r = row0 + tid;
    int rr = (r<rowsPerB)? r : rowsPerB-1;
    int gi=rr/SAMP, s=rr-gi*SAMP;
    int node, ci;
    if(mode==1){
      int pi=gi/SAMP, ps=gi-pi*SAMP;
      node = adj_all[inputs[b*SS+pi]*SAMP+ps];
      ci = adj_all[node*SAMP+s];
    } else if(mode==0){
      node = inputs[b*SS+gi];
      ci = adj_all[node*SAMP+s];
    } else {
      node = inputs[b*SS+gi];
      ci = b*600 + rr;
    }
    ci_s[tid]=ci;
    nw_s[tid]=num[node*SAMP+s];
  }
  {
    int row=tid>>2, qb=(tid&3)*32;
    const uint4* srcw=(const uint4*)(w1b + row*DD + qb);
    uint4* dst=(uint4*)(Bs + row*LDAB + qb);
    #pragma unroll
    for(int j=0;j<4;j++) dst[j]=srcw[j];
  }
  __syncthreads();
  {
    int row=tid>>1, cb=(tid&1)*64;
    const float* ap = src + (size_t)ci_s[row]*DD + cb;
    __nv_bfloat16* dst = As + row*LDAB + cb;
    #pragma unroll
    for(int j=0;j<16;j++){
      float4 v=*(const float4*)&ap[j*4];
      float4 se=*(const float4*)&sess_s[cb+j*4];
      *(__nv_bfloat162*)&dst[j*4]   = __floats2bfloat162_rn(v.x*se.x, v.y*se.y);
      *(__nv_bfloat162*)&dst[j*4+2] = __floats2bfloat162_rn(v.z*se.z, v.w*se.w);
    }
  }
  __syncthreads();

  wmma::fragment<wmma::accumulator,16,16,16,float> acc[8];
  #pragma unroll
  for(int n=0;n<8;n++) wmma::fill_fragment(acc[n], 0.0f);

  #pragma unroll
  for(int k=0;k<DD;k+=16){
    wmma::fragment<wmma::matrix_a,16,16,16,__nv_bfloat16,wmma::row_major> af;
    wmma::load_matrix_sync(af, As + (warp*16)*LDAB + k, LDAB);
    #pragma unroll
    for(int n=0;n<8;n++){
      wmma::fragment<wmma::matrix_b,16,16,16,__nv_bfloat16,wmma::row_major> bf;
      wmma::load_matrix_sync(bf, Bs + k*LDAB + n*16, LDAB);
      wmma::mma_sync(acc[n], af, bf, acc[n]);
    }
  }
  __syncthreads();

  float* epi = (float*)Bs + warp*320;
  int r2=lane>>1, half=lane&1;
  float nw = nw_s[warp*16+r2];
  float v=0.f;
  #pragma unroll
  for(int n=0;n<8;n++){
    wmma::store_matrix_sync(epi, acc[n], 20, wmma::mem_row_major);
    __syncwarp();
    const float* crow = epi + r2*20 + half*8;
    int cb = n*16 + half*8;
    #pragma unroll
    for(int j=0;j<8;j++){
      float t = crow[j] + nw*wl_s[cb+j];
      t = (t>0.f)?t:(LEAKC*t);
      v = fmaf(t, w2_s[cb+j], v);
    }
    __syncwarp();
  }
  v += __shfl_xor_sync(0xffffffffu, v, 1);
  int rg = row0 + warp*16 + r2;
  if(half==0 && rg<rowsPerB) logits[(size_t)b*rowsPerB + rg] = v;
}

// ---------------- k_soft_agg_f: 4 warps/block, warp-per-node ----------------
__global__ void __launch_bounds__(128) k_soft_agg_f(
    const int* __restrict__ inputs, const int* __restrict__ adj_all,
    const float* __restrict__ logits, float* __restrict__ outbuf, int N, int mode)
{
  int w = threadIdx.x>>5, lane = threadIdx.x&31;
  int g = blockIdx.x*4 + w;
  int b=g/N, i=g-b*N;
  __shared__ int   ci_s[4][SAMP];
  __shared__ float lg_s[4][SAMP];
  int node;
  if(mode==1){
    int pi=i/SAMP, ps=i-pi*SAMP;
    node = adj_all[inputs[b*SS+pi]*SAMP+ps];
  } else {
    node = inputs[b*SS+i];
  }
  if(lane<SAMP){
    ci_s[w][lane] = adj_all[node*SAMP+lane];
    lg_s[w][lane] = logits[(size_t)b*(N*SAMP) + i*SAMP + lane];
  }
  __syncwarp();
  float lg[SAMP];
  #pragma unroll
  for(int s=0;s<SAMP;s++) lg[s]=lg_s[w][s];
  float m=-1e30f;
  #pragma unroll
  for(int s=0;s<SAMP;s++) m=fmaxf(m,lg[s]);
  float alpha[SAMP]; float den=0.f;
  #pragma unroll
  for(int s=0;s<SAMP;s++){ alpha[s]=expf(lg[s]-m); den+=alpha[s]; }
  float inv=1.f/den;
  float4 t4 = ((const float4*)&g_E3top[(size_t)node*DD])[lane];
  float a0=0.f,a1=0.f,a2=0.f,a3=0.f;
  #pragma unroll
  for(int s=0;s<SAMP;s++){
    float4 e4 = ((const float4*)&g_E3bot[(size_t)ci_s[w][s]*DD])[lane];
    float al = alpha[s];
    a0=fmaf(al,e4.x,a0); a1=fmaf(al,e4.y,a1); a2=fmaf(al,e4.z,a2); a3=fmaf(al,e4.w,a3);
  }
  float4 o;
  o.x = tanhf(t4.x + a0*inv);
  o.y = tanhf(t4.y + a1*inv);
  o.z = tanhf(t4.z + a2*inv);
  o.w = tanhf(t4.w + a3*inv);
  ((float4*)&outbuf[(size_t)g*DD])[lane] = o;
}

// ---------------- k_soft_agg2: 4 warps/block ----------------
__global__ void __launch_bounds__(128) k_soft_agg2(const float* __restrict__ logits)
{
  int w = threadIdx.x>>5, lane = threadIdx.x&31;
  int g = blockIdx.x*4 + w;
  int b=g/SS, i=g-b*SS;
  __shared__ float lg_s[4][SAMP];
  if(lane<SAMP) lg_s[w][lane] = logits[(size_t)b*600 + i*SAMP + lane];
  __syncwarp();
  float lg[SAMP];
  #pragma unroll
  for(int s=0;s<SAMP;s++) lg[s]=lg_s[w][s];
  float m=-1e30f;
  #pragma unroll
  for(int s=0;s<SAMP;s++) m=fmaxf(m,lg[s]);
  float alpha[SAMP]; float den=0.f;
  #pragma unroll
  for(int s=0;s<SAMP;s++){ alpha[s]=expf(lg[s]-m); den+=alpha[s]; }
  float inv=1.f/den;
  float4 sv4 = ((const float4*)&g_out0[(size_t)g*DD])[lane];
  const float* base = &g_out1[(size_t)(b*600 + i*SAMP)*DD];
  float a0=0.f,a1=0.f,a2=0.f,a3=0.f;
  #pragma unroll
  for(int s=0;s<SAMP;s++){
    float4 nv4 = ((const float4*)&base[(size_t)s*DD])[lane];
    float al = alpha[s];
    a0=fmaf(al,nv4.x,a0); a1=fmaf(al,nv4.y,a1); a2=fmaf(al,nv4.z,a2); a3=fmaf(al,nv4.w,a3);
  }
  float* crow = &g_cat[(size_t)g*2*DD];
  ((float4*)crow)[lane] = sv4;
  float4 ag; ag.x=a0*inv; ag.y=a1*inv; ag.z=a2*inv; ag.w=a3*inv;
  ((float4*)(crow+DD))[lane] = ag;
}

// ---------------- k_gemm3 (mode 2) ----------------
__global__ void __launch_bounds__(128) k_gemm3(const float* __restrict__ w3,
                                               float* __restrict__ out){
  int row0 = blockIdx.x*32; int tid=threadIdx.x;
  int c = tid;
  __shared__ __align__(16) float As[16][32];
  float acc[32];
  #pragma unroll
  for(int r=0;r<32;r++) acc[r]=0.f;
  int rld = tid & 31, kq = tid >> 5;
  for(int k0=0;k0<2*DD;k0+=16){
    float4 av = *(const float4*)&g_cat[(size_t)(row0+rld)*2*DD + k0 + kq*4];
    As[kq*4+0][rld]=av.x; As[kq*4+1][rld]=av.y; As[kq*4+2][rld]=av.z; As[kq*4+3][rld]=av.w;
    __syncthreads();
    const float* w3c = w3 + (size_t)k0*DD + c;
    #pragma unroll 4
    for(int k=0;k<16;k++){
      float bk = w3c[k*DD];
      #pragma unroll
      for(int r4=0;r4<8;r4++){
        float4 a = *(const float4*)&As[k][r4*4];
        acc[r4*4+0]=fmaf(a.x,bk,acc[r4*4+0]);
        acc[r4*4+1]=fmaf(a.y,bk,acc[r4*4+1]);
        acc[r4*4+2]=fmaf(a.z,bk,acc[r4*4+2]);
        acc[r4*4+3]=fmaf(a.w,bk,acc[r4*4+3]);
      }
    }
    __syncthreads();
  }
  #pragma unroll
  for(int r=0;r<32;r++)
    out[(size_t)(row0+r)*DD + c] = tanhf(acc[r]);
}

// ---------------- k_attx ----------------
__global__ void k_attx(const int* __restrict__ adj, const float* __restrict__ a_local){
  int b=blockIdx.x; int tid=threadIdx.x;
  __shared__ __align__(16) float xs[SS][DD+4];
  __shared__ __align__(16) float al_s[4][DD];
  __shared__ float att[SS][SS+2];
  for(int idx=tid; idx<SS*DD; idx+=256){
    int i=idx>>7, d=idx&127;
    xs[i][d]=g_x[(b*SS+i)*DD+d];
  }
  for(int idx=tid; idx<4*DD; idx+=256)
    al_s[idx>>7][idx&127]=a_local[idx];
  __syncthreads();
  for(int p=tid;p<SS*SS;p+=256){
    int i=p/SS, j=p-i*SS;
    int k=adj[b*SS*SS+p];
    float e=-9e15f;
    if(k>=1 && k<=4){
      const float* al = al_s[k-1];
      float ds=0.f;
      #pragma unroll 8
      for(int d=0;d<DD;d+=4){
        float4 xi=*(const float4*)&xs[i][d];
        float4 xj=*(const float4*)&xs[j][d];
        float4 av=*(const float4*)&al[d];
        ds += xi.x*xj.x*av.x + xi.y*xj.y*av.y + xi.z*xj.z*av.z + xi.w*xj.w*av.w;
      }
      e = (ds>0.f)?ds:(LEAKC*ds);
    }
    att[i][j]=e;
  }
  __syncthreads();
  if(tid<SS){
    float m=-1e30f;
    for(int j=0;j<SS;j++) m=fmaxf(m,att[tid][j]);
    float den=0.f;
    for(int j=0;j<SS;j++){ float e=expf(att[tid][j]-m); att[tid][j]=e; den+=e; }
    float inv=1.f/den;
    for(int j=0;j<SS;j++) att[tid][j]*=inv;
  }
  __syncthreads();
  for(int q=tid;q<SS*DD;q+=256){
    int i=q>>7, d=q&127;
    float acc=0.f;
    for(int j=0;j<SS;j++) acc += att[i][j]*xs[j][d];
    g_xnew[(b*SS+i)*DD+d]=acc;
  }
}

// ---------------- k_hs ----------------
__global__ void k_hs(const int* __restrict__ inputs){
  int b=blockIdx.x, tid=threadIdx.x;
  float acc=0.f, cnt=0.f;
  for(int s=0;s<SS;s++){
    if(inputs[b*SS+s]!=0){ acc += g_hglob[(b*SS+s)*DD+tid]; cnt+=1.f; }
  }
  g_hs[b*DD+tid]=acc/cnt;
}

// ---------------- k_c2 ----------------
__global__ void k_c2(const float* __restrict__ glu2, const float* __restrict__ glu4,
                     const float* __restrict__ glu4b){
  int b=blockIdx.x, tid=threadIdx.x;
  __shared__ __align__(16) float hsr[DD], hlr[DD];
  hsr[tid]=g_hs[b*DD+tid]; hlr[tid]=g_hlocal[b*DD+tid];
  __syncthreads();
  float acc=glu4b[tid];
  const float* w2t=glu2+tid; const float* w4t=glu4+tid;
  #pragma unroll 8
  for(int k=0;k<DD;k+=4){
    float4 s4=*(const float4*)&hsr[k];
    float4 l4=*(const float4*)&hlr[k];
    acc=fmaf(s4.x,w2t[(k  )*DD],acc); acc=fmaf(l4.x,w4t[(k  )*DD],acc);
    acc=fmaf(s4.y,w2t[(k+1)*DD],acc); acc=fmaf(l4.y,w4t[(k+1)*DD],acc);
    acc=fmaf(s4.z,w2t[(k+2)*DD],acc); acc=fmaf(l4.z,w4t[(k+2)*DD],acc);
    acc=fmaf(s4.w,w2t[(k+3)*DD],acc); acc=fmaf(l4.w,w4t[(k+3)*DD],acc);
  }
  g_c2[b*DD+tid]=acc;
}

// ---------------- k_zg ----------------
__global__ void k_zg(const float* __restrict__ pos){
  int b=blockIdx.x, tid=threadIdx.x;
  float acc=0.f;
  for(int s=0;s<SS;s++)
    acc += g_beta[b*SS+s]*(g_xdot[(b*SS+s)*DD+tid]+pos[s*DD+tid]);
  g_zg[b*DD+tid]=acc;
}

// ---------------- k_zh ----------------
__global__ void k_zh(const float* __restrict__ gatew){
  int b=blockIdx.x, tid=threadIdx.x;
  __shared__ __align__(16) float zgr[DD], hlr[DD];
  zgr[tid]=g_zg[b*DD+tid]; hlr[tid]=g_hlocal[b*DD+tid];
  __syncthreads();
  const float* wt=gatew+tid;
  float acc=0.f;
  #pragma unroll 8
  for(int k=0;k<DD;k+=4){
    float4 z4=*(const float4*)&zgr[k];
    float4 l4=*(const float4*)&hlr[k];
    acc=fmaf(z4.x,wt[(k  )*DD],acc); acc=fmaf(l4.x,wt[(DD+k  )*DD],acc);
    acc=fmaf(z4.y,wt[(k+1)*DD],acc); acc=fmaf(l4.y,wt[(DD+k+1)*DD],acc);
    acc=fmaf(z4.z,wt[(k+2)*DD],acc); acc=fmaf(l4.z,wt[(DD+k+2)*DD],acc);
    acc=fmaf(z4.w,wt[(k+3)*DD],acc); acc=fmaf(l4.w,wt[(DD+k+3)*DD],acc);
  }
  float gf=sigm(acc)*0.1f;
  float zh=gf*hlr[tid]+(1.f-gf)*zgr[tid];
  g_zhT[tid*BB+b]=zh;
}

// ---------------- k_scores ----------------
__global__ void k_scores(const float* __restrict__ emb, float* __restrict__ out){
  int n0 = blockIdx.x*32; int tid=threadIdx.x;
  __shared__ __align__(16) float es[32][DD];
  int nmax = NSCORE - n0; if(nmax>32) nmax=32;
  for(int idx=tid; idx<nmax*DD; idx+=128){
    int nn=idx>>7, d=idx&127;
    es[nn][d]=emb[(size_t)(n0+nn+1)*DD+d];
  }
  __syncthreads();
  float accv[32];
  #pragma unroll
  for(int nn=0;nn<32;nn++) accv[nn]=0.f;
  for(int d=0;d<DD;d+=4){
    float z0=g_zhT[(d  )*BB+tid];
    float z1=g_zhT[(d+1)*BB+tid];
    float z2=g_zhT[(d+2)*BB+tid];
    float z3=g_zhT[(d+3)*BB+tid];
    #pragma unroll
    for(int nn=0;nn<32;nn++){
      float4 e=*reinterpret_cast<const float4*>(&es[nn][d]);
      accv[nn]=fmaf(z0,e.x,fmaf(z1,e.y,fmaf(z2,e.z,fmaf(z3,e.w,accv[nn]))));
    }
  }
  for(int nn=0;nn<nmax;nn++)
    out[1 + (size_t)tid*NSCORE + n0+nn] = accv[nn];
}

// ---------------- k_simi ----------------
__global__ void k_simi(const int* __restrict__ simi_mask){
  int blk=blockIdx.x; int b=blk/SS; int tid=threadIdx.x;
  __shared__ float f1[DD];
  __shared__ float sims[SS];
  f1[tid]   =g_hf1[blk*DD+tid];
  f1[tid+64]=g_hf1[blk*DD+tid+64];
  __syncthreads();
  if(tid<SS){
    const float* f2=&g_hf2[(b*SS+tid)*DD];
    float acc=0.f;
    for(int d=0;d<DD;d++) acc+=f1[d]*f2[d];
    sims[tid]=acc*2.0f;
  }
  __syncthreads();
  if(tid==0){
    float m=-1e30f;
    for(int j=0;j<SS;j++) m=fmaxf(m,sims[j]);
    float den=0.f;
    for(int j=0;j<SS;j++) den+=expf(sims[j]-m);
    float loss=0.f;
    for(int j=0;j<SS;j++){
      float p=expf(sims[j]-m)/den;
      float l=-logf(p+1e-8f);
      if(simi_mask[blk*SS+j]==1) loss+=l;
    }
    g_partial[blk]=loss;
  }
}

__global__ void k_simi_final(float* __restrict__ out){
  int tid=threadIdx.x;
  __shared__ float red[128];
  float a=0.f;
  for(int i=tid;i<BB*SS;i+=128) a+=g_partial[i];
  red[tid]=a; __syncthreads();
  for(int off=64;off>0;off>>=1){ if(tid<off) red[tid]+=red[tid+off]; __syncthreads(); }
  if(tid==0) out[0]=red[0]/(float)BB;
}

// ---------------- launch ----------------
extern "C" void kernel_launch(void* const* d_in, const int* in_sizes, int n_in,
                              void* d_out, int out_size){
  const int*   inputs =(const int*)  d_in[0];
  const int*   adj    =(const int*)  d_in[1];
  const int*   item   =(const int*)  d_in[2];
  const int*   simi   =(const int*)  d_in[3];
  const int*   as0    =(const int*)  d_in[4];
  const int*   as1    =(const int*)  d_in[5];
  const int*   ssl0   =(const int*)  d_in[6];
  const int*   ssl1   =(const int*)  d_in[7];
  const int*   adj_all=(const int*)  d_in[9];
  const float* num    =(const float*)d_in[10];
  const float* emb    =(const float*)d_in[11];
  const float* pos    =(const float*)d_in[12];
  const float* a_local=(const float*)d_in[13];
  const float* mir1   =(const float*)d_in[14];
  const float* mir2   =(const float*)d_in[15];
  const float* gw1    =(const float*)d_in[16];
  const float* gw2    =(const float*)d_in[17];
  const float* gw3    =(const float*)d_in[18];
  const float* attr   =(const float*)d_in[19];
  const float* hww    =(const float*)d_in[20];
  const float* glu1   =(const float*)d_in[21];
  const float* glu2   =(const float*)d_in[22];
  const float* glu4   =(const float*)d_in[23];
  const float* glu4b  =(const float*)d_in[24];
  const float* ws     =(const float*)d_in[25];
  const float* gatew  =(const float*)d_in[26];
  float* out=(float*)d_out;

  float* p_out0;   cudaGetSymbolAddress((void**)&p_out0,  g_out0);
  float* p_out1;   cudaGetSymbolAddress((void**)&p_out1,  g_out1);
  float* p_hglob;  cudaGetSymbolAddress((void**)&p_hglob, g_hglob);
  float* p_logits; cudaGetSymbolAddress((void**)&p_logits,g_logits);
  __nv_bfloat16* p_w1b; cudaGetSymbolAddress((void**)&p_w1b, g_w1b);

  const int LOGITS_SMEM = 69632 + 34816 + (3*DD + LROWS)*4 + LROWS*4;
  cudaFuncSetAttribute(k_logits, cudaFuncAttributeMaxDynamicSharedMemorySize, LOGITS_SMEM);

  k_w1bf<<<2*DD*DD/256,256>>>(gw1);
  k_e3<<<NNODE/32,128>>>(emb, gw3);
  k_pool<<<BB*SS,DD>>>(inputs, as0, as1, ssl0, ssl1, emb);
  k_attrT<<<BB*SS/16,256>>>(attr);
  k_sess<<<BB,DD>>>(inputs,item,emb);

  // mode 1
  {
    dim3 g((7200+LROWS-1)/LROWS, BB);
    k_logits<<<g,512,LOGITS_SMEM>>>(inputs,adj_all,num, emb, p_w1b, gw1+DD*DD, gw2, p_logits, 7200, 1);
  }
  k_soft_agg_f<<<BB*600/4,128>>>(inputs,adj_all, p_logits, p_out1, 600, 1);

  // mode 0
  {
    dim3 g((600+LROWS-1)/LROWS, BB);
    k_logits<<<g,512,LOGITS_SMEM>>>(inputs,adj_all,num, emb, p_w1b, gw1+DD*DD, gw2, p_logits, 600, 0);
  }
  k_soft_agg_f<<<BB*SS/4,128>>>(inputs,adj_all, p_logits, p_out0, SS, 0);

  // mode 2
  {
    dim3 g((600+LROWS-1)/LROWS, BB);
    k_logits<<<g,512,LOGITS_SMEM>>>(inputs,adj_all,num, p_out1, p_w1b+DD*DD, gw1+129*DD+DD*DD, gw2+DD, p_logits, 600, 2);
  }
  k_soft_agg2<<<BB*SS/4,128>>>(p_logits);
  k_gemm3<<<BB*SS/32,128>>>(gw3+256*DD, p_hglob);

  // local branch
  for(int it=0; it<2; it++){
    k_attx<<<BB,256>>>(adj, a_local + it*4*DD);
    k_gateT<<<BB*SS/16,256>>>(mir1 + it*DD*DD, mir2 + it*DD*DD);
  }
  k_highwayT<<<BB*SS/16,256>>>(hww);
  k_hs<<<BB,DD>>>(inputs);
  k_c2<<<BB,DD>>>(glu2,glu4,glu4b);
  k_betaT<<<BB*SS/16,256>>>(inputs,pos,glu1,ws);
  k_zg<<<BB,DD>>>(pos);
  k_zh<<<BB,DD>>>(gatew);

  k_scores<<<(NSCORE+31)/32,128>>>(emb,out);
  k_simi<<<BB*SS,64>>>(simi);
  k_simi_final<<<1,128>>>(out);
}

// round 16
// speedup vs baseline: 1.1570x; 1.0232x over previous
#include <cuda_runtime.h>
#include <cuda_bf16.h>
#include <math.h>
#include <mma.h>
using namespace nvcuda;

#define BB 128
#define SS 50
#define DD 128
#define NNODE 40000
#define SAMP 12
#define NNEI 8
#define LEAKC 0.2f
#define NSCORE 39999

// ---------------- scratch (device globals; no allocation) ----------------
__device__ float g_h[BB*SS*DD];
__device__ float g_hf1[BB*SS*DD];
__device__ float g_hf2[BB*SS*DD];
__device__ float g_x[BB*SS*DD];
__device__ float g_mirror[BB*SS*DD];
__device__ float g_xnew[BB*SS*DD];
__device__ float g_xdot[BB*SS*DD];
__device__ float g_sess[BB*DD];
__device__ float g_out0[BB*SS*DD];
__device__ float g_out1[BB*600*DD];
__device__ float g_hglob[BB*SS*DD];
__device__ float g_hlocal[BB*DD];
__device__ float g_c2[BB*DD];
__device__ float g_beta[BB*SS];
__device__ float g_zhT[DD*BB];
__device__ float g_partial[BB*SS];
__device__ float g_cat[BB*SS*2*DD];
__device__ float g_logits[BB*7200];
__device__ __nv_bfloat16 g_w1b[2*DD*DD];
__device__ float g_E3top[NNODE*DD];
__device__ float g_E3bot[NNODE*DD];

__device__ __forceinline__ float sigm(float x){ return 1.0f/(1.0f+expf(-x)); }

// ---------------- k_w1bf ----------------
__global__ void k_w1bf(const float* __restrict__ w1){
  int i = blockIdx.x*256 + threadIdx.x;
  int hop = i/(DD*DD), within = i - hop*(DD*DD);
  g_w1b[i] = __float2bfloat16(w1[(size_t)hop*129*DD + within]);
}

// ---------------- k_e3 ----------------
__global__ void __launch_bounds__(128) k_e3(const float* __restrict__ emb,
                                            const float* __restrict__ w3){
  int row0 = blockIdx.x*32; int c = threadIdx.x;
  __shared__ __align__(16) float As[16][32];
  float accT[32], accB[32];
  #pragma unroll
  for(int r=0;r<32;r++){ accT[r]=0.f; accB[r]=0.f; }
  int rld = c & 31, kq = c >> 5;
  for(int k0=0;k0<DD;k0+=16){
    float4 av = *(const float4*)&emb[(size_t)(row0+rld)*DD + k0 + kq*4];
    As[kq*4+0][rld]=av.x; As[kq*4+1][rld]=av.y; As[kq*4+2][rld]=av.z; As[kq*4+3][rld]=av.w;
    __syncthreads();
    const float* wT = w3 + (size_t)k0*DD + c;
    const float* wB = w3 + (size_t)(k0+DD)*DD + c;
    #pragma unroll 4
    for(int k=0;k<16;k++){
      float bT = wT[k*DD], bB = wB[k*DD];
      #pragma unroll
      for(int r4=0;r4<8;r4++){
        float4 a = *(const float4*)&As[k][r4*4];
        accT[r4*4+0]=fmaf(a.x,bT,accT[r4*4+0]); accB[r4*4+0]=fmaf(a.x,bB,accB[r4*4+0]);
        accT[r4*4+1]=fmaf(a.y,bT,accT[r4*4+1]); accB[r4*4+1]=fmaf(a.y,bB,accB[r4*4+1]);
        accT[r4*4+2]=fmaf(a.z,bT,accT[r4*4+2]); accB[r4*4+2]=fmaf(a.z,bB,accB[r4*4+2]);
        accT[r4*4+3]=fmaf(a.w,bT,accT[r4*4+3]); accB[r4*4+3]=fmaf(a.w,bB,accB[r4*4+3]);
      }
    }
    __syncthreads();
  }
  #pragma unroll
  for(int r=0;r<32;r++){
    g_E3top[(size_t)(row0+r)*DD + c] = accT[r];
    g_E3bot[(size_t)(row0+r)*DD + c] = accB[r];
  }
}

// ---------------- k_pool ----------------
__global__ void k_pool(const int* __restrict__ inputs,
                       const int* __restrict__ as0, const int* __restrict__ as1,
                       const int* __restrict__ ssl0, const int* __restrict__ ssl1,
                       const float* __restrict__ emb){
  int blk = blockIdx.x; int tid = threadIdx.x;
  int node = inputs[blk];
  g_h[blk*DD+tid] = emb[node*DD+tid];
  float p1=0.f, p2=0.f;
  const int* L1[2] = {as0, as1};
  const int* L2[2] = {ssl0, ssl1};
  #pragma unroll
  for(int l=0;l<2;l++){
    float s=0.f,c=0.f;
    #pragma unroll
    for(int n=0;n<NNEI;n++){ int id=L1[l][blk*NNEI+n]; if(id!=0){ s+=emb[id*DD+tid]; c+=1.f; } }
    p1 += s/(c+1e-8f);
    s=0.f;c=0.f;
    #pragma unroll
    for(int n=0;n<NNEI;n++){ int id=L2[l][blk*NNEI+n]; if(id!=0){ s+=emb[id*DD+tid]; c+=1.f; } }
    p2 += s/(c+1e-8f);
  }
  g_hf1[blk*DD+tid] = p1*0.5f;
  g_hf2[blk*DD+tid] = p2*0.5f;
}

// ====== 16-row, 256-thread matvec family: 32-k chunks, bk[32] batch, dbl-buffer ======

// ---------------- k_attrT ----------------
__global__ void __launch_bounds__(256) k_attrT(const float* __restrict__ attr_w){
  int row0 = blockIdx.x*16;
  int tid=threadIdx.x;
  int half = tid>>7, c = tid & 127;
  int sk2 = tid & 31, sr2 = tid >> 5;
  __shared__ __align__(16) float As[2][32][17];
  float acc[8];
  #pragma unroll
  for(int r=0;r<8;r++) acc[r]=0.f;

  As[0][sk2][sr2]   = g_h[(size_t)(row0+sr2  )*DD + sk2];
  As[0][sk2][sr2+8] = g_h[(size_t)(row0+sr2+8)*DD + sk2];
  __syncthreads();

  for(int ch=0; ch<8; ch++){
    int buf = ch & 1;
    float bk[32];
    {
      const float* wc = attr_w + (size_t)(ch*32)*DD + c;
      #pragma unroll
      for(int k=0;k<32;k++) bk[k]=wc[k*DD];
    }
    float st0=0.f, st1=0.f;
    if(ch<7){
      int k0n = (ch+1)*32;
      const float* srcA = (k0n<DD)? g_h : g_hf1;
      int kk = k0n & (DD-1);
      st0 = srcA[(size_t)(row0+sr2  )*DD + kk + sk2];
      st1 = srcA[(size_t)(row0+sr2+8)*DD + kk + sk2];
    }
    #pragma unroll
    for(int k=0;k<32;k++){
      #pragma unroll
      for(int r=0;r<8;r++)
        acc[r] = fmaf(As[buf][k][half*8+r], bk[k], acc[r]);
    }
    if(ch<7){
      As[buf^1][sk2][sr2]   = st0;
      As[buf^1][sk2][sr2+8] = st1;
      __syncthreads();
    }
  }
  #pragma unroll
  for(int r=0;r<8;r++){
    int row = row0 + half*8 + r;
    size_t idx=(size_t)row*DD + c;
    float g=sigm(acc[r]);
    float h=g_h[idx], f=g_hf1[idx];
    g_x[idx]=h;
    g_mirror[idx]=g*h+(1.f-g)*f;
  }
}

// ---------------- k_gateT ----------------
__global__ void __launch_bounds__(256) k_gateT(const float* __restrict__ w1,
                                               const float* __restrict__ w2){
  int row0 = blockIdx.x*16;
  int tid=threadIdx.x;
  int half = tid>>7, c = tid & 127;
  int sk2 = tid & 31, sr2 = tid >> 5;
  __shared__ __align__(16) float As[2][32][17];
  float acc[8];
  #pragma unroll
  for(int r=0;r<8;r++) acc[r]=0.f;

  As[0][sk2][sr2]   = g_xnew[(size_t)(row0+sr2  )*DD + sk2];
  As[0][sk2][sr2+8] = g_xnew[(size_t)(row0+sr2+8)*DD + sk2];
  __syncthreads();

  for(int ch=0; ch<8; ch++){
    int buf = ch & 1;
    float bk[32];
    {
      int k0 = ch*32;
      const float* wc = ((k0<DD)? w1 + (size_t)k0*DD : w2 + (size_t)(k0-DD)*DD) + c;
      #pragma unroll
      for(int k=0;k<32;k++) bk[k]=wc[k*DD];
    }
    float st0=0.f, st1=0.f;
    if(ch<7){
      int k0n = (ch+1)*32;
      const float* srcA = (k0n<DD)? g_xnew : g_mirror;
      int kk = k0n & (DD-1);
      st0 = srcA[(size_t)(row0+sr2  )*DD + kk + sk2];
      st1 = srcA[(size_t)(row0+sr2+8)*DD + kk + sk2];
    }
    #pragma unroll
    for(int k=0;k<32;k++){
      #pragma unroll
      for(int r=0;r<8;r++)
        acc[r] = fmaf(As[buf][k][half*8+r], bk[k], acc[r]);
    }
    if(ch<7){
      As[buf^1][sk2][sr2]   = st0;
      As[buf^1][sk2][sr2+8] = st1;
      __syncthreads();
    }
  }
  #pragma unroll
  for(int r=0;r<8;r++){
    int row = row0 + half*8 + r;
    size_t idx=(size_t)row*DD + c;
    float gm=sigm(acc[r]);
    float xv=g_xnew[idx], mv=g_mirror[idx];
    g_x[idx]      = gm*xv + (1.f-gm)*mv;
    g_mirror[idx] = gm*mv + (1.f-gm)*xv;
  }
}

// ---------------- k_highwayT ----------------
__global__ void __launch_bounds__(256) k_highwayT(const float* __restrict__ hw){
  int row0 = blockIdx.x*16;
  int tid=threadIdx.x;
  int half = tid>>7, c = tid & 127;
  int sk2 = tid & 31, sr2 = tid >> 5;
  __shared__ __align__(16) float As[2][32][17];
  float acc[8];
  #pragma unroll
  for(int r=0;r<8;r++) acc[r]=0.f;

  As[0][sk2][sr2]   = g_h[(size_t)(row0+sr2  )*DD + sk2];
  As[0][sk2][sr2+8] = g_h[(size_t)(row0+sr2+8)*DD + sk2];
  __syncthreads();

  for(int ch=0; ch<8; ch++){
    int buf = ch & 1;
    float bk[32];
    {
      const float* wc = hw + (size_t)(ch*32)*DD + c;
      #pragma unroll
      for(int k=0;k<32;k++) bk[k]=wc[k*DD];
    }
    float st0=0.f, st1=0.f;
    if(ch<7){
      int k0n = (ch+1)*32;
      const float* srcA = (k0n<DD)? g_h : g_x;
      int kk = k0n & (DD-1);
      st0 = srcA[(size_t)(row0+sr2  )*DD + kk + sk2];
      st1 = srcA[(size_t)(row0+sr2+8)*DD + kk + sk2];
    }
    #pragma unroll
    for(int k=0;k<32;k++){
      #pragma unroll
      for(int r=0;r<8;r++)
        acc[r] = fmaf(As[buf][k][half*8+r], bk[k], acc[r]);
    }
    if(ch<7){
      As[buf^1][sk2][sr2]   = st0;
      As[buf^1][sk2][sr2+8] = st1;
      __syncthreads();
    }
  }
  #pragma unroll
  for(int r=0;r<8;r++){
    int row = row0 + half*8 + r;
    size_t idx=(size_t)row*DD + c;
    float g=sigm(acc[r]);
    float h=g_h[idx], xv=g_x[idx];
    float xd=g*h+(1.f-g)*xv;
    g_xdot[idx]=xd;
    if(row%SS==SS-1) g_hlocal[(row/SS)*DD+c]=xd;
  }
}

// ---------------- k_betaT ----------------
__global__ void __launch_bounds__(256) k_betaT(const int* __restrict__ inputs,
                                               const float* __restrict__ pos,
                                               const float* __restrict__ glu1,
                                               const float* __restrict__ ws){
  int row0 = blockIdx.x*16;
  int tid=threadIdx.x;
  int half = tid>>7, c = tid & 127;
  int sk2 = tid & 31, sr2 = tid >> 5;
  __shared__ __align__(16) float As[2][32][17];
  __shared__ float pr[16][132];
  __shared__ float red2[16][16];
  float acc[8];
  #pragma unroll
  for(int r=0;r<8;r++) acc[r]=0.f;

  int rowA = row0 + sr2, rowB = row0 + sr2 + 8;
  int sA = rowA % SS, sB = rowB % SS;
  As[0][sk2][sr2]   = g_xdot[(size_t)rowA*DD + sk2] + pos[(size_t)sA*DD + sk2];
  As[0][sk2][sr2+8] = g_xdot[(size_t)rowB*DD + sk2] + pos[(size_t)sB*DD + sk2];
  __syncthreads();

  for(int ch=0; ch<4; ch++){
    int buf = ch & 1;
    float bk[32];
    {
      const float* wc = glu1 + (size_t)(ch*32)*DD + c;
      #pragma unroll
      for(int k=0;k<32;k++) bk[k]=wc[k*DD];
    }
    float st0=0.f, st1=0.f;
    if(ch<3){
      int k0n = (ch+1)*32;
      st0 = g_xdot[(size_t)rowA*DD + k0n + sk2] + pos[(size_t)sA*DD + k0n + sk2];
      st1 = g_xdot[(size_t)rowB*DD + k0n + sk2] + pos[(size_t)sB*DD + k0n + sk2];
    }
    #pragma unroll
    for(int k=0;k<32;k++){
      #pragma unroll
      for(int r=0;r<8;r++)
        acc[r] = fmaf(As[buf][k][half*8+r], bk[k], acc[r]);
    }
    if(ch<3){
      As[buf^1][sk2][sr2]   = st0;
      As[buf^1][sk2][sr2+8] = st1;
      __syncthreads();
    }
  }
  float wsc = ws[c];
  #pragma unroll
  for(int r=0;r<8;r++){
    int row = row0 + half*8 + r;
    int b=row/SS;
    float nh=sigm(acc[r] + g_c2[b*DD+c]);
    pr[half*8+r][c]=nh*wsc;
  }
  __syncthreads();
  {
    int rr=tid>>4, seg=tid&15;
    float s=0.f;
    #pragma unroll
    for(int j=0;j<8;j++) s+=pr[rr][seg*8+j];
    red2[rr][seg]=s;
  }
  __syncthreads();
  if(tid<16){
    float s=0.f;
    #pragma unroll
    for(int j=0;j<16;j++) s+=red2[tid][j];
    int row=row0+tid;
    float mi=(inputs[row]!=0)?1.f:0.f;
    g_beta[row]=s*mi;
  }
}

// ---------------- k_sess ----------------
__global__ void k_sess(const int* __restrict__ inputs, const int* __restrict__ item,
                       const float* __restrict__ emb){
  int b=blockIdx.x, tid=threadIdx.x;
  float acc=0.f, cnt=0.f;
  for(int s=0;s<SS;s++){
    int inp=inputs[b*SS+s];
    if(inp!=0){ acc += emb[item[b*SS+s]*DD+tid]; cnt+=1.f; }
  }
  g_sess[b*DD+tid]=acc/cnt;
}

// ---------------- k_logits ----------------
#define LROWS 256
__global__ void __launch_bounds__(512) k_logits(
    const int* __restrict__ inputs, const int* __restrict__ adj_all,
    const float* __restrict__ num, const float* __restrict__ src,
    const __nv_bfloat16* __restrict__ w1b,
    const float* __restrict__ w1last, const float* __restrict__ w2,
    float* __restrict__ logits, int rowsPerB, int mode)
{
  extern __shared__ char smem[];
  const int LDAB = 136;
  __nv_bfloat16* As = (__nv_bfloat16*)smem;
  __nv_bfloat16* Bs = (__nv_bfloat16*)(smem + 69632);
  float* sess_s = (float*)(smem + 104448);
  float* wl_s   = sess_s + DD;
  float* w2_s   = wl_s + DD;
  float* nw_s   = w2_s + DD;
  int*   ci_s   = (int*)(nw_s + LROWS);

  int b = blockIdx.y;
  int row0 = blockIdx.x*LROWS;
  int tid = threadIdx.x, warp = tid>>5, lane = tid&31;

  if(tid<DD){
    sess_s[tid]=g_sess[b*DD+tid];
    wl_s[tid]  =w1last[tid];
    w2_s[tid]  =w2[tid];
  }
  if(tid<LROWS){
    int r = row0 + tid;
    int rr = (r<rowsPerB)? r : rowsPerB-1;
    int gi=rr/SAMP, s=rr-gi*SAMP;
    int node, ci;
    if(mode==1){
      int pi=gi/SAMP, ps=gi-pi*SAMP;
      node = adj_all[inputs[b*SS+pi]*SAMP+ps];
      ci = adj_all[node*SAMP+s];
    } else if(mode==0){
      node = inputs[b*SS+gi];
      ci = adj_all[node*SAMP+s];
    } else {
      node = inputs[b*SS+gi];
      ci = b*600 + rr;
    }
    ci_s[tid]=ci;
    nw_s[tid]=num[node*SAMP+s];
  }
  {
    int row=tid>>2, qb=(tid&3)*32;
    const uint4* srcw=(const uint4*)(w1b + row*DD + qb);
    uint4* dst=(uint4*)(Bs + row*LDAB + qb);
    #pragma unroll
    for(int j=0;j<4;j++) dst[j]=srcw[j];
  }
  __syncthreads();
  {
    int row=tid>>1, cb=(tid&1)*64;
    const float* ap = src + (size_t)ci_s[row]*DD + cb;
    __nv_bfloat16* dst = As + row*LDAB + cb;
    #pragma unroll
    for(int j=0;j<16;j++){
      float4 v=*(const float4*)&ap[j*4];
      float4 se=*(const float4*)&sess_s[cb+j*4];
      *(__nv_bfloat162*)&dst[j*4]   = __floats2bfloat162_rn(v.x*se.x, v.y*se.y);
      *(__nv_bfloat162*)&dst[j*4+2] = __floats2bfloat162_rn(v.z*se.z, v.w*se.w);
    }
  }
  __syncthreads();

  wmma::fragment<wmma::accumulator,16,16,16,float> acc[8];
  #pragma unroll
  for(int n=0;n<8;n++) wmma::fill_fragment(acc[n], 0.0f);

  #pragma unroll
  for(int k=0;k<DD;k+=16){
    wmma::fragment<wmma::matrix_a,16,16,16,__nv_bfloat16,wmma::row_major> af;
    wmma::load_matrix_sync(af, As + (warp*16)*LDAB + k, LDAB);
    #pragma unroll
    for(int n=0;n<8;n++){
      wmma::fragment<wmma::matrix_b,16,16,16,__nv_bfloat16,wmma::row_major> bf;
      wmma::load_matrix_sync(bf, Bs + k*LDAB + n*16, LDAB);
      wmma::mma_sync(acc[n], af, bf, acc[n]);
    }
  }
  __syncthreads();

  float* epi = (float*)Bs + warp*320;
  int r2=lane>>1, half=lane&1;
  float nw = nw_s[warp*16+r2];
  float v=0.f;
  #pragma unroll
  for(int n=0;n<8;n++){
    wmma::store_matrix_sync(epi, acc[n], 20, wmma::mem_row_major);
    __syncwarp();
    const float* crow = epi + r2*20 + half*8;
    int cb = n*16 + half*8;
    #pragma unroll
    for(int j=0;j<8;j++){
      float t = crow[j] + nw*wl_s[cb+j];
      t = (t>0.f)?t:(LEAKC*t);
      v = fmaf(t, w2_s[cb+j], v);
    }
    __syncwarp();
  }
  v += __shfl_xor_sync(0xffffffffu, v, 1);
  int rg = row0 + warp*16 + r2;
  if(half==0 && rg<rowsPerB) logits[(size_t)b*rowsPerB + rg] = v;
}

// ---------------- k_soft_agg_f: 4 warps/block ----------------
__global__ void __launch_bounds__(128) k_soft_agg_f(
    const int* __restrict__ inputs, const int* __restrict__ adj_all,
    const float* __restrict__ logits, float* __restrict__ outbuf, int N, int mode)
{
  int w = threadIdx.x>>5, lane = threadIdx.x&31;
  int g = blockIdx.x*4 + w;
  int b=g/N, i=g-b*N;
  __shared__ int   ci_s[4][SAMP];
  __shared__ float lg_s[4][SAMP];
  int node;
  if(mode==1){
    int pi=i/SAMP, ps=i-pi*SAMP;
    node = adj_all[inputs[b*SS+pi]*SAMP+ps];
  } else {
    node = inputs[b*SS+i];
  }
  if(lane<SAMP){
    ci_s[w][lane] = adj_all[node*SAMP+lane];
    lg_s[w][lane] = logits[(size_t)b*(N*SAMP) + i*SAMP + lane];
  }
  __syncwarp();
  float lg[SAMP];
  #pragma unroll
  for(int s=0;s<SAMP;s++) lg[s]=lg_s[w][s];
  float m=-1e30f;
  #pragma unroll
  for(int s=0;s<SAMP;s++) m=fmaxf(m,lg[s]);
  float alpha[SAMP]; float den=0.f;
  #pragma unroll
  for(int s=0;s<SAMP;s++){ alpha[s]=expf(lg[s]-m); den+=alpha[s]; }
  float inv=1.f/den;
  float4 t4 = ((const float4*)&g_E3top[(size_t)node*DD])[lane];
  float a0=0.f,a1=0.f,a2=0.f,a3=0.f;
  #pragma unroll
  for(int s=0;s<SAMP;s++){
    float4 e4 = ((const float4*)&g_E3bot[(size_t)ci_s[w][s]*DD])[lane];
    float al = alpha[s];
    a0=fmaf(al,e4.x,a0); a1=fmaf(al,e4.y,a1); a2=fmaf(al,e4.z,a2); a3=fmaf(al,e4.w,a3);
  }
  float4 o;
  o.x = tanhf(t4.x + a0*inv);
  o.y = tanhf(t4.y + a1*inv);
  o.z = tanhf(t4.z + a2*inv);
  o.w = tanhf(t4.w + a3*inv);
  ((float4*)&outbuf[(size_t)g*DD])[lane] = o;
}

// ---------------- k_soft_agg2: 4 warps/block ----------------
__global__ void __launch_bounds__(128) k_soft_agg2(const float* __restrict__ logits)
{
  int w = threadIdx.x>>5, lane = threadIdx.x&31;
  int g = blockIdx.x*4 + w;
  int b=g/SS, i=g-b*SS;
  __shared__ float lg_s[4][SAMP];
  if(lane<SAMP) lg_s[w][lane] = logits[(size_t)b*600 + i*SAMP + lane];
  __syncwarp();
  float lg[SAMP];
  #pragma unroll
  for(int s=0;s<SAMP;s++) lg[s]=lg_s[w][s];
  float m=-1e30f;
  #pragma unroll
  for(int s=0;s<SAMP;s++) m=fmaxf(m,lg[s]);
  float alpha[SAMP]; float den=0.f;
  #pragma unroll
  for(int s=0;s<SAMP;s++){ alpha[s]=expf(lg[s]-m); den+=alpha[s]; }
  float inv=1.f/den;
  float4 sv4 = ((const float4*)&g_out0[(size_t)g*DD])[lane];
  const float* base = &g_out1[(size_t)(b*600 + i*SAMP)*DD];
  float a0=0.f,a1=0.f,a2=0.f,a3=0.f;
  #pragma unroll
  for(int s=0;s<SAMP;s++){
    float4 nv4 = ((const float4*)&base[(size_t)s*DD])[lane];
    float al = alpha[s];
    a0=fmaf(al,nv4.x,a0); a1=fmaf(al,nv4.y,a1); a2=fmaf(al,nv4.z,a2); a3=fmaf(al,nv4.w,a3);
  }
  float* crow = &g_cat[(size_t)g*2*DD];
  ((float4*)crow)[lane] = sv4;
  float4 ag; ag.x=a0*inv; ag.y=a1*inv; ag.z=a2*inv; ag.w=a3*inv;
  ((float4*)(crow+DD))[lane] = ag;
}

// ---------------- k_gemm3 (mode 2) ----------------
__global__ void __launch_bounds__(128) k_gemm3(const float* __restrict__ w3,
                                               float* __restrict__ out){
  int row0 = blockIdx.x*32; int tid=threadIdx.x;
  int c = tid;
  __shared__ __align__(16) float As[16][32];
  float acc[32];
  #pragma unroll
  for(int r=0;r<32;r++) acc[r]=0.f;
  int rld = tid & 31, kq = tid >> 5;
  for(int k0=0;k0<2*DD;k0+=16){
    float4 av = *(const float4*)&g_cat[(size_t)(row0+rld)*2*DD + k0 + kq*4];
    As[kq*4+0][rld]=av.x; As[kq*4+1][rld]=av.y; As[kq*4+2][rld]=av.z; As[kq*4+3][rld]=av.w;
    __syncthreads();
    const float* w3c = w3 + (size_t)k0*DD + c;
    #pragma unroll 4
    for(int k=0;k<16;k++){
      float bk = w3c[k*DD];
      #pragma unroll
      for(int r4=0;r4<8;r4++){
        float4 a = *(const float4*)&As[k][r4*4];
        acc[r4*4+0]=fmaf(a.x,bk,acc[r4*4+0]);
        acc[r4*4+1]=fmaf(a.y,bk,acc[r4*4+1]);
        acc[r4*4+2]=fmaf(a.z,bk,acc[r4*4+2]);
        acc[r4*4+3]=fmaf(a.w,bk,acc[r4*4+3]);
      }
    }
    __syncthreads();
  }
  #pragma unroll
  for(int r=0;r<32;r++)
    out[(size_t)(row0+r)*DD + c] = tanhf(acc[r]);
}

// ---------------- k_attx ----------------
__global__ void k_attx(const int* __restrict__ adj, const float* __restrict__ a_local){
  int b=blockIdx.x; int tid=threadIdx.x;
  __shared__ __align__(16) float xs[SS][DD+4];
  __shared__ __align__(16) float al_s[4][DD];
  __shared__ float att[SS][SS+2];
  for(int idx=tid; idx<SS*DD; idx+=256){
    int i=idx>>7, d=idx&127;
    xs[i][d]=g_x[(b*SS+i)*DD+d];
  }
  for(int idx=tid; idx<4*DD; idx+=256)
    al_s[idx>>7][idx&127]=a_local[idx];
  __syncthreads();
  for(int p=tid;p<SS*SS;p+=256){
    int i=p/SS, j=p-i*SS;
    int k=adj[b*SS*SS+p];
    float e=-9e15f;
    if(k>=1 && k<=4){
      const float* al = al_s[k-1];
      float ds=0.f;
      #pragma unroll 8
      for(int d=0;d<DD;d+=4){
        float4 xi=*(const float4*)&xs[i][d];
        float4 xj=*(const float4*)&xs[j][d];
        float4 av=*(const float4*)&al[d];
        ds += xi.x*xj.x*av.x + xi.y*xj.y*av.y + xi.z*xj.z*av.z + xi.w*xj.w*av.w;
      }
      e = (ds>0.f)?ds:(LEAKC*ds);
    }
    att[i][j]=e;
  }
  __syncthreads();
  if(tid<SS){
    float m=-1e30f;
    for(int j=0;j<SS;j++) m=fmaxf(m,att[tid][j]);
    float den=0.f;
    for(int j=0;j<SS;j++){ float e=expf(att[tid][j]-m); att[tid][j]=e; den+=e; }
    float inv=1.f/den;
    for(int j=0;j<SS;j++) att[tid][j]*=inv;
  }
  __syncthreads();
  for(int q=tid;q<SS*DD;q+=256){
    int i=q>>7, d=q&127;
    float acc=0.f;
    for(int j=0;j<SS;j++) acc += att[i][j]*xs[j][d];
    g_xnew[(b*SS+i)*DD+d]=acc;
  }
}

// ---------------- k_hsc2: fused hs + c2 ----------------
__global__ void k_hsc2(const int* __restrict__ inputs,
                       const float* __restrict__ glu2, const float* __restrict__ glu4,
                       const float* __restrict__ glu4b){
  int b=blockIdx.x, tid=threadIdx.x;
  __shared__ __align__(16) float hsr[DD], hlr[DD];
  float acc=0.f, cnt=0.f;
  for(int s=0;s<SS;s++){
    if(inputs[b*SS+s]!=0){ acc += g_hglob[(b*SS+s)*DD+tid]; cnt+=1.f; }
  }
  hsr[tid]=acc/cnt;
  hlr[tid]=g_hlocal[b*DD+tid];
  __syncthreads();
  float a2=glu4b[tid];
  const float* w2t=glu2+tid; const float* w4t=glu4+tid;
  #pragma unroll 8
  for(int k=0;k<DD;k+=4){
    float4 s4=*(const float4*)&hsr[k];
    float4 l4=*(const float4*)&hlr[k];
    a2=fmaf(s4.x,w2t[(k  )*DD],a2); a2=fmaf(l4.x,w4t[(k  )*DD],a2);
    a2=fmaf(s4.y,w2t[(k+1)*DD],a2); a2=fmaf(l4.y,w4t[(k+1)*DD],a2);
    a2=fmaf(s4.z,w2t[(k+2)*DD],a2); a2=fmaf(l4.z,w4t[(k+2)*DD],a2);
    a2=fmaf(s4.w,w2t[(k+3)*DD],a2); a2=fmaf(l4.w,w4t[(k+3)*DD],a2);
  }
  g_c2[b*DD+tid]=a2;
}

// ---------------- k_zgzh: fused zg + zh ----------------
__global__ void k_zgzh(const float* __restrict__ pos, const float* __restrict__ gatew){
  int b=blockIdx.x, tid=threadIdx.x;
  __shared__ __align__(16) float zgr[DD], hlr[DD];
  float acc=0.f;
  for(int s=0;s<SS;s++)
    acc += g_beta[b*SS+s]*(g_xdot[(b*SS+s)*DD+tid]+pos[s*DD+tid]);
  zgr[tid]=acc;
  hlr[tid]=g_hlocal[b*DD+tid];
  __syncthreads();
  const float* wt=gatew+tid;
  float a2=0.f;
  #pragma unroll 8
  for(int k=0;k<DD;k+=4){
    float4 z4=*(const float4*)&zgr[k];
    float4 l4=*(const float4*)&hlr[k];
    a2=fmaf(z4.x,wt[(k  )*DD],a2); a2=fmaf(l4.x,wt[(DD+k  )*DD],a2);
    a2=fmaf(z4.y,wt[(k+1)*DD],a2); a2=fmaf(l4.y,wt[(DD+k+1)*DD],a2);
    a2=fmaf(z4.z,wt[(k+2)*DD],a2); a2=fmaf(l4.z,wt[(DD+k+2)*DD],a2);
    a2=fmaf(z4.w,wt[(k+3)*DD],a2); a2=fmaf(l4.w,wt[(DD+k+3)*DD],a2);
  }
  float gf=sigm(a2)*0.1f;
  float zh=gf*hlr[tid]+(1.f-gf)*zgr[tid];
  g_zhT[tid*BB+b]=zh;
}

// ---------------- k_scoresT: TF32 TC scores = zh @ emb[1:]^T ----------------
__global__ void __launch_bounds__(256) k_scoresT(const float* __restrict__ emb,
                                                 float* __restrict__ out){
  extern __shared__ char smem2[];
  float* Bs  = (float*)smem2;           // [128][136] tf32 emb tile (69632 B)
  float* epi = Bs + 128*136;            // 8 warps x 320 floats (10240 B)
  int n0 = blockIdx.x*128;
  int tid=threadIdx.x, warp=tid>>5, lane=tid&31;

  // stage emb tile (row n -> node n0+n+1, clamped)
  {
    int n=tid>>1, cb=(tid&1)*64;
    int er = n0+n+1; if(er>NSCORE) er=NSCORE;
    const float* ap = emb + (size_t)er*DD + cb;
    float* dst = Bs + n*136 + cb;
    #pragma unroll
    for(int j=0;j<16;j++){
      float4 v=*(const float4*)&ap[j*4];
      v.x=wmma::__float_to_tf32(v.x); v.y=wmma::__float_to_tf32(v.y);
      v.z=wmma::__float_to_tf32(v.z); v.w=wmma::__float_to_tf32(v.w);
      *(float4*)&dst[j*4]=v;
    }
  }
  __syncthreads();

  wmma::fragment<wmma::accumulator,16,16,8,float> acc[8];
  #pragma unroll
  for(int n=0;n<8;n++) wmma::fill_fragment(acc[n],0.f);
  int m0 = warp*16;
  for(int k0=0;k0<DD;k0+=8){
    wmma::fragment<wmma::matrix_a,16,16,8,wmma::precision::tf32,wmma::col_major> af;
    wmma::load_matrix_sync(af, g_zhT + (size_t)k0*BB + m0, BB);
    #pragma unroll
    for(int i=0;i<af.num_elements;i++) af.x[i]=wmma::__float_to_tf32(af.x[i]);
    #pragma unroll
    for(int nt=0;nt<8;nt++){
      wmma::fragment<wmma::matrix_b,16,16,8,wmma::precision::tf32,wmma::col_major> bf;
      wmma::load_matrix_sync(bf, Bs + nt*16*136 + k0, 136);
      wmma::mma_sync(acc[nt],af,bf,acc[nt]);
    }
  }
  // epilogue: smem round-trip, bounded coalesced stores
  float* ep = epi + warp*320;
  int r=lane>>1, half=lane&1;
  #pragma unroll
  for(int nt=0;nt<8;nt++){
    wmma::store_matrix_sync(ep, acc[nt], 20, wmma::mem_row_major);
    __syncwarp();
    int colb = n0 + nt*16 + half*8;
    float* orow = out + 1 + (size_t)(m0+r)*NSCORE + colb;
    const float* crow = ep + r*20 + half*8;
    #pragma unroll
    for(int j=0;j<8;j++)
      if(colb+j < NSCORE) orow[j] = crow[j];
    __syncwarp();
  }
}

// ---------------- k_simi ----------------
__global__ void k_simi(const int* __restrict__ simi_mask){
  int blk=blockIdx.x; int b=blk/SS; int tid=threadIdx.x;
  __shared__ float f1[DD];
  __shared__ float sims[SS];
  f1[tid]   =g_hf1[blk*DD+tid];
  f1[tid+64]=g_hf1[blk*DD+tid+64];
  __syncthreads();
  if(tid<SS){
    const float* f2=&g_hf2[(b*SS+tid)*DD];
    float acc=0.f;
    for(int d=0;d<DD;d++) acc+=f1[d]*f2[d];
    sims[tid]=acc*2.0f;
  }
  __syncthreads();
  if(tid==0){
    float m=-1e30f;
    for(int j=0;j<SS;j++) m=fmaxf(m,sims[j]);
    float den=0.f;
    for(int j=0;j<SS;j++) den+=expf(sims[j]-m);
    float loss=0.f;
    for(int j=0;j<SS;j++){
      float p=expf(sims[j]-m)/den;
      float l=-logf(p+1e-8f);
      if(simi_mask[blk*SS+j]==1) loss+=l;
    }
    g_partial[blk]=loss;
  }
}

__global__ void k_simi_final(float* __restrict__ out){
  int tid=threadIdx.x;
  __shared__ float red[128];
  float a=0.f;
  for(int i=tid;i<BB*SS;i+=128) a+=g_partial[i];
  red[tid]=a; __syncthreads();
  for(int off=64;off>0;off>>=1){ if(tid<off) red[tid]+=red[tid+off]; __syncthreads(); }
  if(tid==0) out[0]=red[0]/(float)BB;
}

// ---------------- launch ----------------
extern "C" void kernel_launch(void* const* d_in, const int* in_sizes, int n_in,
                              void* d_out, int out_size){
  const int*   inputs =(const int*)  d_in[0];
  const int*   adj    =(const int*)  d_in[1];
  const int*   item   =(const int*)  d_in[2];
  const int*   simi   =(const int*)  d_in[3];
  const int*   as0    =(const int*)  d_in[4];
  const int*   as1    =(const int*)  d_in[5];
  const int*   ssl0   =(const int*)  d_in[6];
  const int*   ssl1   =(const int*)  d_in[7];
  const int*   adj_all=(const int*)  d_in[9];
  const float* num    =(const float*)d_in[10];
  const float* emb    =(const float*)d_in[11];
  const float* pos    =(const float*)d_in[12];
  const float* a_local=(const float*)d_in[13];
  const float* mir1   =(const float*)d_in[14];
  const float* mir2   =(const float*)d_in[15];
  const float* gw1    =(const float*)d_in[16];
  const float* gw2    =(const float*)d_in[17];
  const float* gw3    =(const float*)d_in[18];
  const float* attr   =(const float*)d_in[19];
  const float* hww    =(const float*)d_in[20];
  const float* glu1   =(const float*)d_in[21];
  const float* glu2   =(const float*)d_in[22];
  const float* glu4   =(const float*)d_in[23];
  const float* glu4b  =(const float*)d_in[24];
  const float* ws     =(const float*)d_in[25];
  const float* gatew  =(const float*)d_in[26];
  float* out=(float*)d_out;

  float* p_out0;   cudaGetSymbolAddress((void**)&p_out0,  g_out0);
  float* p_out1;   cudaGetSymbolAddress((void**)&p_out1,  g_out1);
  float* p_hglob;  cudaGetSymbolAddress((void**)&p_hglob, g_hglob);
  float* p_logits; cudaGetSymbolAddress((void**)&p_logits,g_logits);
  __nv_bfloat16* p_w1b; cudaGetSymbolAddress((void**)&p_w1b, g_w1b);

  const int LOGITS_SMEM = 69632 + 34816 + (3*DD + LROWS)*4 + LROWS*4;
  cudaFuncSetAttribute(k_logits, cudaFuncAttributeMaxDynamicSharedMemorySize, LOGITS_SMEM);
  const int SCORES_SMEM = 128*136*4 + 8*320*4;   // 79872 B
  cudaFuncSetAttribute(k_scoresT, cudaFuncAttributeMaxDynamicSharedMemorySize, SCORES_SMEM);

  k_w1bf<<<2*DD*DD/256,256>>>(gw1);
  k_e3<<<NNODE/32,128>>>(emb, gw3);
  k_pool<<<BB*SS,DD>>>(inputs, as0, as1, ssl0, ssl1, emb);
  k_attrT<<<BB*SS/16,256>>>(attr);
  k_sess<<<BB,DD>>>(inputs,item,emb);

  // mode 1
  {
    dim3 g((7200+LROWS-1)/LROWS, BB);
    k_logits<<<g,512,LOGITS_SMEM>>>(inputs,adj_all,num, emb, p_w1b, gw1+DD*DD, gw2, p_logits, 7200, 1);
  }
  k_soft_agg_f<<<BB*600/4,128>>>(inputs,adj_all, p_logits, p_out1, 600, 1);

  // mode 0
  {
    dim3 g((600+LROWS-1)/LROWS, BB);
    k_logits<<<g,512,LOGITS_SMEM>>>(inputs,adj_all,num, emb, p_w1b, gw1+DD*DD, gw2, p_logits, 600, 0);
  }
  k_soft_agg_f<<<BB*SS/4,128>>>(inputs,adj_all, p_logits, p_out0, SS, 0);

  // mode 2
  {
    dim3 g((600+LROWS-1)/LROWS, BB);
    k_logits<<<g,512,LOGITS_SMEM>>>(inputs,adj_all,num, p_out1, p_w1b+DD*DD, gw1+129*DD+DD*DD, gw2+DD, p_logits, 600, 2);
  }
  k_soft_agg2<<<BB*SS/4,128>>>(p_logits);
  k_gemm3<<<BB*SS/32,128>>>(gw3+256*DD, p_hglob);

  // local branch
  for(int it=0; it<2; it++){
    k_attx<<<BB,256>>>(adj, a_local + it*4*DD);
    k_gateT<<<BB*SS/16,256>>>(mir1 + it*DD*DD, mir2 + it*DD*DD);
  }
  k_highwayT<<<BB*SS/16,256>>>(hww);
  k_hsc2<<<BB,DD>>>(inputs, glu2,glu4,glu4b);
  k_betaT<<<BB*SS/16,256>>>(inputs,pos,glu1,ws);
  k_zgzh<<<BB,DD>>>(pos, gatew);

  k_scoresT<<<(NSCORE+127)/128,256,SCORES_SMEM>>>(emb, out);
  k_simi<<<BB*SS,64>>>(simi);
  k_simi_final<<<1,128>>>(out);
}